// round 9
// baseline (speedup 1.0000x reference)
#include <cuda_runtime.h>
#include <cstdint>

#define N_NODES 20000
#define N_EDGES 640000
#define MUL 32
#define ATTR 8
#define RB 16
#define FH 64

#define INV_M      0.17677669529663687f
#define INV_RB     0.25f
#define INV_FH     0.125f
#define INV_SQRT3  0.5773502691896258f
#define INV_DEG    0.17677669529663687f
#define INV_2M     0.125f
#define INV_FAN    0.0625f
#define LOG2F_     0.6931471805599453f

// Scratch (device globals)
__device__ float g_s[N_NODES * MUL];
__device__ float g_v[N_NODES * MUL * 3];        // SoA: [node][comp(3)][u(32)]
__device__ float g_agg[N_NODES * MUL * 8];
__device__ float g_w[(size_t)N_EDGES * 128];    // per-sorted-edge TP weights
// sort scratch
__device__ int g_cnt[N_NODES];
__device__ int g_pos[N_NODES];
__device__ int g_off[N_NODES + 1];
__device__ int g_perm[N_EDGES];

__device__ __forceinline__ float sspf(float x) {
    return fmaxf(x, 0.0f) + log1pf(__expf(-fabsf(x))) - LOG2F_;
}

// ---- packed f32x2 helpers ----
__device__ __forceinline__ unsigned long long pack2(float x, float y) {
    unsigned long long r;
    asm("mov.b64 %0, {%1,%2};" : "=l"(r) : "f"(x), "f"(y));
    return r;
}
__device__ __forceinline__ void unpack2(float& x, float& y, unsigned long long r) {
    asm("mov.b64 {%0,%1}, %2;" : "=f"(x), "=f"(y) : "l"(r));
}
__device__ __forceinline__ void fma2(unsigned long long& d, unsigned long long a,
                                     unsigned long long b) {
    asm("fma.rn.f32x2 %0, %1, %2, %0;" : "+l"(d) : "l"(a), "l"(b));
}

// ---- bf16 pack helpers ----
__device__ __forceinline__ unsigned bf16x2_of(float x1, float x0) {
    unsigned r;
    asm("cvt.rn.bf16x2.f32 %0, %1, %2;" : "=r"(r) : "f"(x1), "f"(x0));
    return r;
}
__device__ __forceinline__ void bf16_hilo(float x0, float x1, unsigned& hi, unsigned& lo) {
    hi = bf16x2_of(x1, x0);
    float h0 = __uint_as_float(hi << 16);
    float h1 = __uint_as_float(hi & 0xffff0000u);
    lo = bf16x2_of(x1 - h1, x0 - h0);
}

__device__ __forceinline__ void mma16816(float* d, const unsigned* a, const unsigned* b) {
    asm volatile(
        "mma.sync.aligned.m16n8k16.row.col.f32.bf16.bf16.f32 "
        "{%0,%1,%2,%3}, {%4,%5,%6,%7}, {%8,%9}, {%0,%1,%2,%3};"
        : "+f"(d[0]), "+f"(d[1]), "+f"(d[2]), "+f"(d[3])
        : "r"(a[0]), "r"(a[1]), "r"(a[2]), "r"(a[3]), "r"(b[0]), "r"(b[1]));
}

// ---------------------------------------------------------------------------
__global__ void k_zero() {
    int i = blockIdx.x * blockDim.x + threadIdx.x;
    if (i < N_NODES) { g_cnt[i] = 0; g_pos[i] = 0; }
}

__global__ void k_hist(const int* __restrict__ eidx) {
    int e = blockIdx.x * blockDim.x + threadIdx.x;
    if (e < N_EDGES) atomicAdd(&g_cnt[eidx[N_EDGES + e]], 1);
}

__global__ void k_scan() {
    __shared__ int sh[1024];
    int tid = threadIdx.x;
    int base = tid * 20;
    int loc[20];
    int s = 0;
#pragma unroll
    for (int j = 0; j < 20; j++) {
        int idx = base + j;
        int c = (idx < N_NODES) ? g_cnt[idx] : 0;
        loc[j] = s;
        s += c;
    }
    sh[tid] = s;
    __syncthreads();
    for (int off = 1; off < 1024; off <<= 1) {
        int v = (tid >= off) ? sh[tid - off] : 0;
        __syncthreads();
        sh[tid] += v;
        __syncthreads();
    }
    int pre = (tid == 0) ? 0 : sh[tid - 1];
#pragma unroll
    for (int j = 0; j < 20; j++) {
        int idx = base + j;
        if (idx < N_NODES) g_off[idx] = pre + loc[j];
    }
    if (tid == 1023) g_off[N_NODES] = sh[1023];
}

__global__ void k_scatter(const int* __restrict__ eidx) {
    int e = blockIdx.x * blockDim.x + threadIdx.x;
    if (e < N_EDGES) {
        int dst = eidx[N_EDGES + e];
        int r = atomicAdd(&g_pos[dst], 1);
        g_perm[g_off[dst] + r] = e;
    }
}

// ---------------------------------------------------------------------------
// Kernel 1: linear_1 (writes g_v in SoA [node][comp][32])
// ---------------------------------------------------------------------------
__global__ void k_lin1(const float* __restrict__ node_s,
                       const float* __restrict__ node_v,
                       const float* __restrict__ W1s,
                       const float* __restrict__ W1v) {
    __shared__ float sW1s[1024];
    __shared__ float sW1v[1024];
    int tid = threadIdx.x;
    for (int i = tid; i < 1024; i += 256) {
        sW1s[i] = W1s[i] * INV_M;
        sW1v[i] = W1v[i] * INV_M;
    }
    __syncthreads();

    int gt = blockIdx.x * 256 + tid;
    int node = gt >> 1;
    int h = gt & 1;
    if (node >= N_NODES) return;

    float accs[16];
    float accv[16][3];
#pragma unroll
    for (int w = 0; w < 16; w++) { accs[w] = 0.f; accv[w][0] = accv[w][1] = accv[w][2] = 0.f; }

    const float* srow = node_s + node * 32;
    const float* vrow = node_v + node * 96;
    for (int u = 0; u < 32; u++) {
        float su = srow[u];
        float vx = vrow[u * 3 + 0], vy = vrow[u * 3 + 1], vz = vrow[u * 3 + 2];
        const float* ws = &sW1s[u * 32 + h * 16];
        const float* wv = &sW1v[u * 32 + h * 16];
#pragma unroll
        for (int w = 0; w < 16; w++) {
            accs[w]    += su * ws[w];
            accv[w][0] += vx * wv[w];
            accv[w][1] += vy * wv[w];
            accv[w][2] += vz * wv[w];
        }
    }
    float* so = g_s + node * 32 + h * 16;
    float* vo = g_v + node * 96 + h * 16;
#pragma unroll
    for (int w = 0; w < 16; w++) {
        so[w] = accs[w];
        vo[w]      = accv[w][0];
        vo[32 + w] = accv[w][1];
        vo[64 + w] = accv[w][2];
    }
}

// ---------------------------------------------------------------------------
// Kernel 2a: edge MLP -> g_w[pos][128]. 512 threads, 128 edges/block.
// GEMM1 scalar fp32; GEMM2 via mma.sync bf16 hi/lo 3-term split;
// D stored straight from MMA fragments (write-only streaming, no TP tail).
// ---------------------------------------------------------------------------
#define ET 128
#define ETHREADS 512
#define PHA_HI 0
#define PHA_LO 4224
#define PB_HI  8448
#define PB_LO  12672
#define WR1_OFF 16896
#define EMB_OFF 17920
#define PERM_OFF 20096
#define MLP_SMEM_FLOATS 20224

__global__ void __launch_bounds__(ETHREADS, 2)
k_mlp(const float* __restrict__ emb,
      const float* __restrict__ Wr1,
      const float* __restrict__ Wr2) {
    extern __shared__ float sm[];
    unsigned* su   = reinterpret_cast<unsigned*>(sm);
    float* sWr1 = sm + WR1_OFF;
    float* semb = sm + EMB_OFF;
    int*   sperm = (int*)(sm + PERM_OFF);

    int tid = threadIdx.x;
    int p0 = blockIdx.x * ET;

    if (tid < 128) sperm[tid] = g_perm[p0 + tid];
    for (int i = tid; i < 1024; i += ETHREADS) sWr1[i] = Wr1[i] * INV_RB;
    for (int i = tid; i < 4096; i += ETHREADS) {
        int n = i & 127, kk = i >> 7;
        float sc = INV_FH * INV_DEG * ((n >= 96) ? INV_SQRT3 : 1.0f);
        float w0 = Wr2[(2 * kk) * 128 + n] * sc;
        float w1 = Wr2[(2 * kk + 1) * 128 + n] * sc;
        unsigned hi, lo;
        bf16_hilo(w0, w1, hi, lo);
        su[PB_HI + n * 33 + kk] = hi;
        su[PB_LO + n * 33 + kk] = lo;
    }
    __syncthreads();

    for (int i = tid; i < ET * RB; i += ETHREADS) {
        int pos = i >> 4, k = i & 15;
        semb[pos * 17 + k] = emb[sperm[pos] * 16 + k];
    }
    __syncthreads();

    int lane = tid & 31;
    int th = tid >> 5;          // 0..15
    int cg = th >> 1;           // GEMM1 col group
    int eh = th & 1;            // GEMM1 edge half

    // ---- GEMM1 (fp32): 2 edges x 8 cols per thread ----
    float acc1[2][8];
#pragma unroll
    for (int j = 0; j < 2; j++)
#pragma unroll
        for (int m = 0; m < 8; m++) acc1[j][m] = 0.f;

    for (int k = 0; k < 16; k++) {
        float em[2];
#pragma unroll
        for (int j = 0; j < 2; j++) em[j] = semb[(lane + 32 * (eh * 2 + j)) * 17 + k];
        float wr[8];
#pragma unroll
        for (int m = 0; m < 8; m++) wr[m] = sWr1[k * 64 + cg * 8 + m];
#pragma unroll
        for (int j = 0; j < 2; j++)
#pragma unroll
            for (int m = 0; m < 8; m++) acc1[j][m] += em[j] * wr[m];
    }
#pragma unroll
    for (int j = 0; j < 2; j++) {
        int edge = lane + 32 * (eh * 2 + j);
#pragma unroll
        for (int m = 0; m < 8; m += 2) {
            float x0 = sspf(acc1[j][m]);
            float x1 = sspf(acc1[j][m + 1]);
            unsigned hi, lo;
            bf16_hilo(x0, x1, hi, lo);
            int kk = cg * 4 + (m >> 1);
            su[PHA_HI + edge * 33 + kk] = hi;
            su[PHA_LO + edge * 33 + kk] = lo;
        }
    }
    __syncthreads();

    // ---- GEMM2 via mma.sync: warp pair (mt, nh); store D direct to g_w ----
    int g = lane >> 2;
    int t = lane & 3;
    int mt = th >> 1;
    int nh = th & 1;
    float d[8][4];
#pragma unroll
    for (int ntl = 0; ntl < 8; ntl++)
#pragma unroll
        for (int c = 0; c < 4; c++) d[ntl][c] = 0.f;

    {
        int r0 = mt * 16 + g;
        int r1 = r0 + 8;
#pragma unroll
        for (int ks = 0; ks < 4; ks++) {
            int kk0 = ks * 8 + t;
            unsigned ahi[4], alo[4];
            ahi[0] = su[PHA_HI + r0 * 33 + kk0];
            ahi[1] = su[PHA_HI + r1 * 33 + kk0];
            ahi[2] = su[PHA_HI + r0 * 33 + kk0 + 4];
            ahi[3] = su[PHA_HI + r1 * 33 + kk0 + 4];
            alo[0] = su[PHA_LO + r0 * 33 + kk0];
            alo[1] = su[PHA_LO + r1 * 33 + kk0];
            alo[2] = su[PHA_LO + r0 * 33 + kk0 + 4];
            alo[3] = su[PHA_LO + r1 * 33 + kk0 + 4];
#pragma unroll
            for (int ntl = 0; ntl < 8; ntl++) {
                int n = (nh * 8 + ntl) * 8 + g;
                unsigned bhi[2], blo[2];
                bhi[0] = su[PB_HI + n * 33 + kk0];
                bhi[1] = su[PB_HI + n * 33 + kk0 + 4];
                blo[0] = su[PB_LO + n * 33 + kk0];
                blo[1] = su[PB_LO + n * 33 + kk0 + 4];
                mma16816(d[ntl], ahi, bhi);
                mma16816(d[ntl], alo, bhi);
                mma16816(d[ntl], ahi, blo);
            }
        }
    }

    // store fragments: rows mt*16+g, +8; cols (nh*8+ntl)*8+2t
    {
        size_t row0 = (size_t)(p0 + mt * 16 + g) * 128;
        size_t row1 = row0 + 8 * 128;
#pragma unroll
        for (int ntl = 0; ntl < 8; ntl++) {
            int c = (nh * 8 + ntl) * 8 + 2 * t;
            *(float2*)&g_w[row0 + c] = make_float2(d[ntl][0], d[ntl][1]);
            *(float2*)&g_w[row1 + c] = make_float2(d[ntl][2], d[ntl][3]);
        }
    }
}

// ---------------------------------------------------------------------------
// Kernel 2b: node-owned TP. One warp per node, lane = u.
// No atomics, no barriers, plain stores to g_agg.
// ---------------------------------------------------------------------------
__global__ void __launch_bounds__(256)
k_tp(const float* __restrict__ y0,
     const float* __restrict__ y1,
     const int*   __restrict__ eidx) {
    int node = (blockIdx.x * 256 + threadIdx.x) >> 5;   // grid covers exactly N_NODES warps
    int lane = threadIdx.x & 31;

    int n0 = g_off[node];
    int n1 = g_off[node + 1];

    float A[8];
#pragma unroll
    for (int q = 0; q < 8; q++) A[q] = 0.f;

    for (int pos = n0; pos < n1; pos++) {
        int e = __ldg(&g_perm[pos]);                 // warp-uniform broadcast
        int src = __ldg(&eidx[e]);
        float yy0 = __ldg(&y0[e]);
        float y1x = __ldg(&y1[3 * e + 0]);
        float y1y = __ldg(&y1[3 * e + 1]);
        float y1z = __ldg(&y1[3 * e + 2]);

        float se = g_s[src * 32 + lane];             // coalesced 128B
        const float* vp = g_v + src * 96 + lane;     // SoA: 3 coalesced lines
        float vx = vp[0], vy = vp[32], vz = vp[64];

        const float* wp = g_w + (size_t)pos * 128 + lane;  // 4 coalesced lines
        float w1 = wp[0], w2 = wp[32], w3 = wp[64], w4 = wp[96];

        A[0] += w1 * (se * yy0);
        A[1] += w4 * (vx * y1x + vy * y1y + vz * y1z);
        float a = w2 * se;
        A[2] += a * y1x; A[3] += a * y1y; A[4] += a * y1z;
        float b = w3 * yy0;
        A[5] += b * vx;  A[6] += b * vy;  A[7] += b * vz;
    }

    float* q = g_agg + (size_t)node * 256 + lane * 8;
    *(float4*)q       = make_float4(A[0], A[1], A[2], A[3]);
    *(float4*)(q + 4) = make_float4(A[4], A[5], A[6], A[7]);
}

// ---------------------------------------------------------------------------
// Kernel 3: linear_2 + self-connection
// ---------------------------------------------------------------------------
#define OUT_SMEM_FLOATS (2048 + 2048 + 8192 + 8192)

__global__ void __launch_bounds__(256)
k_out(const float* __restrict__ node_s,
      const float* __restrict__ node_v,
      const float* __restrict__ attrs,
      const float* __restrict__ W2s,
      const float* __restrict__ W2v,
      const float* __restrict__ Wscs,
      const float* __restrict__ Wscv,
      float* __restrict__ out) {
    extern __shared__ float sm[];
    float* sW2s  = sm;
    float* sW2v  = sW2s + 2048;
    float* sWscs = sW2v + 2048;
    float* sWscv = sWscs + 8192;

    int tid = threadIdx.x;
    for (int i = tid; i < 2048; i += 256) { sW2s[i]  = W2s[i]  * INV_2M;  sW2v[i]  = W2v[i]  * INV_2M; }
    for (int i = tid; i < 8192; i += 256) { sWscs[i] = Wscs[i] * INV_FAN; sWscv[i] = Wscv[i] * INV_FAN; }
    __syncthreads();

    int node = blockIdx.x * 32 + (tid >> 3);
    int part = tid & 7;
    int wo = part * 4;

    unsigned long long accs2[2] = {0ull, 0ull};
    unsigned long long accv2[3][2] = {{0ull, 0ull}, {0ull, 0ull}, {0ull, 0ull}};

    const float4* ag = reinterpret_cast<const float4*>(g_agg + (size_t)node * 256);
#pragma unroll 4
    for (int u = 0; u < 32; u++) {
        float4 Aq = ag[u * 2 + 0];
        float4 Bq = ag[u * 2 + 1];
#pragma unroll
        for (int half = 0; half < 2; half++) {
            int k = half * 32 + u;
            ulonglong2 ws = *(const ulonglong2*)&sW2s[k * 32 + wo];
            ulonglong2 wv = *(const ulonglong2*)&sW2v[k * 32 + wo];
            float as  = half ? Aq.y : Aq.x;
            float avx = half ? Bq.y : Aq.z;
            float avy = half ? Bq.z : Aq.w;
            float avz = half ? Bq.w : Bq.x;
            unsigned long long as2  = pack2(as, as);
            unsigned long long avx2 = pack2(avx, avx);
            unsigned long long avy2 = pack2(avy, avy);
            unsigned long long avz2 = pack2(avz, avz);
            fma2(accs2[0], as2, ws.x);
            fma2(accs2[1], as2, ws.y);
            fma2(accv2[0][0], avx2, wv.x);
            fma2(accv2[0][1], avx2, wv.y);
            fma2(accv2[1][0], avy2, wv.x);
            fma2(accv2[1][1], avy2, wv.y);
            fma2(accv2[2][0], avz2, wv.x);
            fma2(accv2[2][1], avz2, wv.y);
        }
    }

    unsigned long long at2[8];
    const float* arow = attrs + node * 8;
#pragma unroll
    for (int v = 0; v < 8; v++) { float a = arow[v]; at2[v] = pack2(a, a); }

    const float* srow = node_s + node * 32;
    const float* vrow = node_v + node * 96;
#pragma unroll 2
    for (int u = 0; u < 32; u++) {
        float su = srow[u];
        float vx = vrow[u * 3 + 0], vy = vrow[u * 3 + 1], vz = vrow[u * 3 + 2];
        unsigned long long Ts[2] = {0ull, 0ull};
        unsigned long long Tv[2] = {0ull, 0ull};
#pragma unroll
        for (int v = 0; v < 8; v++) {
            ulonglong2 ps = *(const ulonglong2*)&sWscs[(u * 8 + v) * 32 + wo];
            ulonglong2 pv = *(const ulonglong2*)&sWscv[(u * 8 + v) * 32 + wo];
            fma2(Ts[0], at2[v], ps.x);
            fma2(Ts[1], at2[v], ps.y);
            fma2(Tv[0], at2[v], pv.x);
            fma2(Tv[1], at2[v], pv.y);
        }
        unsigned long long su2 = pack2(su, su);
        unsigned long long vx2 = pack2(vx, vx);
        unsigned long long vy2 = pack2(vy, vy);
        unsigned long long vz2 = pack2(vz, vz);
#pragma unroll
        for (int p = 0; p < 2; p++) {
            fma2(accs2[p], su2, Ts[p]);
            fma2(accv2[0][p], vx2, Tv[p]);
            fma2(accv2[1][p], vy2, Tv[p]);
            fma2(accv2[2][p], vz2, Tv[p]);
        }
    }

    float* o = out + (size_t)node * 128;
#pragma unroll
    for (int p = 0; p < 2; p++) {
        float s0, s1;
        unpack2(s0, s1, accs2[p]);
        float v0[3], v1[3];
        unpack2(v0[0], v1[0], accv2[0][p]);
        unpack2(v0[1], v1[1], accv2[1][p]);
        unpack2(v0[2], v1[2], accv2[2][p]);
        int w0 = wo + p * 2;
        o[w0]     = s0;
        o[w0 + 1] = s1;
        o[32 + w0 * 3 + 0] = v0[0];
        o[32 + w0 * 3 + 1] = v0[1];
        o[32 + w0 * 3 + 2] = v0[2];
        o[32 + (w0 + 1) * 3 + 0] = v1[0];
        o[32 + (w0 + 1) * 3 + 1] = v1[1];
        o[32 + (w0 + 1) * 3 + 2] = v1[2];
    }
}

// ---------------------------------------------------------------------------
extern "C" void kernel_launch(void* const* d_in, const int* in_sizes, int n_in,
                              void* d_out, int out_size) {
    const float* node_s     = (const float*)d_in[0];
    const float* node_v     = (const float*)d_in[1];
    const float* node_attrs = (const float*)d_in[2];
    const float* edge_emb   = (const float*)d_in[3];
    const float* edge_y0    = (const float*)d_in[4];
    const float* edge_y1    = (const float*)d_in[5];
    const int*   edge_index = (const int*)d_in[6];
    const float* W1s        = (const float*)d_in[7];
    const float* W1v        = (const float*)d_in[8];
    const float* Wr1        = (const float*)d_in[9];
    const float* Wr2        = (const float*)d_in[10];
    const float* W2s        = (const float*)d_in[11];
    const float* W2v        = (const float*)d_in[12];
    const float* Wscs       = (const float*)d_in[13];
    const float* Wscv       = (const float*)d_in[14];
    float* out = (float*)d_out;

    cudaFuncSetAttribute(k_mlp, cudaFuncAttributeMaxDynamicSharedMemorySize,
                         MLP_SMEM_FLOATS * sizeof(float));
    cudaFuncSetAttribute(k_out, cudaFuncAttributeMaxDynamicSharedMemorySize,
                         OUT_SMEM_FLOATS * sizeof(float));

    k_zero<<<(N_NODES + 255) / 256, 256>>>();
    k_hist<<<2500, 256>>>(edge_index);
    k_scan<<<1, 1024>>>();
    k_scatter<<<2500, 256>>>(edge_index);
    k_lin1<<<(2 * N_NODES + 255) / 256, 256>>>(node_s, node_v, W1s, W1v);
    k_mlp<<<N_EDGES / ET, ETHREADS, MLP_SMEM_FLOATS * sizeof(float)>>>(
        edge_emb, Wr1, Wr2);
    k_tp<<<(N_NODES * 32) / 256, 256>>>(edge_y0, edge_y1, edge_index);
    k_out<<<(N_NODES * 8) / 256, 256, OUT_SMEM_FLOATS * sizeof(float)>>>(
        node_s, node_v, node_attrs, W2s, W2v, Wscs, Wscv, out);
}

// round 10
// speedup vs baseline: 1.1315x; 1.1315x over previous
#include <cuda_runtime.h>
#include <cstdint>

#define N_NODES 20000
#define N_EDGES 640000
#define MUL 32
#define ATTR 8
#define RB 16
#define FH 64

#define INV_M      0.17677669529663687f
#define INV_RB     0.25f
#define INV_FH     0.125f
#define INV_SQRT3  0.5773502691896258f
#define INV_DEG    0.17677669529663687f
#define INV_2M     0.125f
#define INV_FAN    0.0625f
#define LOG2F_     0.6931471805599453f

// Scratch (device globals)
__device__ float g_s[N_NODES * MUL];
__device__ float g_v[N_NODES * MUL * 3];      // SoA: [node][comp(3)][u(32)]
__device__ float g_agg[N_NODES * MUL * 8];
// sort scratch
__device__ int g_cnt[N_NODES];
__device__ int g_pos[N_NODES];
__device__ int g_off[N_NODES + 1];
__device__ int g_perm[N_EDGES];

__device__ __forceinline__ float sspf(float x) {
    return fmaxf(x, 0.0f) + log1pf(__expf(-fabsf(x))) - LOG2F_;
}

// no "memory" clobber — g_agg is write-only here and atomic adds commute
__device__ __forceinline__ void red_add_v4(float* addr, float a, float b, float c, float d) {
    asm volatile("red.global.add.v4.f32 [%0], {%1,%2,%3,%4};"
                 :: "l"(addr), "f"(a), "f"(b), "f"(c), "f"(d));
}

// ---- packed f32x2 helpers ----
__device__ __forceinline__ unsigned long long pack2(float x, float y) {
    unsigned long long r;
    asm("mov.b64 %0, {%1,%2};" : "=l"(r) : "f"(x), "f"(y));
    return r;
}
__device__ __forceinline__ void unpack2(float& x, float& y, unsigned long long r) {
    asm("mov.b64 {%0,%1}, %2;" : "=f"(x), "=f"(y) : "l"(r));
}
__device__ __forceinline__ void fma2(unsigned long long& d, unsigned long long a,
                                     unsigned long long b) {
    asm("fma.rn.f32x2 %0, %1, %2, %0;" : "+l"(d) : "l"(a), "l"(b));
}

// ---- bf16 pack helpers ----
__device__ __forceinline__ unsigned bf16x2_of(float x1, float x0) {
    unsigned r;
    asm("cvt.rn.bf16x2.f32 %0, %1, %2;" : "=r"(r) : "f"(x1), "f"(x0));
    return r;
}
__device__ __forceinline__ void bf16_hilo(float x0, float x1, unsigned& hi, unsigned& lo) {
    hi = bf16x2_of(x1, x0);
    float h0 = __uint_as_float(hi << 16);
    float h1 = __uint_as_float(hi & 0xffff0000u);
    lo = bf16x2_of(x1 - h1, x0 - h0);
}

__device__ __forceinline__ void mma16816(float* d, const unsigned* a, const unsigned* b) {
    asm volatile(
        "mma.sync.aligned.m16n8k16.row.col.f32.bf16.bf16.f32 "
        "{%0,%1,%2,%3}, {%4,%5,%6,%7}, {%8,%9}, {%0,%1,%2,%3};"
        : "+f"(d[0]), "+f"(d[1]), "+f"(d[2]), "+f"(d[3])
        : "r"(a[0]), "r"(a[1]), "r"(a[2]), "r"(a[3]), "r"(b[0]), "r"(b[1]));
}

// ---------------------------------------------------------------------------
__global__ void k_zero() {
    int i = blockIdx.x * blockDim.x + threadIdx.x;
    float4* p = reinterpret_cast<float4*>(g_agg);
    p[i] = make_float4(0.f, 0.f, 0.f, 0.f);
    if (i < N_NODES) { g_cnt[i] = 0; g_pos[i] = 0; }
}

__global__ void k_hist(const int* __restrict__ eidx) {
    int e = blockIdx.x * blockDim.x + threadIdx.x;
    if (e < N_EDGES) atomicAdd(&g_cnt[eidx[N_EDGES + e]], 1);
}

__global__ void k_scan() {
    __shared__ int sh[1024];
    int tid = threadIdx.x;
    int base = tid * 20;
    int loc[20];
    int s = 0;
#pragma unroll
    for (int j = 0; j < 20; j++) {
        int idx = base + j;
        int c = (idx < N_NODES) ? g_cnt[idx] : 0;
        loc[j] = s;
        s += c;
    }
    sh[tid] = s;
    __syncthreads();
    for (int off = 1; off < 1024; off <<= 1) {
        int v = (tid >= off) ? sh[tid - off] : 0;
        __syncthreads();
        sh[tid] += v;
        __syncthreads();
    }
    int pre = (tid == 0) ? 0 : sh[tid - 1];
#pragma unroll
    for (int j = 0; j < 20; j++) {
        int idx = base + j;
        if (idx < N_NODES) g_off[idx] = pre + loc[j];
    }
    if (tid == 1023) g_off[N_NODES] = sh[1023];
}

__global__ void k_scatter(const int* __restrict__ eidx) {
    int e = blockIdx.x * blockDim.x + threadIdx.x;
    if (e < N_EDGES) {
        int dst = eidx[N_EDGES + e];
        int r = atomicAdd(&g_pos[dst], 1);
        g_perm[g_off[dst] + r] = e;
    }
}

// ---------------------------------------------------------------------------
// Kernel 1: linear_1 (writes g_v in SoA [node][comp][32])
// ---------------------------------------------------------------------------
__global__ void k_lin1(const float* __restrict__ node_s,
                       const float* __restrict__ node_v,
                       const float* __restrict__ W1s,
                       const float* __restrict__ W1v) {
    __shared__ float sW1s[1024];
    __shared__ float sW1v[1024];
    int tid = threadIdx.x;
    for (int i = tid; i < 1024; i += 256) {
        sW1s[i] = W1s[i] * INV_M;
        sW1v[i] = W1v[i] * INV_M;
    }
    __syncthreads();

    int gt = blockIdx.x * 256 + tid;
    int node = gt >> 1;
    int h = gt & 1;
    if (node >= N_NODES) return;

    float accs[16];
    float accv[16][3];
#pragma unroll
    for (int w = 0; w < 16; w++) { accs[w] = 0.f; accv[w][0] = accv[w][1] = accv[w][2] = 0.f; }

    const float* srow = node_s + node * 32;
    const float* vrow = node_v + node * 96;
    for (int u = 0; u < 32; u++) {
        float su = srow[u];
        float vx = vrow[u * 3 + 0], vy = vrow[u * 3 + 1], vz = vrow[u * 3 + 2];
        const float* ws = &sW1s[u * 32 + h * 16];
        const float* wv = &sW1v[u * 32 + h * 16];
#pragma unroll
        for (int w = 0; w < 16; w++) {
            accs[w]    += su * ws[w];
            accv[w][0] += vx * wv[w];
            accv[w][1] += vy * wv[w];
            accv[w][2] += vz * wv[w];
        }
    }
    float* so = g_s + node * 32 + h * 16;
    float* vo = g_v + node * 96 + h * 16;     // SoA: + comp*32
#pragma unroll
    for (int w = 0; w < 16; w++) {
        so[w] = accs[w];
        vo[w]      = accv[w][0];
        vo[32 + w] = accv[w][1];
        vo[64 + w] = accv[w][2];
    }
}

// ---------------------------------------------------------------------------
// Kernel 2: fused edge kernel (R8 structure), 512 threads.
// + L2 prefetch of TP gather lines during MLP compute
// + per-warp-pair named barrier before TP (no block-wide convoy)
// ---------------------------------------------------------------------------
#define ET 128
#define ETHREADS 512
#define PHA_HI 0
#define PHA_LO 4224
#define PB_HI  8448
#define PB_LO  12672
#define WR1_OFF 16896
#define EMB_OFF 17920
#define META_OFF 20096
#define EDGE_SMEM_FLOATS 20992

__global__ void __launch_bounds__(ETHREADS, 2)
k_edge(const float* __restrict__ emb,
       const float* __restrict__ y0,
       const float* __restrict__ y1,
       const int*   __restrict__ eidx,
       const float* __restrict__ Wr1,
       const float* __restrict__ Wr2) {
    extern __shared__ float sm[];
    unsigned* su   = reinterpret_cast<unsigned*>(sm);
    float* sw   = sm;                     // overlay after MMA
    float* sWr1 = sm + WR1_OFF;
    float* semb = sm + EMB_OFF;
    int*   sperm = (int*)(sm + META_OFF);
    int*   ssrc  = sperm + 128;
    int*   sdst  = ssrc + 128;
    float* sy0   = (float*)(sdst + 128);
    float* sy1   = sy0 + 128;

    int tid = threadIdx.x;
    int p0 = blockIdx.x * ET;

    if (tid < 128) sperm[tid] = g_perm[p0 + tid];
    for (int i = tid; i < 1024; i += ETHREADS) sWr1[i] = Wr1[i] * INV_RB;
    for (int i = tid; i < 4096; i += ETHREADS) {
        int n = i & 127, kk = i >> 7;
        float sc = INV_FH * INV_DEG * ((n >= 96) ? INV_SQRT3 : 1.0f);
        float w0 = Wr2[(2 * kk) * 128 + n] * sc;
        float w1 = Wr2[(2 * kk + 1) * 128 + n] * sc;
        unsigned hi, lo;
        bf16_hilo(w0, w1, hi, lo);
        su[PB_HI + n * 33 + kk] = hi;
        su[PB_LO + n * 33 + kk] = lo;
    }
    __syncthreads();

    if (tid < 128) {
        int e = sperm[tid];
        ssrc[tid] = eidx[e];
        sdst[tid] = eidx[N_EDGES + e];
        sy0[tid] = y0[e];
    }
    for (int i = tid; i < 384; i += ETHREADS) {
        int pos = i / 3, comp = i - pos * 3;
        sy1[i] = y1[sperm[pos] * 3 + comp];
    }
    for (int i = tid; i < ET * RB; i += ETHREADS) {
        int pos = i >> 4, k = i & 15;
        semb[pos * 17 + k] = emb[sperm[pos] * 16 + k];
    }
    __syncthreads();

    int lane = tid & 31;
    int th = tid >> 5;          // 0..15
    int cg = th >> 1;           // GEMM1 col group 0..7
    int eh = th & 1;            // GEMM1 edge half

    // ---- L2 prefetch of TP gather lines (overlaps MLP compute; no reg cost) ----
    {
        int basew = th * 8;
        if (lane < 8) {
            const float* p = g_s + (size_t)ssrc[basew + lane] * 32;
            asm volatile("prefetch.global.L2 [%0];" :: "l"(p));
        } else {
            int j = (lane - 8) / 3, c = (lane - 8) - 3 * j;
            if (j < 8) {
                const float* p = g_v + (size_t)ssrc[basew + j] * 96 + c * 32;
                asm volatile("prefetch.global.L2 [%0];" :: "l"(p));
            }
        }
    }

    // ---- GEMM1 (fp32): 2 edges x 8 cols per thread ----
    float acc1[2][8];
#pragma unroll
    for (int j = 0; j < 2; j++)
#pragma unroll
        for (int m = 0; m < 8; m++) acc1[j][m] = 0.f;

    for (int k = 0; k < 16; k++) {
        float em[2];
#pragma unroll
        for (int j = 0; j < 2; j++) em[j] = semb[(lane + 32 * (eh * 2 + j)) * 17 + k];
        float wr[8];
#pragma unroll
        for (int m = 0; m < 8; m++) wr[m] = sWr1[k * 64 + cg * 8 + m];
#pragma unroll
        for (int j = 0; j < 2; j++)
#pragma unroll
            for (int m = 0; m < 8; m++) acc1[j][m] += em[j] * wr[m];
    }
#pragma unroll
    for (int j = 0; j < 2; j++) {
        int edge = lane + 32 * (eh * 2 + j);
#pragma unroll
        for (int m = 0; m < 8; m += 2) {
            float x0 = sspf(acc1[j][m]);
            float x1 = sspf(acc1[j][m + 1]);
            unsigned hi, lo;
            bf16_hilo(x0, x1, hi, lo);
            int kk = cg * 4 + (m >> 1);
            su[PHA_HI + edge * 33 + kk] = hi;
            su[PHA_LO + edge * 33 + kk] = lo;
        }
    }
    __syncthreads();

    // ---- GEMM2 via mma.sync: warp pair (mt, nh) ----
    int g = lane >> 2;
    int t = lane & 3;
    int mt = th >> 1;           // M-tile: edges [mt*16, mt*16+16)
    int nh = th & 1;            // N half
    float d[8][4];
#pragma unroll
    for (int ntl = 0; ntl < 8; ntl++)
#pragma unroll
        for (int c = 0; c < 4; c++) d[ntl][c] = 0.f;

    {
        int r0 = mt * 16 + g;
        int r1 = r0 + 8;
#pragma unroll
        for (int ks = 0; ks < 4; ks++) {
            int kk0 = ks * 8 + t;
            unsigned ahi[4], alo[4];
            ahi[0] = su[PHA_HI + r0 * 33 + kk0];
            ahi[1] = su[PHA_HI + r1 * 33 + kk0];
            ahi[2] = su[PHA_HI + r0 * 33 + kk0 + 4];
            ahi[3] = su[PHA_HI + r1 * 33 + kk0 + 4];
            alo[0] = su[PHA_LO + r0 * 33 + kk0];
            alo[1] = su[PHA_LO + r1 * 33 + kk0];
            alo[2] = su[PHA_LO + r0 * 33 + kk0 + 4];
            alo[3] = su[PHA_LO + r1 * 33 + kk0 + 4];
#pragma unroll
            for (int ntl = 0; ntl < 8; ntl++) {
                int n = (nh * 8 + ntl) * 8 + g;
                unsigned bhi[2], blo[2];
                bhi[0] = su[PB_HI + n * 33 + kk0];
                bhi[1] = su[PB_HI + n * 33 + kk0 + 4];
                blo[0] = su[PB_LO + n * 33 + kk0];
                blo[1] = su[PB_LO + n * 33 + kk0 + 4];
                mma16816(d[ntl], ahi, bhi);
                mma16816(d[ntl], alo, bhi);
                mma16816(d[ntl], ahi, blo);
            }
        }
    }
    __syncthreads();   // phA/pB dead; safe to overlay sw

    // ---- store D -> sw[edge][col] with xor swizzle ----
    {
        int e0 = mt * 16 + g;
        int e1 = e0 + 8;
        int sw0 = (e0 & 7) << 2;
        int sw1 = (e1 & 7) << 2;
#pragma unroll
        for (int ntl = 0; ntl < 8; ntl++) {
            int c = (nh * 8 + ntl) * 8 + 2 * t;
            int b = c & ~31;
            int cc = c & 31;
            *(float2*)&sw[e0 * 128 + b + (cc ^ sw0)] = make_float2(d[ntl][0], d[ntl][1]);
            *(float2*)&sw[e1 * 128 + b + (cc ^ sw1)] = make_float2(d[ntl][2], d[ntl][3]);
        }
    }
    // TP warp th reads only sw rows [th*8, th*8+8) ⊂ M-tile (th>>1), produced
    // by its warp PAIR {th&~1, th|1} — named barrier per pair, no block convoy.
    asm volatile("bar.sync %0, 64;" :: "r"((th >> 1) + 1) : "memory");

    // ---- warp-cooperative TP: warp th owns edges [th*8, th*8+8), lane = u ----
    int base = th * 8;

    float se_r[8];
#pragma unroll
    for (int j = 0; j < 8; j++) se_r[j] = g_s[ssrc[base + j] * 32 + lane];

    const float* vp0 = g_v + ssrc[base] * 96 + lane;
    float vxc = vp0[0], vyc = vp0[32], vzc = vp0[64];

    float A[8];
#pragma unroll
    for (int q = 0; q < 8; q++) A[q] = 0.f;

    int cur = sdst[base];
#pragma unroll
    for (int j = 0; j < 8; j++) {
        int pos = base + j;
        float vxn = 0.f, vyn = 0.f, vzn = 0.f;
        if (j < 7) {
            const float* vpn = g_v + ssrc[pos + 1] * 96 + lane;
            vxn = vpn[0]; vyn = vpn[32]; vzn = vpn[64];
        }
        int dd = sdst[pos];
        if (dd != cur) {
            float* q = g_agg + (size_t)cur * 256 + lane * 8;
            red_add_v4(q,     A[0], A[1], A[2], A[3]);
            red_add_v4(q + 4, A[4], A[5], A[6], A[7]);
#pragma unroll
            for (int qq = 0; qq < 8; qq++) A[qq] = 0.f;
            cur = dd;
        }
        float yy0 = sy0[pos];
        float y1x = sy1[pos * 3 + 0], y1y = sy1[pos * 3 + 1], y1z = sy1[pos * 3 + 2];
        float se = se_r[j];
        int sx = lane ^ ((pos & 7) << 2);
        int wb = pos * 128;
        float w1 = sw[wb + sx], w2 = sw[wb + 32 + sx], w3 = sw[wb + 64 + sx], w4 = sw[wb + 96 + sx];

        A[0] += w1 * (se * yy0);
        A[1] += w4 * (vxc * y1x + vyc * y1y + vzc * y1z);
        float a = w2 * se;
        A[2] += a * y1x; A[3] += a * y1y; A[4] += a * y1z;
        float b = w3 * yy0;
        A[5] += b * vxc; A[6] += b * vyc; A[7] += b * vzc;

        vxc = vxn; vyc = vyn; vzc = vzn;
    }
    float* q = g_agg + (size_t)cur * 256 + lane * 8;
    red_add_v4(q,     A[0], A[1], A[2], A[3]);
    red_add_v4(q + 4, A[4], A[5], A[6], A[7]);
}

// ---------------------------------------------------------------------------
// Kernel 3: linear_2 + self-connection. 16 threads/node (2 outputs each).
// ---------------------------------------------------------------------------
#define OUT_SMEM_FLOATS (2048 + 2048 + 8192 + 8192)

__global__ void __launch_bounds__(256)
k_out(const float* __restrict__ node_s,
      const float* __restrict__ node_v,
      const float* __restrict__ attrs,
      const float* __restrict__ W2s,
      const float* __restrict__ W2v,
      const float* __restrict__ Wscs,
      const float* __restrict__ Wscv,
      float* __restrict__ out) {
    extern __shared__ float sm[];
    float* sW2s  = sm;
    float* sW2v  = sW2s + 2048;
    float* sWscs = sW2v + 2048;
    float* sWscv = sWscs + 8192;

    int tid = threadIdx.x;
    for (int i = tid; i < 2048; i += 256) { sW2s[i]  = W2s[i]  * INV_2M;  sW2v[i]  = W2v[i]  * INV_2M; }
    for (int i = tid; i < 8192; i += 256) { sWscs[i] = Wscs[i] * INV_FAN; sWscv[i] = Wscv[i] * INV_FAN; }
    __syncthreads();

    int node = blockIdx.x * 16 + (tid >> 4);
    int part = tid & 15;                // owns outputs w in [part*2, part*2+2)
    int wo = part * 2;

    unsigned long long accs2 = 0ull;
    unsigned long long accv2[3] = {0ull, 0ull, 0ull};

    // ---- linear_2 ----
    const float4* ag = reinterpret_cast<const float4*>(g_agg + (size_t)node * 256);
#pragma unroll 4
    for (int u = 0; u < 32; u++) {
        float4 Aq = ag[u * 2 + 0];
        float4 Bq = ag[u * 2 + 1];
#pragma unroll
        for (int half = 0; half < 2; half++) {
            int k = half * 32 + u;
            unsigned long long ws = *(const unsigned long long*)&sW2s[k * 32 + wo];
            unsigned long long wv = *(const unsigned long long*)&sW2v[k * 32 + wo];
            float as  = half ? Aq.y : Aq.x;
            float avx = half ? Bq.y : Aq.z;
            float avy = half ? Bq.z : Aq.w;
            float avz = half ? Bq.w : Bq.x;
            fma2(accs2, pack2(as, as), ws);
            fma2(accv2[0], pack2(avx, avx), wv);
            fma2(accv2[1], pack2(avy, avy), wv);
            fma2(accv2[2], pack2(avz, avz), wv);
        }
    }

    // ---- self connection, factored T[u,w] = sum_v a_v W[u,v,w] ----
    unsigned long long at2[8];
    const float* arow = attrs + node * 8;
#pragma unroll
    for (int v = 0; v < 8; v++) { float a = arow[v]; at2[v] = pack2(a, a); }

    const float* srow = node_s + node * 32;
    const float* vrow = node_v + node * 96;
#pragma unroll 2
    for (int u = 0; u < 32; u++) {
        float su = srow[u];
        float vx = vrow[u * 3 + 0], vy = vrow[u * 3 + 1], vz = vrow[u * 3 + 2];
        unsigned long long Ts = 0ull;
        unsigned long long Tv = 0ull;
#pragma unroll
        for (int v = 0; v < 8; v++) {
            unsigned long long ps = *(const unsigned long long*)&sWscs[(u * 8 + v) * 32 + wo];
            unsigned long long pv = *(const unsigned long long*)&sWscv[(u * 8 + v) * 32 + wo];
            fma2(Ts, at2[v], ps);
            fma2(Tv, at2[v], pv);
        }
        fma2(accs2, pack2(su, su), Ts);
        fma2(accv2[0], pack2(vx, vx), Tv);
        fma2(accv2[1], pack2(vy, vy), Tv);
        fma2(accv2[2], pack2(vz, vz), Tv);
    }

    // ---- output ----
    float* o = out + (size_t)node * 128;
    float s0, s1;
    unpack2(s0, s1, accs2);
    float v0[3], v1[3];
    unpack2(v0[0], v1[0], accv2[0]);
    unpack2(v0[1], v1[1], accv2[1]);
    unpack2(v0[2], v1[2], accv2[2]);
    o[wo]     = s0;
    o[wo + 1] = s1;
    o[32 + wo * 3 + 0] = v0[0];
    o[32 + wo * 3 + 1] = v0[1];
    o[32 + wo * 3 + 2] = v0[2];
    o[32 + (wo + 1) * 3 + 0] = v1[0];
    o[32 + (wo + 1) * 3 + 1] = v1[1];
    o[32 + (wo + 1) * 3 + 2] = v1[2];
}

// ---------------------------------------------------------------------------
extern "C" void kernel_launch(void* const* d_in, const int* in_sizes, int n_in,
                              void* d_out, int out_size) {
    const float* node_s     = (const float*)d_in[0];
    const float* node_v     = (const float*)d_in[1];
    const float* node_attrs = (const float*)d_in[2];
    const float* edge_emb   = (const float*)d_in[3];
    const float* edge_y0    = (const float*)d_in[4];
    const float* edge_y1    = (const float*)d_in[5];
    const int*   edge_index = (const int*)d_in[6];
    const float* W1s        = (const float*)d_in[7];
    const float* W1v        = (const float*)d_in[8];
    const float* Wr1        = (const float*)d_in[9];
    const float* Wr2        = (const float*)d_in[10];
    const float* W2s        = (const float*)d_in[11];
    const float* W2v        = (const float*)d_in[12];
    const float* Wscs       = (const float*)d_in[13];
    const float* Wscv       = (const float*)d_in[14];
    float* out = (float*)d_out;

    cudaFuncSetAttribute(k_edge, cudaFuncAttributeMaxDynamicSharedMemorySize,
                         EDGE_SMEM_FLOATS * sizeof(float));
    cudaFuncSetAttribute(k_out, cudaFuncAttributeMaxDynamicSharedMemorySize,
                         OUT_SMEM_FLOATS * sizeof(float));

    k_zero<<<5000, 256>>>();
    k_hist<<<2500, 256>>>(edge_index);
    k_scan<<<1, 1024>>>();
    k_scatter<<<2500, 256>>>(edge_index);
    k_lin1<<<(2 * N_NODES + 255) / 256, 256>>>(node_s, node_v, W1s, W1v);
    k_edge<<<N_EDGES / ET, ETHREADS, EDGE_SMEM_FLOATS * sizeof(float)>>>(
        edge_emb, edge_y0, edge_y1, edge_index, Wr1, Wr2);
    k_out<<<(N_NODES + 15) / 16, 256, OUT_SMEM_FLOATS * sizeof(float)>>>(
        node_s, node_v, node_attrs, W2s, W2v, Wscs, Wscv, out);
}

// round 11
// speedup vs baseline: 1.1992x; 1.0598x over previous
#include <cuda_runtime.h>
#include <cstdint>

#define N_NODES 20000
#define N_EDGES 640000
#define MUL 32
#define ATTR 8
#define RB 16
#define FH 64

#define INV_M      0.17677669529663687f
#define INV_RB     0.25f
#define INV_FH     0.125f
#define INV_SQRT3  0.5773502691896258f
#define INV_DEG    0.17677669529663687f
#define INV_2M     0.125f
#define INV_FAN    0.0625f
#define LOG2F_     0.6931471805599453f

// Scratch (device globals)
__device__ float g_s[N_NODES * MUL];
__device__ float g_v[N_NODES * MUL * 3];      // SoA: [node][comp(3)][u(32)]
__device__ float g_agg[N_NODES * MUL * 8];
// sort scratch
__device__ int g_cnt[N_NODES];
__device__ int g_pos[N_NODES];
__device__ int g_off[N_NODES + 1];
__device__ int g_perm[N_EDGES];

__device__ __forceinline__ float sspf(float x) {
    return fmaxf(x, 0.0f) + log1pf(__expf(-fabsf(x))) - LOG2F_;
}

// no "memory" clobber — g_agg is write-only here and atomic adds commute
__device__ __forceinline__ void red_add_v4(float* addr, float a, float b, float c, float d) {
    asm volatile("red.global.add.v4.f32 [%0], {%1,%2,%3,%4};"
                 :: "l"(addr), "f"(a), "f"(b), "f"(c), "f"(d));
}

// ---- packed f32x2 helpers ----
__device__ __forceinline__ unsigned long long pack2(float x, float y) {
    unsigned long long r;
    asm("mov.b64 %0, {%1,%2};" : "=l"(r) : "f"(x), "f"(y));
    return r;
}
__device__ __forceinline__ void unpack2(float& x, float& y, unsigned long long r) {
    asm("mov.b64 {%0,%1}, %2;" : "=f"(x), "=f"(y) : "l"(r));
}
__device__ __forceinline__ void fma2(unsigned long long& d, unsigned long long a,
                                     unsigned long long b) {
    asm("fma.rn.f32x2 %0, %1, %2, %0;" : "+l"(d) : "l"(a), "l"(b));
}

// ---- bf16 pack helpers ----
__device__ __forceinline__ unsigned bf16x2_of(float x1, float x0) {
    unsigned r;
    asm("cvt.rn.bf16x2.f32 %0, %1, %2;" : "=r"(r) : "f"(x1), "f"(x0));
    return r;
}
__device__ __forceinline__ void bf16_hilo(float x0, float x1, unsigned& hi, unsigned& lo) {
    hi = bf16x2_of(x1, x0);
    float h0 = __uint_as_float(hi << 16);
    float h1 = __uint_as_float(hi & 0xffff0000u);
    lo = bf16x2_of(x1 - h1, x0 - h0);
}

__device__ __forceinline__ void mma16816(float* d, const unsigned* a, const unsigned* b) {
    asm volatile(
        "mma.sync.aligned.m16n8k16.row.col.f32.bf16.bf16.f32 "
        "{%0,%1,%2,%3}, {%4,%5,%6,%7}, {%8,%9}, {%0,%1,%2,%3};"
        : "+f"(d[0]), "+f"(d[1]), "+f"(d[2]), "+f"(d[3])
        : "r"(a[0]), "r"(a[1]), "r"(a[2]), "r"(a[3]), "r"(b[0]), "r"(b[1]));
}

// kk (bf16x2 word index 0..31) -> paired layout index so (kk, kk+4) are adjacent
__device__ __forceinline__ int kp_of(int kk) {
    int ks = kk >> 3, r = kk & 7;
    return ((ks << 2) + (r & 3)) * 2 + (r >> 2);
}

// ---------------------------------------------------------------------------
__global__ void k_zero() {
    int i = blockIdx.x * blockDim.x + threadIdx.x;
    float4* p = reinterpret_cast<float4*>(g_agg);
    p[i] = make_float4(0.f, 0.f, 0.f, 0.f);
    if (i < N_NODES) { g_cnt[i] = 0; g_pos[i] = 0; }
}

__global__ void k_hist(const int* __restrict__ eidx) {
    int e = blockIdx.x * blockDim.x + threadIdx.x;
    if (e < N_EDGES) atomicAdd(&g_cnt[eidx[N_EDGES + e]], 1);
}

__global__ void k_scan() {
    __shared__ int sh[1024];
    int tid = threadIdx.x;
    int base = tid * 20;
    int loc[20];
    int s = 0;
#pragma unroll
    for (int j = 0; j < 20; j++) {
        int idx = base + j;
        int c = (idx < N_NODES) ? g_cnt[idx] : 0;
        loc[j] = s;
        s += c;
    }
    sh[tid] = s;
    __syncthreads();
    for (int off = 1; off < 1024; off <<= 1) {
        int v = (tid >= off) ? sh[tid - off] : 0;
        __syncthreads();
        sh[tid] += v;
        __syncthreads();
    }
    int pre = (tid == 0) ? 0 : sh[tid - 1];
#pragma unroll
    for (int j = 0; j < 20; j++) {
        int idx = base + j;
        if (idx < N_NODES) g_off[idx] = pre + loc[j];
    }
    if (tid == 1023) g_off[N_NODES] = sh[1023];
}

__global__ void k_scatter(const int* __restrict__ eidx) {
    int e = blockIdx.x * blockDim.x + threadIdx.x;
    if (e < N_EDGES) {
        int dst = eidx[N_EDGES + e];
        int r = atomicAdd(&g_pos[dst], 1);
        g_perm[g_off[dst] + r] = e;
    }
}

// ---------------------------------------------------------------------------
// Kernel 1: linear_1 (writes g_v in SoA [node][comp][32])
// ---------------------------------------------------------------------------
__global__ void k_lin1(const float* __restrict__ node_s,
                       const float* __restrict__ node_v,
                       const float* __restrict__ W1s,
                       const float* __restrict__ W1v) {
    __shared__ float sW1s[1024];
    __shared__ float sW1v[1024];
    int tid = threadIdx.x;
    for (int i = tid; i < 1024; i += 256) {
        sW1s[i] = W1s[i] * INV_M;
        sW1v[i] = W1v[i] * INV_M;
    }
    __syncthreads();

    int gt = blockIdx.x * 256 + tid;
    int node = gt >> 1;
    int h = gt & 1;
    if (node >= N_NODES) return;

    float accs[16];
    float accv[16][3];
#pragma unroll
    for (int w = 0; w < 16; w++) { accs[w] = 0.f; accv[w][0] = accv[w][1] = accv[w][2] = 0.f; }

    const float* srow = node_s + node * 32;
    const float* vrow = node_v + node * 96;
    for (int u = 0; u < 32; u++) {
        float su = srow[u];
        float vx = vrow[u * 3 + 0], vy = vrow[u * 3 + 1], vz = vrow[u * 3 + 2];
        const float* ws = &sW1s[u * 32 + h * 16];
        const float* wv = &sW1v[u * 32 + h * 16];
#pragma unroll
        for (int w = 0; w < 16; w++) {
            accs[w]    += su * ws[w];
            accv[w][0] += vx * wv[w];
            accv[w][1] += vy * wv[w];
            accv[w][2] += vz * wv[w];
        }
    }
    float* so = g_s + node * 32 + h * 16;
    float* vo = g_v + node * 96 + h * 16;     // SoA: + comp*32
#pragma unroll
    for (int w = 0; w < 16; w++) {
        so[w] = accs[w];
        vo[w]      = accv[w][0];
        vo[32 + w] = accv[w][1];
        vo[64 + w] = accv[w][2];
    }
}

// ---------------------------------------------------------------------------
// Kernel 2: fused edge kernel (R8 structure), 512 threads.
// kk-paired smem layout (pitch 34): every mma fragment load is LDS.64.
// ---------------------------------------------------------------------------
#define ET 128
#define ETHREADS 512
#define PHA_HI 0
#define PHA_LO 4352
#define PB_HI  8704
#define PB_LO  13056
#define WR1_OFF 17408
#define EMB_OFF 18432
#define META_OFF 20608
#define EDGE_SMEM_FLOATS 21504

__global__ void __launch_bounds__(ETHREADS, 2)
k_edge(const float* __restrict__ emb,
       const float* __restrict__ y0,
       const float* __restrict__ y1,
       const int*   __restrict__ eidx,
       const float* __restrict__ Wr1,
       const float* __restrict__ Wr2) {
    extern __shared__ float sm[];
    unsigned* su   = reinterpret_cast<unsigned*>(sm);
    float* sw   = sm;                     // overlay after MMA
    float* sWr1 = sm + WR1_OFF;
    float* semb = sm + EMB_OFF;
    int*   sperm = (int*)(sm + META_OFF);
    int*   ssrc  = sperm + 128;
    int*   sdst  = ssrc + 128;
    float* sy0   = (float*)(sdst + 128);
    float* sy1   = sy0 + 128;

    int tid = threadIdx.x;
    int p0 = blockIdx.x * ET;

    if (tid < 128) sperm[tid] = g_perm[p0 + tid];
    for (int i = tid; i < 1024; i += ETHREADS) sWr1[i] = Wr1[i] * INV_RB;
    for (int i = tid; i < 4096; i += ETHREADS) {
        int n = i & 127, kk = i >> 7;
        float sc = INV_FH * INV_DEG * ((n >= 96) ? INV_SQRT3 : 1.0f);
        float w0 = Wr2[(2 * kk) * 128 + n] * sc;
        float w1 = Wr2[(2 * kk + 1) * 128 + n] * sc;
        unsigned hi, lo;
        bf16_hilo(w0, w1, hi, lo);
        int kp = kp_of(kk);
        su[PB_HI + n * 34 + kp] = hi;
        su[PB_LO + n * 34 + kp] = lo;
    }
    __syncthreads();

    if (tid < 128) {
        int e = sperm[tid];
        ssrc[tid] = eidx[e];
        sdst[tid] = eidx[N_EDGES + e];
        sy0[tid] = y0[e];
    }
    for (int i = tid; i < 384; i += ETHREADS) {
        int pos = i / 3, comp = i - pos * 3;
        sy1[i] = y1[sperm[pos] * 3 + comp];
    }
    for (int i = tid; i < ET * RB; i += ETHREADS) {
        int pos = i >> 4, k = i & 15;
        semb[pos * 17 + k] = emb[sperm[pos] * 16 + k];
    }
    __syncthreads();

    int lane = tid & 31;
    int th = tid >> 5;          // 0..15
    int cg = th >> 1;           // GEMM1 col group 0..7
    int eh = th & 1;            // GEMM1 edge half

    // ---- GEMM1 (fp32): 2 edges x 8 cols per thread ----
    float acc1[2][8];
#pragma unroll
    for (int j = 0; j < 2; j++)
#pragma unroll
        for (int m = 0; m < 8; m++) acc1[j][m] = 0.f;

    for (int k = 0; k < 16; k++) {
        float em[2];
#pragma unroll
        for (int j = 0; j < 2; j++) em[j] = semb[(lane + 32 * (eh * 2 + j)) * 17 + k];
        float wr[8];
#pragma unroll
        for (int m = 0; m < 8; m++) wr[m] = sWr1[k * 64 + cg * 8 + m];
#pragma unroll
        for (int j = 0; j < 2; j++)
#pragma unroll
            for (int m = 0; m < 8; m++) acc1[j][m] += em[j] * wr[m];
    }
#pragma unroll
    for (int j = 0; j < 2; j++) {
        int edge = lane + 32 * (eh * 2 + j);
#pragma unroll
        for (int m = 0; m < 8; m += 2) {
            float x0 = sspf(acc1[j][m]);
            float x1 = sspf(acc1[j][m + 1]);
            unsigned hi, lo;
            bf16_hilo(x0, x1, hi, lo);
            int kp = kp_of(cg * 4 + (m >> 1));
            su[PHA_HI + edge * 34 + kp] = hi;
            su[PHA_LO + edge * 34 + kp] = lo;
        }
    }
    __syncthreads();

    // ---- GEMM2 via mma.sync: warp pair (mt, nh); LDS.64 fragment loads ----
    int g = lane >> 2;
    int t = lane & 3;
    int mt = th >> 1;           // M-tile: edges [mt*16, mt*16+16)
    int nh = th & 1;            // N half
    float d[8][4];
#pragma unroll
    for (int ntl = 0; ntl < 8; ntl++)
#pragma unroll
        for (int c = 0; c < 4; c++) d[ntl][c] = 0.f;

    {
        int r0 = mt * 16 + g;
        int r1 = r0 + 8;
#pragma unroll
        for (int ks = 0; ks < 4; ks++) {
            int kb = (ks * 4 + t) * 2;      // paired index of (kk0, kk0+4)
            uint2 a0h = *(const uint2*)&su[PHA_HI + r0 * 34 + kb];
            uint2 a1h = *(const uint2*)&su[PHA_HI + r1 * 34 + kb];
            uint2 a0l = *(const uint2*)&su[PHA_LO + r0 * 34 + kb];
            uint2 a1l = *(const uint2*)&su[PHA_LO + r1 * 34 + kb];
            unsigned ahi[4] = {a0h.x, a1h.x, a0h.y, a1h.y};
            unsigned alo[4] = {a0l.x, a1l.x, a0l.y, a1l.y};
#pragma unroll
            for (int ntl = 0; ntl < 8; ntl++) {
                int n = (nh * 8 + ntl) * 8 + g;
                uint2 bh = *(const uint2*)&su[PB_HI + n * 34 + kb];
                uint2 bl = *(const uint2*)&su[PB_LO + n * 34 + kb];
                unsigned bhi[2] = {bh.x, bh.y};
                unsigned blo[2] = {bl.x, bl.y};
                mma16816(d[ntl], ahi, bhi);
                mma16816(d[ntl], alo, bhi);
                mma16816(d[ntl], ahi, blo);
            }
        }
    }
    __syncthreads();   // phA/pB dead; safe to overlay sw

    // ---- store D -> sw[edge][col] with xor swizzle ----
    {
        int e0 = mt * 16 + g;
        int e1 = e0 + 8;
        int sw0 = (e0 & 7) << 2;
        int sw1 = (e1 & 7) << 2;
#pragma unroll
        for (int ntl = 0; ntl < 8; ntl++) {
            int c = (nh * 8 + ntl) * 8 + 2 * t;
            int b = c & ~31;
            int cc = c & 31;
            *(float2*)&sw[e0 * 128 + b + (cc ^ sw0)] = make_float2(d[ntl][0], d[ntl][1]);
            *(float2*)&sw[e1 * 128 + b + (cc ^ sw1)] = make_float2(d[ntl][2], d[ntl][3]);
        }
    }
    __syncthreads();   // TP warp reads rows produced by its warp pair

    // ---- warp-cooperative TP: warp th owns edges [th*8, th*8+8), lane = u ----
    int base = th * 8;

    float se_r[8];
#pragma unroll
    for (int j = 0; j < 8; j++) se_r[j] = g_s[ssrc[base + j] * 32 + lane];

    const float* vp0 = g_v + ssrc[base] * 96 + lane;
    float vxc = vp0[0], vyc = vp0[32], vzc = vp0[64];

    float A[8];
#pragma unroll
    for (int q = 0; q < 8; q++) A[q] = 0.f;

    int cur = sdst[base];
#pragma unroll
    for (int j = 0; j < 8; j++) {
        int pos = base + j;
        float vxn = 0.f, vyn = 0.f, vzn = 0.f;
        if (j < 7) {
            const float* vpn = g_v + ssrc[pos + 1] * 96 + lane;
            vxn = vpn[0]; vyn = vpn[32]; vzn = vpn[64];
        }
        int dd = sdst[pos];
        if (dd != cur) {
            float* q = g_agg + (size_t)cur * 256 + lane * 8;
            red_add_v4(q,     A[0], A[1], A[2], A[3]);
            red_add_v4(q + 4, A[4], A[5], A[6], A[7]);
#pragma unroll
            for (int qq = 0; qq < 8; qq++) A[qq] = 0.f;
            cur = dd;
        }
        float yy0 = sy0[pos];
        float y1x = sy1[pos * 3 + 0], y1y = sy1[pos * 3 + 1], y1z = sy1[pos * 3 + 2];
        float se = se_r[j];
        int sx = lane ^ ((pos & 7) << 2);
        int wb = pos * 128;
        float w1 = sw[wb + sx], w2 = sw[wb + 32 + sx], w3 = sw[wb + 64 + sx], w4 = sw[wb + 96 + sx];

        A[0] += w1 * (se * yy0);
        A[1] += w4 * (vxc * y1x + vyc * y1y + vzc * y1z);
        float a = w2 * se;
        A[2] += a * y1x; A[3] += a * y1y; A[4] += a * y1z;
        float b = w3 * yy0;
        A[5] += b * vxc; A[6] += b * vyc; A[7] += b * vzc;

        vxc = vxn; vyc = vyn; vzc = vzn;
    }
    float* q = g_agg + (size_t)cur * 256 + lane * 8;
    red_add_v4(q,     A[0], A[1], A[2], A[3]);
    red_add_v4(q + 4, A[4], A[5], A[6], A[7]);
}

// ---------------------------------------------------------------------------
// Kernel 3: linear_2 + self-connection (R8 version: 8 threads/node)
// ---------------------------------------------------------------------------
#define OUT_SMEM_FLOATS (2048 + 2048 + 8192 + 8192)

__global__ void __launch_bounds__(256)
k_out(const float* __restrict__ node_s,
      const float* __restrict__ node_v,
      const float* __restrict__ attrs,
      const float* __restrict__ W2s,
      const float* __restrict__ W2v,
      const float* __restrict__ Wscs,
      const float* __restrict__ Wscv,
      float* __restrict__ out) {
    extern __shared__ float sm[];
    float* sW2s  = sm;
    float* sW2v  = sW2s + 2048;
    float* sWscs = sW2v + 2048;
    float* sWscv = sWscs + 8192;

    int tid = threadIdx.x;
    for (int i = tid; i < 2048; i += 256) { sW2s[i]  = W2s[i]  * INV_2M;  sW2v[i]  = W2v[i]  * INV_2M; }
    for (int i = tid; i < 8192; i += 256) { sWscs[i] = Wscs[i] * INV_FAN; sWscv[i] = Wscv[i] * INV_FAN; }
    __syncthreads();

    int node = blockIdx.x * 32 + (tid >> 3);
    int part = tid & 7;
    int wo = part * 4;

    unsigned long long accs2[2] = {0ull, 0ull};
    unsigned long long accv2[3][2] = {{0ull, 0ull}, {0ull, 0ull}, {0ull, 0ull}};

    const float4* ag = reinterpret_cast<const float4*>(g_agg + (size_t)node * 256);
#pragma unroll 4
    for (int u = 0; u < 32; u++) {
        float4 Aq = ag[u * 2 + 0];
        float4 Bq = ag[u * 2 + 1];
#pragma unroll
        for (int half = 0; half < 2; half++) {
            int k = half * 32 + u;
            ulonglong2 ws = *(const ulonglong2*)&sW2s[k * 32 + wo];
            ulonglong2 wv = *(const ulonglong2*)&sW2v[k * 32 + wo];
            float as  = half ? Aq.y : Aq.x;
            float avx = half ? Bq.y : Aq.z;
            float avy = half ? Bq.z : Aq.w;
            float avz = half ? Bq.w : Bq.x;
            unsigned long long as2  = pack2(as, as);
            unsigned long long avx2 = pack2(avx, avx);
            unsigned long long avy2 = pack2(avy, avy);
            unsigned long long avz2 = pack2(avz, avz);
            fma2(accs2[0], as2, ws.x);
            fma2(accs2[1], as2, ws.y);
            fma2(accv2[0][0], avx2, wv.x);
            fma2(accv2[0][1], avx2, wv.y);
            fma2(accv2[1][0], avy2, wv.x);
            fma2(accv2[1][1], avy2, wv.y);
            fma2(accv2[2][0], avz2, wv.x);
            fma2(accv2[2][1], avz2, wv.y);
        }
    }

    unsigned long long at2[8];
    const float* arow = attrs + node * 8;
#pragma unroll
    for (int v = 0; v < 8; v++) { float a = arow[v]; at2[v] = pack2(a, a); }

    const float* srow = node_s + node * 32;
    const float* vrow = node_v + node * 96;
#pragma unroll 2
    for (int u = 0; u < 32; u++) {
        float su = srow[u];
        float vx = vrow[u * 3 + 0], vy = vrow[u * 3 + 1], vz = vrow[u * 3 + 2];
        unsigned long long Ts[2] = {0ull, 0ull};
        unsigned long long Tv[2] = {0ull, 0ull};
#pragma unroll
        for (int v = 0; v < 8; v++) {
            ulonglong2 ps = *(const ulonglong2*)&sWscs[(u * 8 + v) * 32 + wo];
            ulonglong2 pv = *(const ulonglong2*)&sWscv[(u * 8 + v) * 32 + wo];
            fma2(Ts[0], at2[v], ps.x);
            fma2(Ts[1], at2[v], ps.y);
            fma2(Tv[0], at2[v], pv.x);
            fma2(Tv[1], at2[v], pv.y);
        }
        unsigned long long su2 = pack2(su, su);
        unsigned long long vx2 = pack2(vx, vx);
        unsigned long long vy2 = pack2(vy, vy);
        unsigned long long vz2 = pack2(vz, vz);
#pragma unroll
        for (int p = 0; p < 2; p++) {
            fma2(accs2[p], su2, Ts[p]);
            fma2(accv2[0][p], vx2, Tv[p]);
            fma2(accv2[1][p], vy2, Tv[p]);
            fma2(accv2[2][p], vz2, Tv[p]);
        }
    }

    float* o = out + (size_t)node * 128;
#pragma unroll
    for (int p = 0; p < 2; p++) {
        float s0, s1;
        unpack2(s0, s1, accs2[p]);
        float v0[3], v1[3];
        unpack2(v0[0], v1[0], accv2[0][p]);
        unpack2(v0[1], v1[1], accv2[1][p]);
        unpack2(v0[2], v1[2], accv2[2][p]);
        int w0 = wo + p * 2;
        o[w0]     = s0;
        o[w0 + 1] = s1;
        o[32 + w0 * 3 + 0] = v0[0];
        o[32 + w0 * 3 + 1] = v0[1];
        o[32 + w0 * 3 + 2] = v0[2];
        o[32 + (w0 + 1) * 3 + 0] = v1[0];
        o[32 + (w0 + 1) * 3 + 1] = v1[1];
        o[32 + (w0 + 1) * 3 + 2] = v1[2];
    }
}

// ---------------------------------------------------------------------------
extern "C" void kernel_launch(void* const* d_in, const int* in_sizes, int n_in,
                              void* d_out, int out_size) {
    const float* node_s     = (const float*)d_in[0];
    const float* node_v     = (const float*)d_in[1];
    const float* node_attrs = (const float*)d_in[2];
    const float* edge_emb   = (const float*)d_in[3];
    const float* edge_y0    = (const float*)d_in[4];
    const float* edge_y1    = (const float*)d_in[5];
    const int*   edge_index = (const int*)d_in[6];
    const float* W1s        = (const float*)d_in[7];
    const float* W1v        = (const float*)d_in[8];
    const float* Wr1        = (const float*)d_in[9];
    const float* Wr2        = (const float*)d_in[10];
    const float* W2s        = (const float*)d_in[11];
    const float* W2v        = (const float*)d_in[12];
    const float* Wscs       = (const float*)d_in[13];
    const float* Wscv       = (const float*)d_in[14];
    float* out = (float*)d_out;

    cudaFuncSetAttribute(k_edge, cudaFuncAttributeMaxDynamicSharedMemorySize,
                         EDGE_SMEM_FLOATS * sizeof(float));
    cudaFuncSetAttribute(k_out, cudaFuncAttributeMaxDynamicSharedMemorySize,
                         OUT_SMEM_FLOATS * sizeof(float));

    k_zero<<<5000, 256>>>();
    k_hist<<<2500, 256>>>(edge_index);
    k_scan<<<1, 1024>>>();
    k_scatter<<<2500, 256>>>(edge_index);
    k_lin1<<<(2 * N_NODES + 255) / 256, 256>>>(node_s, node_v, W1s, W1v);
    k_edge<<<N_EDGES / ET, ETHREADS, EDGE_SMEM_FLOATS * sizeof(float)>>>(
        edge_emb, edge_y0, edge_y1, edge_index, Wr1, Wr2);
    k_out<<<(N_NODES * 8) / 256, 256, OUT_SMEM_FLOATS * sizeof(float)>>>(
        node_s, node_v, node_attrs, W2s, W2v, Wscs, Wscv, out);
}

// round 12
// speedup vs baseline: 1.2176x; 1.0154x over previous
#include <cuda_runtime.h>
#include <cstdint>

#define N_NODES 20000
#define N_EDGES 640000
#define MUL 32
#define ATTR 8
#define RB 16
#define FH 64

#define INV_M      0.17677669529663687f
#define INV_RB     0.25f
#define INV_FH     0.125f
#define INV_SQRT3  0.5773502691896258f
#define INV_DEG    0.17677669529663687f
#define INV_2M     0.125f
#define INV_FAN    0.0625f
#define LOG2F_     0.6931471805599453f

// Scratch (device globals)
__device__ float g_s[N_NODES * MUL];
__device__ float g_v[N_NODES * MUL * 3];      // SoA: [node][comp(3)][u(32)]
__device__ float g_agg[N_NODES * MUL * 8];
// sort scratch
__device__ int g_cnt[N_NODES];
__device__ int g_pos[N_NODES];
__device__ int g_off[N_NODES + 1];
__device__ int g_perm[N_EDGES];
// preprocessed weights (packed bf16x2 hi|lo image of Wr2^T, + scaled Wr1)
__device__ unsigned g_pBc[8704];
__device__ float g_Wr1c[1024];

__device__ __forceinline__ float sspf(float x) {
    return fmaxf(x, 0.0f) + log1pf(__expf(-fabsf(x))) - LOG2F_;
}

// no "memory" clobber — g_agg is write-only here and atomic adds commute
__device__ __forceinline__ void red_add_v4(float* addr, float a, float b, float c, float d) {
    asm volatile("red.global.add.v4.f32 [%0], {%1,%2,%3,%4};"
                 :: "l"(addr), "f"(a), "f"(b), "f"(c), "f"(d));
}

// ---- packed f32x2 helpers ----
__device__ __forceinline__ unsigned long long pack2(float x, float y) {
    unsigned long long r;
    asm("mov.b64 %0, {%1,%2};" : "=l"(r) : "f"(x), "f"(y));
    return r;
}
__device__ __forceinline__ void unpack2(float& x, float& y, unsigned long long r) {
    asm("mov.b64 {%0,%1}, %2;" : "=f"(x), "=f"(y) : "l"(r));
}
__device__ __forceinline__ void fma2(unsigned long long& d, unsigned long long a,
                                     unsigned long long b) {
    asm("fma.rn.f32x2 %0, %1, %2, %0;" : "+l"(d) : "l"(a), "l"(b));
}

// ---- bf16 pack helpers ----
__device__ __forceinline__ unsigned bf16x2_of(float x1, float x0) {
    unsigned r;
    asm("cvt.rn.bf16x2.f32 %0, %1, %2;" : "=r"(r) : "f"(x1), "f"(x0));
    return r;
}
__device__ __forceinline__ void bf16_hilo(float x0, float x1, unsigned& hi, unsigned& lo) {
    hi = bf16x2_of(x1, x0);
    float h0 = __uint_as_float(hi << 16);
    float h1 = __uint_as_float(hi & 0xffff0000u);
    lo = bf16x2_of(x1 - h1, x0 - h0);
}

__device__ __forceinline__ void mma16816(float* d, const unsigned* a, const unsigned* b) {
    asm volatile(
        "mma.sync.aligned.m16n8k16.row.col.f32.bf16.bf16.f32 "
        "{%0,%1,%2,%3}, {%4,%5,%6,%7}, {%8,%9}, {%0,%1,%2,%3};"
        : "+f"(d[0]), "+f"(d[1]), "+f"(d[2]), "+f"(d[3])
        : "r"(a[0]), "r"(a[1]), "r"(a[2]), "r"(a[3]), "r"(b[0]), "r"(b[1]));
}

// kk (bf16x2 word index 0..31) -> paired layout index so (kk, kk+4) are adjacent
__device__ __forceinline__ int kp_of(int kk) {
    int ks = kk >> 3, r = kk & 7;
    return ((ks << 2) + (r & 3)) * 2 + (r >> 2);
}

// ---------------------------------------------------------------------------
// One-shot weight preprocessing: packed/paired Wr2^T image + scaled Wr1
// ---------------------------------------------------------------------------
__global__ void k_prep(const float* __restrict__ Wr1,
                       const float* __restrict__ Wr2) {
    int tid = threadIdx.x;                      // 512 threads, 1 block
    for (int i = tid; i < 1024; i += 512) g_Wr1c[i] = Wr1[i] * INV_RB;
    for (int i = tid; i < 4096; i += 512) {
        int n = i & 127, kk = i >> 7;
        float sc = INV_FH * INV_DEG * ((n >= 96) ? INV_SQRT3 : 1.0f);
        float w0 = Wr2[(2 * kk) * 128 + n] * sc;
        float w1 = Wr2[(2 * kk + 1) * 128 + n] * sc;
        unsigned hi, lo;
        bf16_hilo(w0, w1, hi, lo);
        int kp = kp_of(kk);
        g_pBc[n * 34 + kp] = hi;                // matches smem PB_HI layout
        g_pBc[4352 + n * 34 + kp] = lo;         // matches smem PB_LO layout
    }
}

// ---------------------------------------------------------------------------
__global__ void k_zero() {
    int i = blockIdx.x * blockDim.x + threadIdx.x;
    float4* p = reinterpret_cast<float4*>(g_agg);
    p[i] = make_float4(0.f, 0.f, 0.f, 0.f);
    if (i < N_NODES) { g_cnt[i] = 0; g_pos[i] = 0; }
}

__global__ void k_hist(const int* __restrict__ eidx) {
    int e = blockIdx.x * blockDim.x + threadIdx.x;
    if (e < N_EDGES) atomicAdd(&g_cnt[eidx[N_EDGES + e]], 1);
}

__global__ void k_scan() {
    __shared__ int sh[1024];
    int tid = threadIdx.x;
    int base = tid * 20;
    int loc[20];
    int s = 0;
#pragma unroll
    for (int j = 0; j < 20; j++) {
        int idx = base + j;
        int c = (idx < N_NODES) ? g_cnt[idx] : 0;
        loc[j] = s;
        s += c;
    }
    sh[tid] = s;
    __syncthreads();
    for (int off = 1; off < 1024; off <<= 1) {
        int v = (tid >= off) ? sh[tid - off] : 0;
        __syncthreads();
        sh[tid] += v;
        __syncthreads();
    }
    int pre = (tid == 0) ? 0 : sh[tid - 1];
#pragma unroll
    for (int j = 0; j < 20; j++) {
        int idx = base + j;
        if (idx < N_NODES) g_off[idx] = pre + loc[j];
    }
    if (tid == 1023) g_off[N_NODES] = sh[1023];
}

__global__ void k_scatter(const int* __restrict__ eidx) {
    int e = blockIdx.x * blockDim.x + threadIdx.x;
    if (e < N_EDGES) {
        int dst = eidx[N_EDGES + e];
        int r = atomicAdd(&g_pos[dst], 1);
        g_perm[g_off[dst] + r] = e;
    }
}

// ---------------------------------------------------------------------------
// Kernel 1: linear_1 (writes g_v in SoA [node][comp][32])
// ---------------------------------------------------------------------------
__global__ void k_lin1(const float* __restrict__ node_s,
                       const float* __restrict__ node_v,
                       const float* __restrict__ W1s,
                       const float* __restrict__ W1v) {
    __shared__ float sW1s[1024];
    __shared__ float sW1v[1024];
    int tid = threadIdx.x;
    for (int i = tid; i < 1024; i += 256) {
        sW1s[i] = W1s[i] * INV_M;
        sW1v[i] = W1v[i] * INV_M;
    }
    __syncthreads();

    int gt = blockIdx.x * 256 + tid;
    int node = gt >> 1;
    int h = gt & 1;
    if (node >= N_NODES) return;

    float accs[16];
    float accv[16][3];
#pragma unroll
    for (int w = 0; w < 16; w++) { accs[w] = 0.f; accv[w][0] = accv[w][1] = accv[w][2] = 0.f; }

    const float* srow = node_s + node * 32;
    const float* vrow = node_v + node * 96;
    for (int u = 0; u < 32; u++) {
        float su = srow[u];
        float vx = vrow[u * 3 + 0], vy = vrow[u * 3 + 1], vz = vrow[u * 3 + 2];
        const float* ws = &sW1s[u * 32 + h * 16];
        const float* wv = &sW1v[u * 32 + h * 16];
#pragma unroll
        for (int w = 0; w < 16; w++) {
            accs[w]    += su * ws[w];
            accv[w][0] += vx * wv[w];
            accv[w][1] += vy * wv[w];
            accv[w][2] += vz * wv[w];
        }
    }
    float* so = g_s + node * 32 + h * 16;
    float* vo = g_v + node * 96 + h * 16;     // SoA: + comp*32
#pragma unroll
    for (int w = 0; w < 16; w++) {
        so[w] = accs[w];
        vo[w]      = accv[w][0];
        vo[32 + w] = accv[w][1];
        vo[64 + w] = accv[w][2];
    }
}

// ---------------------------------------------------------------------------
// Kernel 2: fused edge kernel (R11 structure), 512 threads.
// Weight staging is now a straight uint4 copy of the preprocessed image.
// ---------------------------------------------------------------------------
#define ET 128
#define ETHREADS 512
#define PHA_HI 0
#define PHA_LO 4352
#define PB_HI  8704
#define PB_LO  13056
#define WR1_OFF 17408
#define EMB_OFF 18432
#define META_OFF 20608
#define EDGE_SMEM_FLOATS 21504

__global__ void __launch_bounds__(ETHREADS, 2)
k_edge(const float* __restrict__ emb,
       const float* __restrict__ y0,
       const float* __restrict__ y1,
       const int*   __restrict__ eidx) {
    extern __shared__ float sm[];
    unsigned* su   = reinterpret_cast<unsigned*>(sm);
    float* sw   = sm;                     // overlay after MMA
    float* sWr1 = sm + WR1_OFF;
    float* semb = sm + EMB_OFF;
    int*   sperm = (int*)(sm + META_OFF);
    int*   ssrc  = sperm + 128;
    int*   sdst  = ssrc + 128;
    float* sy0   = (float*)(sdst + 128);
    float* sy1   = sy0 + 128;

    int tid = threadIdx.x;
    int p0 = blockIdx.x * ET;

    if (tid < 128) sperm[tid] = g_perm[p0 + tid];
    // straight copies of preprocessed weight images
    {
        const uint4* s4 = reinterpret_cast<const uint4*>(g_pBc);
        uint4* d4 = reinterpret_cast<uint4*>(su + PB_HI);
        for (int i = tid; i < 2176; i += ETHREADS) d4[i] = s4[i];
        const float4* w4 = reinterpret_cast<const float4*>(g_Wr1c);
        float4* dw = reinterpret_cast<float4*>(sWr1);
        for (int i = tid; i < 256; i += ETHREADS) dw[i] = w4[i];
    }
    __syncthreads();

    if (tid < 128) {
        int e = sperm[tid];
        ssrc[tid] = eidx[e];
        sdst[tid] = eidx[N_EDGES + e];
        sy0[tid] = y0[e];
    }
    for (int i = tid; i < 384; i += ETHREADS) {
        int pos = i / 3, comp = i - pos * 3;
        sy1[i] = y1[sperm[pos] * 3 + comp];
    }
    for (int i = tid; i < ET * RB; i += ETHREADS) {
        int pos = i >> 4, k = i & 15;
        semb[pos * 17 + k] = emb[sperm[pos] * 16 + k];
    }
    __syncthreads();

    int lane = tid & 31;
    int th = tid >> 5;          // 0..15
    int cg = th >> 1;           // GEMM1 col group 0..7
    int eh = th & 1;            // GEMM1 edge half

    // ---- GEMM1 (fp32): 2 edges x 8 cols per thread ----
    float acc1[2][8];
#pragma unroll
    for (int j = 0; j < 2; j++)
#pragma unroll
        for (int m = 0; m < 8; m++) acc1[j][m] = 0.f;

    for (int k = 0; k < 16; k++) {
        float em[2];
#pragma unroll
        for (int j = 0; j < 2; j++) em[j] = semb[(lane + 32 * (eh * 2 + j)) * 17 + k];
        float wr[8];
#pragma unroll
        for (int m = 0; m < 8; m++) wr[m] = sWr1[k * 64 + cg * 8 + m];
#pragma unroll
        for (int j = 0; j < 2; j++)
#pragma unroll
            for (int m = 0; m < 8; m++) acc1[j][m] += em[j] * wr[m];
    }
#pragma unroll
    for (int j = 0; j < 2; j++) {
        int edge = lane + 32 * (eh * 2 + j);
#pragma unroll
        for (int m = 0; m < 8; m += 2) {
            float x0 = sspf(acc1[j][m]);
            float x1 = sspf(acc1[j][m + 1]);
            unsigned hi, lo;
            bf16_hilo(x0, x1, hi, lo);
            int kp = kp_of(cg * 4 + (m >> 1));
            su[PHA_HI + edge * 34 + kp] = hi;
            su[PHA_LO + edge * 34 + kp] = lo;
        }
    }
    __syncthreads();

    // ---- GEMM2 via mma.sync: warp pair (mt, nh); LDS.64 fragment loads ----
    int g = lane >> 2;
    int t = lane & 3;
    int mt = th >> 1;           // M-tile: edges [mt*16, mt*16+16)
    int nh = th & 1;            // N half
    float d[8][4];
#pragma unroll
    for (int ntl = 0; ntl < 8; ntl++)
#pragma unroll
        for (int c = 0; c < 4; c++) d[ntl][c] = 0.f;

    {
        int r0 = mt * 16 + g;
        int r1 = r0 + 8;
#pragma unroll
        for (int ks = 0; ks < 4; ks++) {
            int kb = (ks * 4 + t) * 2;      // paired index of (kk0, kk0+4)
            uint2 a0h = *(const uint2*)&su[PHA_HI + r0 * 34 + kb];
            uint2 a1h = *(const uint2*)&su[PHA_HI + r1 * 34 + kb];
            uint2 a0l = *(const uint2*)&su[PHA_LO + r0 * 34 + kb];
            uint2 a1l = *(const uint2*)&su[PHA_LO + r1 * 34 + kb];
            unsigned ahi[4] = {a0h.x, a1h.x, a0h.y, a1h.y};
            unsigned alo[4] = {a0l.x, a1l.x, a0l.y, a1l.y};
#pragma unroll
            for (int ntl = 0; ntl < 8; ntl++) {
                int n = (nh * 8 + ntl) * 8 + g;
                uint2 bh = *(const uint2*)&su[PB_HI + n * 34 + kb];
                uint2 bl = *(const uint2*)&su[PB_LO + n * 34 + kb];
                unsigned bhi[2] = {bh.x, bh.y};
                unsigned blo[2] = {bl.x, bl.y};
                mma16816(d[ntl], ahi, bhi);
                mma16816(d[ntl], alo, bhi);
                mma16816(d[ntl], ahi, blo);
            }
        }
    }
    __syncthreads();   // phA/pB dead; safe to overlay sw

    // ---- store D -> sw[edge][col] with xor swizzle ----
    {
        int e0 = mt * 16 + g;
        int e1 = e0 + 8;
        int sw0 = (e0 & 7) << 2;
        int sw1 = (e1 & 7) << 2;
#pragma unroll
        for (int ntl = 0; ntl < 8; ntl++) {
            int c = (nh * 8 + ntl) * 8 + 2 * t;
            int b = c & ~31;
            int cc = c & 31;
            *(float2*)&sw[e0 * 128 + b + (cc ^ sw0)] = make_float2(d[ntl][0], d[ntl][1]);
            *(float2*)&sw[e1 * 128 + b + (cc ^ sw1)] = make_float2(d[ntl][2], d[ntl][3]);
        }
    }
    __syncthreads();   // TP warp reads rows produced by its warp pair

    // ---- warp-cooperative TP: warp th owns edges [th*8, th*8+8), lane = u ----
    int base = th * 8;

    float se_r[8];
#pragma unroll
    for (int j = 0; j < 8; j++) se_r[j] = g_s[ssrc[base + j] * 32 + lane];

    const float* vp0 = g_v + ssrc[base] * 96 + lane;
    float vxc = vp0[0], vyc = vp0[32], vzc = vp0[64];

    float A[8];
#pragma unroll
    for (int q = 0; q < 8; q++) A[q] = 0.f;

    int cur = sdst[base];
#pragma unroll
    for (int j = 0; j < 8; j++) {
        int pos = base + j;
        float vxn = 0.f, vyn = 0.f, vzn = 0.f;
        if (j < 7) {
            const float* vpn = g_v + ssrc[pos + 1] * 96 + lane;
            vxn = vpn[0]; vyn = vpn[32]; vzn = vpn[64];
        }
        int dd = sdst[pos];
        if (dd != cur) {
            float* q = g_agg + (size_t)cur * 256 + lane * 8;
            red_add_v4(q,     A[0], A[1], A[2], A[3]);
            red_add_v4(q + 4, A[4], A[5], A[6], A[7]);
#pragma unroll
            for (int qq = 0; qq < 8; qq++) A[qq] = 0.f;
            cur = dd;
        }
        float yy0 = sy0[pos];
        float y1x = sy1[pos * 3 + 0], y1y = sy1[pos * 3 + 1], y1z = sy1[pos * 3 + 2];
        float se = se_r[j];
        int sx = lane ^ ((pos & 7) << 2);
        int wb = pos * 128;
        float w1 = sw[wb + sx], w2 = sw[wb + 32 + sx], w3 = sw[wb + 64 + sx], w4 = sw[wb + 96 + sx];

        A[0] += w1 * (se * yy0);
        A[1] += w4 * (vxc * y1x + vyc * y1y + vzc * y1z);
        float a = w2 * se;
        A[2] += a * y1x; A[3] += a * y1y; A[4] += a * y1z;
        float b = w3 * yy0;
        A[5] += b * vxc; A[6] += b * vyc; A[7] += b * vzc;

        vxc = vxn; vyc = vyn; vzc = vzn;
    }
    float* q = g_agg + (size_t)cur * 256 + lane * 8;
    red_add_v4(q,     A[0], A[1], A[2], A[3]);
    red_add_v4(q + 4, A[4], A[5], A[6], A[7]);
}

// ---------------------------------------------------------------------------
// Kernel 3: linear_2 + self-connection (8 threads/node)
// ---------------------------------------------------------------------------
#define OUT_SMEM_FLOATS (2048 + 2048 + 8192 + 8192)

__global__ void __launch_bounds__(256)
k_out(const float* __restrict__ node_s,
      const float* __restrict__ node_v,
      const float* __restrict__ attrs,
      const float* __restrict__ W2s,
      const float* __restrict__ W2v,
      const float* __restrict__ Wscs,
      const float* __restrict__ Wscv,
      float* __restrict__ out) {
    extern __shared__ float sm[];
    float* sW2s  = sm;
    float* sW2v  = sW2s + 2048;
    float* sWscs = sW2v + 2048;
    float* sWscv = sWscs + 8192;

    int tid = threadIdx.x;
    for (int i = tid; i < 2048; i += 256) { sW2s[i]  = W2s[i]  * INV_2M;  sW2v[i]  = W2v[i]  * INV_2M; }
    for (int i = tid; i < 8192; i += 256) { sWscs[i] = Wscs[i] * INV_FAN; sWscv[i] = Wscv[i] * INV_FAN; }
    __syncthreads();

    int node = blockIdx.x * 32 + (tid >> 3);
    int part = tid & 7;
    int wo = part * 4;

    unsigned long long accs2[2] = {0ull, 0ull};
    unsigned long long accv2[3][2] = {{0ull, 0ull}, {0ull, 0ull}, {0ull, 0ull}};

    const float4* ag = reinterpret_cast<const float4*>(g_agg + (size_t)node * 256);
#pragma unroll 4
    for (int u = 0; u < 32; u++) {
        float4 Aq = ag[u * 2 + 0];
        float4 Bq = ag[u * 2 + 1];
#pragma unroll
        for (int half = 0; half < 2; half++) {
            int k = half * 32 + u;
            ulonglong2 ws = *(const ulonglong2*)&sW2s[k * 32 + wo];
            ulonglong2 wv = *(const ulonglong2*)&sW2v[k * 32 + wo];
            float as  = half ? Aq.y : Aq.x;
            float avx = half ? Bq.y : Aq.z;
            float avy = half ? Bq.z : Aq.w;
            float avz = half ? Bq.w : Bq.x;
            unsigned long long as2  = pack2(as, as);
            unsigned long long avx2 = pack2(avx, avx);
            unsigned long long avy2 = pack2(avy, avy);
            unsigned long long avz2 = pack2(avz, avz);
            fma2(accs2[0], as2, ws.x);
            fma2(accs2[1], as2, ws.y);
            fma2(accv2[0][0], avx2, wv.x);
            fma2(accv2[0][1], avx2, wv.y);
            fma2(accv2[1][0], avy2, wv.x);
            fma2(accv2[1][1], avy2, wv.y);
            fma2(accv2[2][0], avz2, wv.x);
            fma2(accv2[2][1], avz2, wv.y);
        }
    }

    unsigned long long at2[8];
    const float* arow = attrs + node * 8;
#pragma unroll
    for (int v = 0; v < 8; v++) { float a = arow[v]; at2[v] = pack2(a, a); }

    const float* srow = node_s + node * 32;
    const float* vrow = node_v + node * 96;
#pragma unroll 2
    for (int u = 0; u < 32; u++) {
        float su = srow[u];
        float vx = vrow[u * 3 + 0], vy = vrow[u * 3 + 1], vz = vrow[u * 3 + 2];
        unsigned long long Ts[2] = {0ull, 0ull};
        unsigned long long Tv[2] = {0ull, 0ull};
#pragma unroll
        for (int v = 0; v < 8; v++) {
            ulonglong2 ps = *(const ulonglong2*)&sWscs[(u * 8 + v) * 32 + wo];
            ulonglong2 pv = *(const ulonglong2*)&sWscv[(u * 8 + v) * 32 + wo];
            fma2(Ts[0], at2[v], ps.x);
            fma2(Ts[1], at2[v], ps.y);
            fma2(Tv[0], at2[v], pv.x);
            fma2(Tv[1], at2[v], pv.y);
        }
        unsigned long long su2 = pack2(su, su);
        unsigned long long vx2 = pack2(vx, vx);
        unsigned long long vy2 = pack2(vy, vy);
        unsigned long long vz2 = pack2(vz, vz);
#pragma unroll
        for (int p = 0; p < 2; p++) {
            fma2(accs2[p], su2, Ts[p]);
            fma2(accv2[0][p], vx2, Tv[p]);
            fma2(accv2[1][p], vy2, Tv[p]);
            fma2(accv2[2][p], vz2, Tv[p]);
        }
    }

    float* o = out + (size_t)node * 128;
#pragma unroll
    for (int p = 0; p < 2; p++) {
        float s0, s1;
        unpack2(s0, s1, accs2[p]);
        float v0[3], v1[3];
        unpack2(v0[0], v1[0], accv2[0][p]);
        unpack2(v0[1], v1[1], accv2[1][p]);
        unpack2(v0[2], v1[2], accv2[2][p]);
        int w0 = wo + p * 2;
        o[w0]     = s0;
        o[w0 + 1] = s1;
        o[32 + w0 * 3 + 0] = v0[0];
        o[32 + w0 * 3 + 1] = v0[1];
        o[32 + w0 * 3 + 2] = v0[2];
        o[32 + (w0 + 1) * 3 + 0] = v1[0];
        o[32 + (w0 + 1) * 3 + 1] = v1[1];
        o[32 + (w0 + 1) * 3 + 2] = v1[2];
    }
}

// ---------------------------------------------------------------------------
extern "C" void kernel_launch(void* const* d_in, const int* in_sizes, int n_in,
                              void* d_out, int out_size) {
    const float* node_s     = (const float*)d_in[0];
    const float* node_v     = (const float*)d_in[1];
    const float* node_attrs = (const float*)d_in[2];
    const float* edge_emb   = (const float*)d_in[3];
    const float* edge_y0    = (const float*)d_in[4];
    const float* edge_y1    = (const float*)d_in[5];
    const int*   edge_index = (const int*)d_in[6];
    const float* W1s        = (const float*)d_in[7];
    const float* W1v        = (const float*)d_in[8];
    const float* Wr1        = (const float*)d_in[9];
    const float* Wr2        = (const float*)d_in[10];
    const float* W2s        = (const float*)d_in[11];
    const float* W2v        = (const float*)d_in[12];
    const float* Wscs       = (const float*)d_in[13];
    const float* Wscv       = (const float*)d_in[14];
    float* out = (float*)d_out;

    cudaFuncSetAttribute(k_edge, cudaFuncAttributeMaxDynamicSharedMemorySize,
                         EDGE_SMEM_FLOATS * sizeof(float));
    cudaFuncSetAttribute(k_out, cudaFuncAttributeMaxDynamicSharedMemorySize,
                         OUT_SMEM_FLOATS * sizeof(float));

    k_prep<<<1, 512>>>(Wr1, Wr2);
    k_zero<<<5000, 256>>>();
    k_hist<<<2500, 256>>>(edge_index);
    k_scan<<<1, 1024>>>();
    k_scatter<<<2500, 256>>>(edge_index);
    k_lin1<<<(2 * N_NODES + 255) / 256, 256>>>(node_s, node_v, W1s, W1v);
    k_edge<<<N_EDGES / ET, ETHREADS, EDGE_SMEM_FLOATS * sizeof(float)>>>(
        edge_emb, edge_y0, edge_y1, edge_index);
    k_out<<<(N_NODES * 8) / 256, 256, OUT_SMEM_FLOATS * sizeof(float)>>>(
        node_s, node_v, node_attrs, W2s, W2v, Wscs, Wscv, out);
}

// round 13
// speedup vs baseline: 1.2272x; 1.0079x over previous
#include <cuda_runtime.h>
#include <cstdint>

#define N_NODES 20000
#define N_EDGES 640000
#define MUL 32
#define ATTR 8
#define RB 16
#define FH 64

#define INV_M      0.17677669529663687f
#define INV_RB     0.25f
#define INV_FH     0.125f
#define INV_SQRT3  0.5773502691896258f
#define INV_DEG    0.17677669529663687f
#define INV_2M     0.125f
#define INV_FAN    0.0625f
#define LOG2F_     0.6931471805599453f

// Scratch (device globals)
__device__ float g_s[N_NODES * MUL];
__device__ float g_v[N_NODES * MUL * 3];      // SoA: [node][comp(3)][u(32)]
__device__ float g_agg[N_NODES * MUL * 8];
// sort scratch
__device__ int g_cnt[N_NODES];
__device__ int g_pos[N_NODES];
__device__ int g_off[N_NODES + 1];
__device__ int g_perm[N_EDGES];
// preprocessed weights (packed bf16x2 hi|lo image of Wr2^T, + scaled Wr1)
__device__ unsigned g_pBc[8704];
__device__ float g_Wr1c[1024];

__device__ __forceinline__ float sspf(float x) {
    return fmaxf(x, 0.0f) + log1pf(__expf(-fabsf(x))) - LOG2F_;
}

// no "memory" clobber — g_agg is write-only here and atomic adds commute
__device__ __forceinline__ void red_add_v4(float* addr, float a, float b, float c, float d) {
    asm volatile("red.global.add.v4.f32 [%0], {%1,%2,%3,%4};"
                 :: "l"(addr), "f"(a), "f"(b), "f"(c), "f"(d));
}

// ---- packed f32x2 helpers ----
__device__ __forceinline__ unsigned long long pack2(float x, float y) {
    unsigned long long r;
    asm("mov.b64 %0, {%1,%2};" : "=l"(r) : "f"(x), "f"(y));
    return r;
}
__device__ __forceinline__ void unpack2(float& x, float& y, unsigned long long r) {
    asm("mov.b64 {%0,%1}, %2;" : "=f"(x), "=f"(y) : "l"(r));
}
__device__ __forceinline__ void fma2(unsigned long long& d, unsigned long long a,
                                     unsigned long long b) {
    asm("fma.rn.f32x2 %0, %1, %2, %0;" : "+l"(d) : "l"(a), "l"(b));
}

// ---- bf16 pack helpers ----
__device__ __forceinline__ unsigned bf16x2_of(float x1, float x0) {
    unsigned r;
    asm("cvt.rn.bf16x2.f32 %0, %1, %2;" : "=r"(r) : "f"(x1), "f"(x0));
    return r;
}
__device__ __forceinline__ void bf16_hilo(float x0, float x1, unsigned& hi, unsigned& lo) {
    hi = bf16x2_of(x1, x0);
    float h0 = __uint_as_float(hi << 16);
    float h1 = __uint_as_float(hi & 0xffff0000u);
    lo = bf16x2_of(x1 - h1, x0 - h0);
}

__device__ __forceinline__ void mma16816(float* d, const unsigned* a, const unsigned* b) {
    asm volatile(
        "mma.sync.aligned.m16n8k16.row.col.f32.bf16.bf16.f32 "
        "{%0,%1,%2,%3}, {%4,%5,%6,%7}, {%8,%9}, {%0,%1,%2,%3};"
        : "+f"(d[0]), "+f"(d[1]), "+f"(d[2]), "+f"(d[3])
        : "r"(a[0]), "r"(a[1]), "r"(a[2]), "r"(a[3]), "r"(b[0]), "r"(b[1]));
}

// kk (bf16x2 word index 0..31) -> paired layout index so (kk, kk+4) are adjacent
__device__ __forceinline__ int kp_of(int kk) {
    int ks = kk >> 3, r = kk & 7;
    return ((ks << 2) + (r & 3)) * 2 + (r >> 2);
}

// ---------------------------------------------------------------------------
// One-shot weight preprocessing: packed/paired Wr2^T image + scaled Wr1
// ---------------------------------------------------------------------------
__global__ void k_prep(const float* __restrict__ Wr1,
                       const float* __restrict__ Wr2) {
    int tid = threadIdx.x;                      // 512 threads, 1 block
    for (int i = tid; i < 1024; i += 512) g_Wr1c[i] = Wr1[i] * INV_RB;
    for (int i = tid; i < 4096; i += 512) {
        int n = i & 127, kk = i >> 7;
        float sc = INV_FH * INV_DEG * ((n >= 96) ? INV_SQRT3 : 1.0f);
        float w0 = Wr2[(2 * kk) * 128 + n] * sc;
        float w1 = Wr2[(2 * kk + 1) * 128 + n] * sc;
        unsigned hi, lo;
        bf16_hilo(w0, w1, hi, lo);
        int kp = kp_of(kk);
        g_pBc[n * 34 + kp] = hi;                // matches smem PB_HI layout
        g_pBc[4352 + n * 34 + kp] = lo;         // matches smem PB_LO layout
    }
}

// ---------------------------------------------------------------------------
__global__ void k_zero() {
    int i = blockIdx.x * blockDim.x + threadIdx.x;
    float4* p = reinterpret_cast<float4*>(g_agg);
    p[i] = make_float4(0.f, 0.f, 0.f, 0.f);
    if (i < N_NODES) { g_cnt[i] = 0; g_pos[i] = 0; }
}

__global__ void k_hist(const int* __restrict__ eidx) {
    int e = blockIdx.x * blockDim.x + threadIdx.x;
    if (e < N_EDGES) atomicAdd(&g_cnt[eidx[N_EDGES + e]], 1);
}

// ---------------------------------------------------------------------------
// k_scan: 3-barrier shuffle scan with coalesced smem staging.
// 1024 threads; threads 0..999 each own 20 consecutive counts.
// Dynamic smem: 20000 ints (counts -> offsets in place) + 32 warp sums.
// ---------------------------------------------------------------------------
__global__ void k_scan() {
    extern __shared__ int si[];               // [20000] + warp sums at [20000..20032)
    int* swarp = si + 20000;
    int tid = threadIdx.x;
    int lane = tid & 31;
    int wid = tid >> 5;

    // coalesced stage of counts
    for (int i = tid; i < N_NODES; i += 1024) si[i] = g_cnt[i];
    __syncthreads();

    // local sum of 20
    int base = tid * 20;
    int s = 0;
    if (tid < 1000) {
#pragma unroll
        for (int j = 0; j < 20; j++) s += si[base + j];
    }
    int own = s;

    // warp inclusive scan (shuffle)
#pragma unroll
    for (int off = 1; off < 32; off <<= 1) {
        int v = __shfl_up_sync(0xffffffffu, s, off);
        if (lane >= off) s += v;
    }
    if (lane == 31) swarp[wid] = s;
    __syncthreads();

    // warp 0 scans the 32 warp totals
    if (wid == 0) {
        int v = swarp[lane];
#pragma unroll
        for (int off = 1; off < 32; off <<= 1) {
            int u = __shfl_up_sync(0xffffffffu, v, off);
            if (lane >= off) v += u;
        }
        swarp[lane] = v;
    }
    __syncthreads();

    // exclusive prefix for this thread's chunk
    int warp_excl = (wid == 0) ? 0 : swarp[wid - 1];
    int excl = warp_excl + (s - own);          // s = inclusive within warp

    if (tid < 1000) {
        int running = excl;
#pragma unroll
        for (int j = 0; j < 20; j++) {
            int c = si[base + j];
            si[base + j] = running;
            running += c;
        }
    }
    __syncthreads();

    // coalesced store of offsets
    for (int i = tid; i < N_NODES; i += 1024) g_off[i] = si[i];
    if (tid == 0) g_off[N_NODES] = swarp[31];  // grand total
}

__global__ void k_scatter(const int* __restrict__ eidx) {
    int e = blockIdx.x * blockDim.x + threadIdx.x;
    if (e < N_EDGES) {
        int dst = eidx[N_EDGES + e];
        int r = atomicAdd(&g_pos[dst], 1);
        g_perm[g_off[dst] + r] = e;
    }
}

// ---------------------------------------------------------------------------
// Kernel 1: linear_1 (writes g_v in SoA [node][comp][32])
// ---------------------------------------------------------------------------
__global__ void k_lin1(const float* __restrict__ node_s,
                       const float* __restrict__ node_v,
                       const float* __restrict__ W1s,
                       const float* __restrict__ W1v) {
    __shared__ float sW1s[1024];
    __shared__ float sW1v[1024];
    int tid = threadIdx.x;
    for (int i = tid; i < 1024; i += 256) {
        sW1s[i] = W1s[i] * INV_M;
        sW1v[i] = W1v[i] * INV_M;
    }
    __syncthreads();

    int gt = blockIdx.x * 256 + tid;
    int node = gt >> 1;
    int h = gt & 1;
    if (node >= N_NODES) return;

    float accs[16];
    float accv[16][3];
#pragma unroll
    for (int w = 0; w < 16; w++) { accs[w] = 0.f; accv[w][0] = accv[w][1] = accv[w][2] = 0.f; }

    const float* srow = node_s + node * 32;
    const float* vrow = node_v + node * 96;
    for (int u = 0; u < 32; u++) {
        float su = srow[u];
        float vx = vrow[u * 3 + 0], vy = vrow[u * 3 + 1], vz = vrow[u * 3 + 2];
        const float* ws = &sW1s[u * 32 + h * 16];
        const float* wv = &sW1v[u * 32 + h * 16];
#pragma unroll
        for (int w = 0; w < 16; w++) {
            accs[w]    += su * ws[w];
            accv[w][0] += vx * wv[w];
            accv[w][1] += vy * wv[w];
            accv[w][2] += vz * wv[w];
        }
    }
    float* so = g_s + node * 32 + h * 16;
    float* vo = g_v + node * 96 + h * 16;     // SoA: + comp*32
#pragma unroll
    for (int w = 0; w < 16; w++) {
        so[w] = accs[w];
        vo[w]      = accv[w][0];
        vo[32 + w] = accv[w][1];
        vo[64 + w] = accv[w][2];
    }
}

// ---------------------------------------------------------------------------
// Kernel 2: fused edge kernel (R12 structure), 512 threads.
// ---------------------------------------------------------------------------
#define ET 128
#define ETHREADS 512
#define PHA_HI 0
#define PHA_LO 4352
#define PB_HI  8704
#define PB_LO  13056
#define WR1_OFF 17408
#define EMB_OFF 18432
#define META_OFF 20608
#define EDGE_SMEM_FLOATS 21504

__global__ void __launch_bounds__(ETHREADS, 2)
k_edge(const float* __restrict__ emb,
       const float* __restrict__ y0,
       const float* __restrict__ y1,
       const int*   __restrict__ eidx) {
    extern __shared__ float sm[];
    unsigned* su   = reinterpret_cast<unsigned*>(sm);
    float* sw   = sm;                     // overlay after MMA
    float* sWr1 = sm + WR1_OFF;
    float* semb = sm + EMB_OFF;
    int*   sperm = (int*)(sm + META_OFF);
    int*   ssrc  = sperm + 128;
    int*   sdst  = ssrc + 128;
    float* sy0   = (float*)(sdst + 128);
    float* sy1   = sy0 + 128;

    int tid = threadIdx.x;
    int p0 = blockIdx.x * ET;

    if (tid < 128) sperm[tid] = g_perm[p0 + tid];
    // straight copies of preprocessed weight images
    {
        const uint4* s4 = reinterpret_cast<const uint4*>(g_pBc);
        uint4* d4 = reinterpret_cast<uint4*>(su + PB_HI);
        for (int i = tid; i < 2176; i += ETHREADS) d4[i] = s4[i];
        const float4* w4 = reinterpret_cast<const float4*>(g_Wr1c);
        float4* dw = reinterpret_cast<float4*>(sWr1);
        for (int i = tid; i < 256; i += ETHREADS) dw[i] = w4[i];
    }
    __syncthreads();

    if (tid < 128) {
        int e = sperm[tid];
        ssrc[tid] = eidx[e];
        sdst[tid] = eidx[N_EDGES + e];
        sy0[tid] = y0[e];
    }
    for (int i = tid; i < 384; i += ETHREADS) {
        int pos = i / 3, comp = i - pos * 3;
        sy1[i] = y1[sperm[pos] * 3 + comp];
    }
    for (int i = tid; i < ET * RB; i += ETHREADS) {
        int pos = i >> 4, k = i & 15;
        semb[pos * 17 + k] = emb[sperm[pos] * 16 + k];
    }
    __syncthreads();

    int lane = tid & 31;
    int th = tid >> 5;          // 0..15
    int cg = th >> 1;           // GEMM1 col group 0..7
    int eh = th & 1;            // GEMM1 edge half

    // ---- GEMM1 (fp32): 2 edges x 8 cols per thread ----
    float acc1[2][8];
#pragma unroll
    for (int j = 0; j < 2; j++)
#pragma unroll
        for (int m = 0; m < 8; m++) acc1[j][m] = 0.f;

    for (int k = 0; k < 16; k++) {
        float em[2];
#pragma unroll
        for (int j = 0; j < 2; j++) em[j] = semb[(lane + 32 * (eh * 2 + j)) * 17 + k];
        float wr[8];
#pragma unroll
        for (int m = 0; m < 8; m++) wr[m] = sWr1[k * 64 + cg * 8 + m];
#pragma unroll
        for (int j = 0; j < 2; j++)
#pragma unroll
            for (int m = 0; m < 8; m++) acc1[j][m] += em[j] * wr[m];
    }
#pragma unroll
    for (int j = 0; j < 2; j++) {
        int edge = lane + 32 * (eh * 2 + j);
#pragma unroll
        for (int m = 0; m < 8; m += 2) {
            float x0 = sspf(acc1[j][m]);
            float x1 = sspf(acc1[j][m + 1]);
            unsigned hi, lo;
            bf16_hilo(x0, x1, hi, lo);
            int kp = kp_of(cg * 4 + (m >> 1));
            su[PHA_HI + edge * 34 + kp] = hi;
            su[PHA_LO + edge * 34 + kp] = lo;
        }
    }
    __syncthreads();

    // ---- GEMM2 via mma.sync: warp pair (mt, nh); LDS.64 fragment loads ----
    int g = lane >> 2;
    int t = lane & 3;
    int mt = th >> 1;           // M-tile: edges [mt*16, mt*16+16)
    int nh = th & 1;            // N half
    float d[8][4];
#pragma unroll
    for (int ntl = 0; ntl < 8; ntl++)
#pragma unroll
        for (int c = 0; c < 4; c++) d[ntl][c] = 0.f;

    {
        int r0 = mt * 16 + g;
        int r1 = r0 + 8;
#pragma unroll
        for (int ks = 0; ks < 4; ks++) {
            int kb = (ks * 4 + t) * 2;      // paired index of (kk0, kk0+4)
            uint2 a0h = *(const uint2*)&su[PHA_HI + r0 * 34 + kb];
            uint2 a1h = *(const uint2*)&su[PHA_HI + r1 * 34 + kb];
            uint2 a0l = *(const uint2*)&su[PHA_LO + r0 * 34 + kb];
            uint2 a1l = *(const uint2*)&su[PHA_LO + r1 * 34 + kb];
            unsigned ahi[4] = {a0h.x, a1h.x, a0h.y, a1h.y};
            unsigned alo[4] = {a0l.x, a1l.x, a0l.y, a1l.y};
#pragma unroll
            for (int ntl = 0; ntl < 8; ntl++) {
                int n = (nh * 8 + ntl) * 8 + g;
                uint2 bh = *(const uint2*)&su[PB_HI + n * 34 + kb];
                uint2 bl = *(const uint2*)&su[PB_LO + n * 34 + kb];
                unsigned bhi[2] = {bh.x, bh.y};
                unsigned blo[2] = {bl.x, bl.y};
                mma16816(d[ntl], ahi, bhi);
                mma16816(d[ntl], alo, bhi);
                mma16816(d[ntl], ahi, blo);
            }
        }
    }
    __syncthreads();   // phA/pB dead; safe to overlay sw

    // ---- store D -> sw[edge][col] with xor swizzle ----
    {
        int e0 = mt * 16 + g;
        int e1 = e0 + 8;
        int sw0 = (e0 & 7) << 2;
        int sw1 = (e1 & 7) << 2;
#pragma unroll
        for (int ntl = 0; ntl < 8; ntl++) {
            int c = (nh * 8 + ntl) * 8 + 2 * t;
            int b = c & ~31;
            int cc = c & 31;
            *(float2*)&sw[e0 * 128 + b + (cc ^ sw0)] = make_float2(d[ntl][0], d[ntl][1]);
            *(float2*)&sw[e1 * 128 + b + (cc ^ sw1)] = make_float2(d[ntl][2], d[ntl][3]);
        }
    }
    __syncthreads();   // TP warp reads rows produced by its warp pair

    // ---- warp-cooperative TP: warp th owns edges [th*8, th*8+8), lane = u ----
    int base = th * 8;

    float se_r[8];
#pragma unroll
    for (int j = 0; j < 8; j++) se_r[j] = g_s[ssrc[base + j] * 32 + lane];

    const float* vp0 = g_v + ssrc[base] * 96 + lane;
    float vxc = vp0[0], vyc = vp0[32], vzc = vp0[64];

    float A[8];
#pragma unroll
    for (int q = 0; q < 8; q++) A[q] = 0.f;

    int cur = sdst[base];
#pragma unroll
    for (int j = 0; j < 8; j++) {
        int pos = base + j;
        float vxn = 0.f, vyn = 0.f, vzn = 0.f;
        if (j < 7) {
            const float* vpn = g_v + ssrc[pos + 1] * 96 + lane;
            vxn = vpn[0]; vyn = vpn[32]; vzn = vpn[64];
        }
        int dd = sdst[pos];
        if (dd != cur) {
            float* q = g_agg + (size_t)cur * 256 + lane * 8;
            red_add_v4(q,     A[0], A[1], A[2], A[3]);
            red_add_v4(q + 4, A[4], A[5], A[6], A[7]);
#pragma unroll
            for (int qq = 0; qq < 8; qq++) A[qq] = 0.f;
            cur = dd;
        }
        float yy0 = sy0[pos];
        float y1x = sy1[pos * 3 + 0], y1y = sy1[pos * 3 + 1], y1z = sy1[pos * 3 + 2];
        float se = se_r[j];
        int sx = lane ^ ((pos & 7) << 2);
        int wb = pos * 128;
        float w1 = sw[wb + sx], w2 = sw[wb + 32 + sx], w3 = sw[wb + 64 + sx], w4 = sw[wb + 96 + sx];

        A[0] += w1 * (se * yy0);
        A[1] += w4 * (vxc * y1x + vyc * y1y + vzc * y1z);
        float a = w2 * se;
        A[2] += a * y1x; A[3] += a * y1y; A[4] += a * y1z;
        float b = w3 * yy0;
        A[5] += b * vxc; A[6] += b * vyc; A[7] += b * vzc;

        vxc = vxn; vyc = vyn; vzc = vzn;
    }
    float* q = g_agg + (size_t)cur * 256 + lane * 8;
    red_add_v4(q,     A[0], A[1], A[2], A[3]);
    red_add_v4(q + 4, A[4], A[5], A[6], A[7]);
}

// ---------------------------------------------------------------------------
// Kernel 3: linear_2 + self-connection (8 threads/node)
// ---------------------------------------------------------------------------
#define OUT_SMEM_FLOATS (2048 + 2048 + 8192 + 8192)

__global__ void __launch_bounds__(256)
k_out(const float* __restrict__ node_s,
      const float* __restrict__ node_v,
      const float* __restrict__ attrs,
      const float* __restrict__ W2s,
      const float* __restrict__ W2v,
      const float* __restrict__ Wscs,
      const float* __restrict__ Wscv,
      float* __restrict__ out) {
    extern __shared__ float sm[];
    float* sW2s  = sm;
    float* sW2v  = sW2s + 2048;
    float* sWscs = sW2v + 2048;
    float* sWscv = sWscs + 8192;

    int tid = threadIdx.x;
    for (int i = tid; i < 2048; i += 256) { sW2s[i]  = W2s[i]  * INV_2M;  sW2v[i]  = W2v[i]  * INV_2M; }
    for (int i = tid; i < 8192; i += 256) { sWscs[i] = Wscs[i] * INV_FAN; sWscv[i] = Wscv[i] * INV_FAN; }
    __syncthreads();

    int node = blockIdx.x * 32 + (tid >> 3);
    int part = tid & 7;
    int wo = part * 4;

    unsigned long long accs2[2] = {0ull, 0ull};
    unsigned long long accv2[3][2] = {{0ull, 0ull}, {0ull, 0ull}, {0ull, 0ull}};

    const float4* ag = reinterpret_cast<const float4*>(g_agg + (size_t)node * 256);
#pragma unroll 4
    for (int u = 0; u < 32; u++) {
        float4 Aq = ag[u * 2 + 0];
        float4 Bq = ag[u * 2 + 1];
#pragma unroll
        for (int half = 0; half < 2; half++) {
            int k = half * 32 + u;
            ulonglong2 ws = *(const ulonglong2*)&sW2s[k * 32 + wo];
            ulonglong2 wv = *(const ulonglong2*)&sW2v[k * 32 + wo];
            float as  = half ? Aq.y : Aq.x;
            float avx = half ? Bq.y : Aq.z;
            float avy = half ? Bq.z : Aq.w;
            float avz = half ? Bq.w : Bq.x;
            unsigned long long as2  = pack2(as, as);
            unsigned long long avx2 = pack2(avx, avx);
            unsigned long long avy2 = pack2(avy, avy);
            unsigned long long avz2 = pack2(avz, avz);
            fma2(accs2[0], as2, ws.x);
            fma2(accs2[1], as2, ws.y);
            fma2(accv2[0][0], avx2, wv.x);
            fma2(accv2[0][1], avx2, wv.y);
            fma2(accv2[1][0], avy2, wv.x);
            fma2(accv2[1][1], avy2, wv.y);
            fma2(accv2[2][0], avz2, wv.x);
            fma2(accv2[2][1], avz2, wv.y);
        }
    }

    unsigned long long at2[8];
    const float* arow = attrs + node * 8;
#pragma unroll
    for (int v = 0; v < 8; v++) { float a = arow[v]; at2[v] = pack2(a, a); }

    const float* srow = node_s + node * 32;
    const float* vrow = node_v + node * 96;
#pragma unroll 2
    for (int u = 0; u < 32; u++) {
        float su = srow[u];
        float vx = vrow[u * 3 + 0], vy = vrow[u * 3 + 1], vz = vrow[u * 3 + 2];
        unsigned long long Ts[2] = {0ull, 0ull};
        unsigned long long Tv[2] = {0ull, 0ull};
#pragma unroll
        for (int v = 0; v < 8; v++) {
            ulonglong2 ps = *(const ulonglong2*)&sWscs[(u * 8 + v) * 32 + wo];
            ulonglong2 pv = *(const ulonglong2*)&sWscv[(u * 8 + v) * 32 + wo];
            fma2(Ts[0], at2[v], ps.x);
            fma2(Ts[1], at2[v], ps.y);
            fma2(Tv[0], at2[v], pv.x);
            fma2(Tv[1], at2[v], pv.y);
        }
        unsigned long long su2 = pack2(su, su);
        unsigned long long vx2 = pack2(vx, vx);
        unsigned long long vy2 = pack2(vy, vy);
        unsigned long long vz2 = pack2(vz, vz);
#pragma unroll
        for (int p = 0; p < 2; p++) {
            fma2(accs2[p], su2, Ts[p]);
            fma2(accv2[0][p], vx2, Tv[p]);
            fma2(accv2[1][p], vy2, Tv[p]);
            fma2(accv2[2][p], vz2, Tv[p]);
        }
    }

    float* o = out + (size_t)node * 128;
#pragma unroll
    for (int p = 0; p < 2; p++) {
        float s0, s1;
        unpack2(s0, s1, accs2[p]);
        float v0[3], v1[3];
        unpack2(v0[0], v1[0], accv2[0][p]);
        unpack2(v0[1], v1[1], accv2[1][p]);
        unpack2(v0[2], v1[2], accv2[2][p]);
        int w0 = wo + p * 2;
        o[w0]     = s0;
        o[w0 + 1] = s1;
        o[32 + w0 * 3 + 0] = v0[0];
        o[32 + w0 * 3 + 1] = v0[1];
        o[32 + w0 * 3 + 2] = v0[2];
        o[32 + (w0 + 1) * 3 + 0] = v1[0];
        o[32 + (w0 + 1) * 3 + 1] = v1[1];
        o[32 + (w0 + 1) * 3 + 2] = v1[2];
    }
}

// ---------------------------------------------------------------------------
extern "C" void kernel_launch(void* const* d_in, const int* in_sizes, int n_in,
                              void* d_out, int out_size) {
    const float* node_s     = (const float*)d_in[0];
    const float* node_v     = (const float*)d_in[1];
    const float* node_attrs = (const float*)d_in[2];
    const float* edge_emb   = (const float*)d_in[3];
    const float* edge_y0    = (const float*)d_in[4];
    const float* edge_y1    = (const float*)d_in[5];
    const int*   edge_index = (const int*)d_in[6];
    const float* W1s        = (const float*)d_in[7];
    const float* W1v        = (const float*)d_in[8];
    const float* Wr1        = (const float*)d_in[9];
    const float* Wr2        = (const float*)d_in[10];
    const float* W2s        = (const float*)d_in[11];
    const float* W2v        = (const float*)d_in[12];
    const float* Wscs       = (const float*)d_in[13];
    const float* Wscv       = (const float*)d_in[14];
    float* out = (float*)d_out;

    const int scan_smem = (N_NODES + 32) * sizeof(int);
    cudaFuncSetAttribute(k_scan, cudaFuncAttributeMaxDynamicSharedMemorySize, scan_smem);
    cudaFuncSetAttribute(k_edge, cudaFuncAttributeMaxDynamicSharedMemorySize,
                         EDGE_SMEM_FLOATS * sizeof(float));
    cudaFuncSetAttribute(k_out, cudaFuncAttributeMaxDynamicSharedMemorySize,
                         OUT_SMEM_FLOATS * sizeof(float));

    k_prep<<<1, 512>>>(Wr1, Wr2);
    k_zero<<<5000, 256>>>();
    k_hist<<<2500, 256>>>(edge_index);
    k_scan<<<1, 1024, scan_smem>>>();
    k_scatter<<<2500, 256>>>(edge_index);
    k_lin1<<<(2 * N_NODES + 255) / 256, 256>>>(node_s, node_v, W1s, W1v);
    k_edge<<<N_EDGES / ET, ETHREADS, EDGE_SMEM_FLOATS * sizeof(float)>>>(
        edge_emb, edge_y0, edge_y1, edge_index);
    k_out<<<(N_NODES * 8) / 256, 256, OUT_SMEM_FLOATS * sizeof(float)>>>(
        node_s, node_v, node_attrs, W2s, W2v, Wscs, Wscv, out);
}

// round 14
// speedup vs baseline: 1.2694x; 1.0344x over previous
#include <cuda_runtime.h>
#include <cstdint>

#define N_NODES 20000
#define N_EDGES 640000
#define MUL 32
#define ATTR 8
#define RB 16
#define FH 64

#define INV_M      0.17677669529663687f
#define INV_RB     0.25f
#define INV_FH     0.125f
#define INV_SQRT3  0.5773502691896258f
#define INV_DEG    0.17677669529663687f
#define INV_2M     0.125f
#define INV_FAN    0.0625f
#define LOG2F_     0.6931471805599453f

// Scratch (device globals)
__device__ float g_s[N_NODES * MUL];
__device__ float g_v[N_NODES * MUL * 3];      // SoA: [node][comp(3)][u(32)]
__device__ float g_agg[N_NODES * MUL * 8];
// sort scratch
__device__ int g_cnt[N_NODES];
__device__ int g_off[N_NODES + 1];
__device__ int g_perm[N_EDGES];
__device__ int g_rank[N_EDGES];
// preprocessed weights (packed bf16x2 hi|lo image of Wr2^T, + scaled Wr1)
__device__ unsigned g_pBc[8704];
__device__ float g_Wr1c[1024];

__device__ __forceinline__ float sspf(float x) {
    return fmaxf(x, 0.0f) + log1pf(__expf(-fabsf(x))) - LOG2F_;
}

// no "memory" clobber — g_agg is write-only here and atomic adds commute
__device__ __forceinline__ void red_add_v4(float* addr, float a, float b, float c, float d) {
    asm volatile("red.global.add.v4.f32 [%0], {%1,%2,%3,%4};"
                 :: "l"(addr), "f"(a), "f"(b), "f"(c), "f"(d));
}

// ---- packed f32x2 helpers ----
__device__ __forceinline__ unsigned long long pack2(float x, float y) {
    unsigned long long r;
    asm("mov.b64 %0, {%1,%2};" : "=l"(r) : "f"(x), "f"(y));
    return r;
}
__device__ __forceinline__ void unpack2(float& x, float& y, unsigned long long r) {
    asm("mov.b64 {%0,%1}, %2;" : "=f"(x), "=f"(y) : "l"(r));
}
__device__ __forceinline__ void fma2(unsigned long long& d, unsigned long long a,
                                     unsigned long long b) {
    asm("fma.rn.f32x2 %0, %1, %2, %0;" : "+l"(d) : "l"(a), "l"(b));
}

// ---- bf16 pack helpers ----
__device__ __forceinline__ unsigned bf16x2_of(float x1, float x0) {
    unsigned r;
    asm("cvt.rn.bf16x2.f32 %0, %1, %2;" : "=r"(r) : "f"(x1), "f"(x0));
    return r;
}
__device__ __forceinline__ void bf16_hilo(float x0, float x1, unsigned& hi, unsigned& lo) {
    hi = bf16x2_of(x1, x0);
    float h0 = __uint_as_float(hi << 16);
    float h1 = __uint_as_float(hi & 0xffff0000u);
    lo = bf16x2_of(x1 - h1, x0 - h0);
}

__device__ __forceinline__ void mma16816(float* d, const unsigned* a, const unsigned* b) {
    asm volatile(
        "mma.sync.aligned.m16n8k16.row.col.f32.bf16.bf16.f32 "
        "{%0,%1,%2,%3}, {%4,%5,%6,%7}, {%8,%9}, {%0,%1,%2,%3};"
        : "+f"(d[0]), "+f"(d[1]), "+f"(d[2]), "+f"(d[3])
        : "r"(a[0]), "r"(a[1]), "r"(a[2]), "r"(a[3]), "r"(b[0]), "r"(b[1]));
}

// kk (bf16x2 word index 0..31) -> paired layout index so (kk, kk+4) are adjacent
__device__ __forceinline__ int kp_of(int kk) {
    int ks = kk >> 3, r = kk & 7;
    return ((ks << 2) + (r & 3)) * 2 + (r >> 2);
}

// ---------------------------------------------------------------------------
// One-shot weight preprocessing
// ---------------------------------------------------------------------------
__global__ void k_prep(const float* __restrict__ Wr1,
                       const float* __restrict__ Wr2) {
    int tid = threadIdx.x;                      // 512 threads, 1 block
    for (int i = tid; i < 1024; i += 512) g_Wr1c[i] = Wr1[i] * INV_RB;
    for (int i = tid; i < 4096; i += 512) {
        int n = i & 127, kk = i >> 7;
        float sc = INV_FH * INV_DEG * ((n >= 96) ? INV_SQRT3 : 1.0f);
        float w0 = Wr2[(2 * kk) * 128 + n] * sc;
        float w1 = Wr2[(2 * kk + 1) * 128 + n] * sc;
        unsigned hi, lo;
        bf16_hilo(w0, w1, hi, lo);
        int kp = kp_of(kk);
        g_pBc[n * 34 + kp] = hi;
        g_pBc[4352 + n * 34 + kp] = lo;
    }
}

// ---------------------------------------------------------------------------
__global__ void k_zero_cnt() {
    int i = blockIdx.x * blockDim.x + threadIdx.x;
    if (i < N_NODES) g_cnt[i] = 0;
}

__global__ void k_zero_agg() {
    int i = blockIdx.x * blockDim.x + threadIdx.x;
    float4* p = reinterpret_cast<float4*>(g_agg);
    p[i] = make_float4(0.f, 0.f, 0.f, 0.f);
}

__global__ void k_hist(const int* __restrict__ eidx) {
    int e = blockIdx.x * blockDim.x + threadIdx.x;
    if (e < N_EDGES) {
        int r = atomicAdd(&g_cnt[eidx[N_EDGES + e]], 1);
        g_rank[e] = r;
    }
}

// ---------------------------------------------------------------------------
// k_scan: 3-barrier shuffle scan with coalesced smem staging.
// ---------------------------------------------------------------------------
__global__ void k_scan() {
    extern __shared__ int si[];               // [20000] + warp sums at [20000..20032)
    int* swarp = si + 20000;
    int tid = threadIdx.x;
    int lane = tid & 31;
    int wid = tid >> 5;

    for (int i = tid; i < N_NODES; i += 1024) si[i] = g_cnt[i];
    __syncthreads();

    int base = tid * 20;
    int s = 0;
    if (tid < 1000) {
#pragma unroll
        for (int j = 0; j < 20; j++) s += si[base + j];
    }
    int own = s;

#pragma unroll
    for (int off = 1; off < 32; off <<= 1) {
        int v = __shfl_up_sync(0xffffffffu, s, off);
        if (lane >= off) s += v;
    }
    if (lane == 31) swarp[wid] = s;
    __syncthreads();

    if (wid == 0) {
        int v = swarp[lane];
#pragma unroll
        for (int off = 1; off < 32; off <<= 1) {
            int u = __shfl_up_sync(0xffffffffu, v, off);
            if (lane >= off) v += u;
        }
        swarp[lane] = v;
    }
    __syncthreads();

    int warp_excl = (wid == 0) ? 0 : swarp[wid - 1];
    int excl = warp_excl + (s - own);

    if (tid < 1000) {
        int running = excl;
#pragma unroll
        for (int j = 0; j < 20; j++) {
            int c = si[base + j];
            si[base + j] = running;
            running += c;
        }
    }
    __syncthreads();

    for (int i = tid; i < N_NODES; i += 1024) g_off[i] = si[i];
    if (tid == 0) g_off[N_NODES] = swarp[31];
}

// atomic-free scatter using precomputed ranks
__global__ void k_scatter(const int* __restrict__ eidx) {
    int e = blockIdx.x * blockDim.x + threadIdx.x;
    if (e < N_EDGES) {
        int dst = eidx[N_EDGES + e];
        g_perm[g_off[dst] + g_rank[e]] = e;
    }
}

// ---------------------------------------------------------------------------
// Kernel 1: linear_1 (writes g_v in SoA [node][comp][32])
// ---------------------------------------------------------------------------
__global__ void k_lin1(const float* __restrict__ node_s,
                       const float* __restrict__ node_v,
                       const float* __restrict__ W1s,
                       const float* __restrict__ W1v) {
    __shared__ float sW1s[1024];
    __shared__ float sW1v[1024];
    int tid = threadIdx.x;
    for (int i = tid; i < 1024; i += 256) {
        sW1s[i] = W1s[i] * INV_M;
        sW1v[i] = W1v[i] * INV_M;
    }
    __syncthreads();

    int gt = blockIdx.x * 256 + tid;
    int node = gt >> 1;
    int h = gt & 1;
    if (node >= N_NODES) return;

    float accs[16];
    float accv[16][3];
#pragma unroll
    for (int w = 0; w < 16; w++) { accs[w] = 0.f; accv[w][0] = accv[w][1] = accv[w][2] = 0.f; }

    const float* srow = node_s + node * 32;
    const float* vrow = node_v + node * 96;
    for (int u = 0; u < 32; u++) {
        float su = srow[u];
        float vx = vrow[u * 3 + 0], vy = vrow[u * 3 + 1], vz = vrow[u * 3 + 2];
        const float* ws = &sW1s[u * 32 + h * 16];
        const float* wv = &sW1v[u * 32 + h * 16];
#pragma unroll
        for (int w = 0; w < 16; w++) {
            accs[w]    += su * ws[w];
            accv[w][0] += vx * wv[w];
            accv[w][1] += vy * wv[w];
            accv[w][2] += vz * wv[w];
        }
    }
    float* so = g_s + node * 32 + h * 16;
    float* vo = g_v + node * 96 + h * 16;
#pragma unroll
    for (int w = 0; w < 16; w++) {
        so[w] = accs[w];
        vo[w]      = accv[w][0];
        vo[32 + w] = accv[w][1];
        vo[64 + w] = accv[w][2];
    }
}

// ---------------------------------------------------------------------------
// Kernel 2: fused edge kernel (unchanged from R13)
// ---------------------------------------------------------------------------
#define ET 128
#define ETHREADS 512
#define PHA_HI 0
#define PHA_LO 4352
#define PB_HI  8704
#define PB_LO  13056
#define WR1_OFF 17408
#define EMB_OFF 18432
#define META_OFF 20608
#define EDGE_SMEM_FLOATS 21504

__global__ void __launch_bounds__(ETHREADS, 2)
k_edge(const float* __restrict__ emb,
       const float* __restrict__ y0,
       const float* __restrict__ y1,
       const int*   __restrict__ eidx) {
    extern __shared__ float sm[];
    unsigned* su   = reinterpret_cast<unsigned*>(sm);
    float* sw   = sm;
    float* sWr1 = sm + WR1_OFF;
    float* semb = sm + EMB_OFF;
    int*   sperm = (int*)(sm + META_OFF);
    int*   ssrc  = sperm + 128;
    int*   sdst  = ssrc + 128;
    float* sy0   = (float*)(sdst + 128);
    float* sy1   = sy0 + 128;

    int tid = threadIdx.x;
    int p0 = blockIdx.x * ET;

    if (tid < 128) sperm[tid] = g_perm[p0 + tid];
    {
        const uint4* s4 = reinterpret_cast<const uint4*>(g_pBc);
        uint4* d4 = reinterpret_cast<uint4*>(su + PB_HI);
        for (int i = tid; i < 2176; i += ETHREADS) d4[i] = s4[i];
        const float4* w4 = reinterpret_cast<const float4*>(g_Wr1c);
        float4* dw = reinterpret_cast<float4*>(sWr1);
        for (int i = tid; i < 256; i += ETHREADS) dw[i] = w4[i];
    }
    __syncthreads();

    if (tid < 128) {
        int e = sperm[tid];
        ssrc[tid] = eidx[e];
        sdst[tid] = eidx[N_EDGES + e];
        sy0[tid] = y0[e];
    }
    for (int i = tid; i < 384; i += ETHREADS) {
        int pos = i / 3, comp = i - pos * 3;
        sy1[i] = y1[sperm[pos] * 3 + comp];
    }
    for (int i = tid; i < ET * RB; i += ETHREADS) {
        int pos = i >> 4, k = i & 15;
        semb[pos * 17 + k] = emb[sperm[pos] * 16 + k];
    }
    __syncthreads();

    int lane = tid & 31;
    int th = tid >> 5;
    int cg = th >> 1;
    int eh = th & 1;

    float acc1[2][8];
#pragma unroll
    for (int j = 0; j < 2; j++)
#pragma unroll
        for (int m = 0; m < 8; m++) acc1[j][m] = 0.f;

    for (int k = 0; k < 16; k++) {
        float em[2];
#pragma unroll
        for (int j = 0; j < 2; j++) em[j] = semb[(lane + 32 * (eh * 2 + j)) * 17 + k];
        float wr[8];
#pragma unroll
        for (int m = 0; m < 8; m++) wr[m] = sWr1[k * 64 + cg * 8 + m];
#pragma unroll
        for (int j = 0; j < 2; j++)
#pragma unroll
            for (int m = 0; m < 8; m++) acc1[j][m] += em[j] * wr[m];
    }
#pragma unroll
    for (int j = 0; j < 2; j++) {
        int edge = lane + 32 * (eh * 2 + j);
#pragma unroll
        for (int m = 0; m < 8; m += 2) {
            float x0 = sspf(acc1[j][m]);
            float x1 = sspf(acc1[j][m + 1]);
            unsigned hi, lo;
            bf16_hilo(x0, x1, hi, lo);
            int kp = kp_of(cg * 4 + (m >> 1));
            su[PHA_HI + edge * 34 + kp] = hi;
            su[PHA_LO + edge * 34 + kp] = lo;
        }
    }
    __syncthreads();

    int g = lane >> 2;
    int t = lane & 3;
    int mt = th >> 1;
    int nh = th & 1;
    float d[8][4];
#pragma unroll
    for (int ntl = 0; ntl < 8; ntl++)
#pragma unroll
        for (int c = 0; c < 4; c++) d[ntl][c] = 0.f;

    {
        int r0 = mt * 16 + g;
        int r1 = r0 + 8;
#pragma unroll
        for (int ks = 0; ks < 4; ks++) {
            int kb = (ks * 4 + t) * 2;
            uint2 a0h = *(const uint2*)&su[PHA_HI + r0 * 34 + kb];
            uint2 a1h = *(const uint2*)&su[PHA_HI + r1 * 34 + kb];
            uint2 a0l = *(const uint2*)&su[PHA_LO + r0 * 34 + kb];
            uint2 a1l = *(const uint2*)&su[PHA_LO + r1 * 34 + kb];
            unsigned ahi[4] = {a0h.x, a1h.x, a0h.y, a1h.y};
            unsigned alo[4] = {a0l.x, a1l.x, a0l.y, a1l.y};
#pragma unroll
            for (int ntl = 0; ntl < 8; ntl++) {
                int n = (nh * 8 + ntl) * 8 + g;
                uint2 bh = *(const uint2*)&su[PB_HI + n * 34 + kb];
                uint2 bl = *(const uint2*)&su[PB_LO + n * 34 + kb];
                unsigned bhi[2] = {bh.x, bh.y};
                unsigned blo[2] = {bl.x, bl.y};
                mma16816(d[ntl], ahi, bhi);
                mma16816(d[ntl], alo, bhi);
                mma16816(d[ntl], ahi, blo);
            }
        }
    }
    __syncthreads();

    {
        int e0 = mt * 16 + g;
        int e1 = e0 + 8;
        int sw0 = (e0 & 7) << 2;
        int sw1 = (e1 & 7) << 2;
#pragma unroll
        for (int ntl = 0; ntl < 8; ntl++) {
            int c = (nh * 8 + ntl) * 8 + 2 * t;
            int b = c & ~31;
            int cc = c & 31;
            *(float2*)&sw[e0 * 128 + b + (cc ^ sw0)] = make_float2(d[ntl][0], d[ntl][1]);
            *(float2*)&sw[e1 * 128 + b + (cc ^ sw1)] = make_float2(d[ntl][2], d[ntl][3]);
        }
    }
    __syncthreads();

    int base = th * 8;

    float se_r[8];
#pragma unroll
    for (int j = 0; j < 8; j++) se_r[j] = g_s[ssrc[base + j] * 32 + lane];

    const float* vp0 = g_v + ssrc[base] * 96 + lane;
    float vxc = vp0[0], vyc = vp0[32], vzc = vp0[64];

    float A[8];
#pragma unroll
    for (int q = 0; q < 8; q++) A[q] = 0.f;

    int cur = sdst[base];
#pragma unroll
    for (int j = 0; j < 8; j++) {
        int pos = base + j;
        float vxn = 0.f, vyn = 0.f, vzn = 0.f;
        if (j < 7) {
            const float* vpn = g_v + ssrc[pos + 1] * 96 + lane;
            vxn = vpn[0]; vyn = vpn[32]; vzn = vpn[64];
        }
        int dd = sdst[pos];
        if (dd != cur) {
            float* q = g_agg + (size_t)cur * 256 + lane * 8;
            red_add_v4(q,     A[0], A[1], A[2], A[3]);
            red_add_v4(q + 4, A[4], A[5], A[6], A[7]);
#pragma unroll
            for (int qq = 0; qq < 8; qq++) A[qq] = 0.f;
            cur = dd;
        }
        float yy0 = sy0[pos];
        float y1x = sy1[pos * 3 + 0], y1y = sy1[pos * 3 + 1], y1z = sy1[pos * 3 + 2];
        float se = se_r[j];
        int sx = lane ^ ((pos & 7) << 2);
        int wb = pos * 128;
        float w1 = sw[wb + sx], w2 = sw[wb + 32 + sx], w3 = sw[wb + 64 + sx], w4 = sw[wb + 96 + sx];

        A[0] += w1 * (se * yy0);
        A[1] += w4 * (vxc * y1x + vyc * y1y + vzc * y1z);
        float a = w2 * se;
        A[2] += a * y1x; A[3] += a * y1y; A[4] += a * y1z;
        float b = w3 * yy0;
        A[5] += b * vxc; A[6] += b * vyc; A[7] += b * vzc;

        vxc = vxn; vyc = vyn; vzc = vzn;
    }
    float* q = g_agg + (size_t)cur * 256 + lane * 8;
    red_add_v4(q,     A[0], A[1], A[2], A[3]);
    red_add_v4(q + 4, A[4], A[5], A[6], A[7]);
}

// ---------------------------------------------------------------------------
// Kernel 3: linear_2 + self-connection (unchanged from R13)
// ---------------------------------------------------------------------------
#define OUT_SMEM_FLOATS (2048 + 2048 + 8192 + 8192)

__global__ void __launch_bounds__(256)
k_out(const float* __restrict__ node_s,
      const float* __restrict__ node_v,
      const float* __restrict__ attrs,
      const float* __restrict__ W2s,
      const float* __restrict__ W2v,
      const float* __restrict__ Wscs,
      const float* __restrict__ Wscv,
      float* __restrict__ out) {
    extern __shared__ float sm[];
    float* sW2s  = sm;
    float* sW2v  = sW2s + 2048;
    float* sWscs = sW2v + 2048;
    float* sWscv = sWscs + 8192;

    int tid = threadIdx.x;
    for (int i = tid; i < 2048; i += 256) { sW2s[i]  = W2s[i]  * INV_2M;  sW2v[i]  = W2v[i]  * INV_2M; }
    for (int i = tid; i < 8192; i += 256) { sWscs[i] = Wscs[i] * INV_FAN; sWscv[i] = Wscv[i] * INV_FAN; }
    __syncthreads();

    int node = blockIdx.x * 32 + (tid >> 3);
    int part = tid & 7;
    int wo = part * 4;

    unsigned long long accs2[2] = {0ull, 0ull};
    unsigned long long accv2[3][2] = {{0ull, 0ull}, {0ull, 0ull}, {0ull, 0ull}};

    const float4* ag = reinterpret_cast<const float4*>(g_agg + (size_t)node * 256);
#pragma unroll 4
    for (int u = 0; u < 32; u++) {
        float4 Aq = ag[u * 2 + 0];
        float4 Bq = ag[u * 2 + 1];
#pragma unroll
        for (int half = 0; half < 2; half++) {
            int k = half * 32 + u;
            ulonglong2 ws = *(const ulonglong2*)&sW2s[k * 32 + wo];
            ulonglong2 wv = *(const ulonglong2*)&sW2v[k * 32 + wo];
            float as  = half ? Aq.y : Aq.x;
            float avx = half ? Bq.y : Aq.z;
            float avy = half ? Bq.z : Aq.w;
            float avz = half ? Bq.w : Bq.x;
            unsigned long long as2  = pack2(as, as);
            unsigned long long avx2 = pack2(avx, avx);
            unsigned long long avy2 = pack2(avy, avy);
            unsigned long long avz2 = pack2(avz, avz);
            fma2(accs2[0], as2, ws.x);
            fma2(accs2[1], as2, ws.y);
            fma2(accv2[0][0], avx2, wv.x);
            fma2(accv2[0][1], avx2, wv.y);
            fma2(accv2[1][0], avy2, wv.x);
            fma2(accv2[1][1], avy2, wv.y);
            fma2(accv2[2][0], avz2, wv.x);
            fma2(accv2[2][1], avz2, wv.y);
        }
    }

    unsigned long long at2[8];
    const float* arow = attrs + node * 8;
#pragma unroll
    for (int v = 0; v < 8; v++) { float a = arow[v]; at2[v] = pack2(a, a); }

    const float* srow = node_s + node * 32;
    const float* vrow = node_v + node * 96;
#pragma unroll 2
    for (int u = 0; u < 32; u++) {
        float su = srow[u];
        float vx = vrow[u * 3 + 0], vy = vrow[u * 3 + 1], vz = vrow[u * 3 + 2];
        unsigned long long Ts[2] = {0ull, 0ull};
        unsigned long long Tv[2] = {0ull, 0ull};
#pragma unroll
        for (int v = 0; v < 8; v++) {
            ulonglong2 ps = *(const ulonglong2*)&sWscs[(u * 8 + v) * 32 + wo];
            ulonglong2 pv = *(const ulonglong2*)&sWscv[(u * 8 + v) * 32 + wo];
            fma2(Ts[0], at2[v], ps.x);
            fma2(Ts[1], at2[v], ps.y);
            fma2(Tv[0], at2[v], pv.x);
            fma2(Tv[1], at2[v], pv.y);
        }
        unsigned long long su2 = pack2(su, su);
        unsigned long long vx2 = pack2(vx, vx);
        unsigned long long vy2 = pack2(vy, vy);
        unsigned long long vz2 = pack2(vz, vz);
#pragma unroll
        for (int p = 0; p < 2; p++) {
            fma2(accs2[p], su2, Ts[p]);
            fma2(accv2[0][p], vx2, Tv[p]);
            fma2(accv2[1][p], vy2, Tv[p]);
            fma2(accv2[2][p], vz2, Tv[p]);
        }
    }

    float* o = out + (size_t)node * 128;
#pragma unroll
    for (int p = 0; p < 2; p++) {
        float s0, s1;
        unpack2(s0, s1, accs2[p]);
        float v0[3], v1[3];
        unpack2(v0[0], v1[0], accv2[0][p]);
        unpack2(v0[1], v1[1], accv2[1][p]);
        unpack2(v0[2], v1[2], accv2[2][p]);
        int w0 = wo + p * 2;
        o[w0]     = s0;
        o[w0 + 1] = s1;
        o[32 + w0 * 3 + 0] = v0[0];
        o[32 + w0 * 3 + 1] = v0[1];
        o[32 + w0 * 3 + 2] = v0[2];
        o[32 + (w0 + 1) * 3 + 0] = v1[0];
        o[32 + (w0 + 1) * 3 + 1] = v1[1];
        o[32 + (w0 + 1) * 3 + 2] = v1[2];
    }
}

// ---------------------------------------------------------------------------
extern "C" void kernel_launch(void* const* d_in, const int* in_sizes, int n_in,
                              void* d_out, int out_size) {
    const float* node_s     = (const float*)d_in[0];
    const float* node_v     = (const float*)d_in[1];
    const float* node_attrs = (const float*)d_in[2];
    const float* edge_emb   = (const float*)d_in[3];
    const float* edge_y0    = (const float*)d_in[4];
    const float* edge_y1    = (const float*)d_in[5];
    const int*   edge_index = (const int*)d_in[6];
    const float* W1s        = (const float*)d_in[7];
    const float* W1v        = (const float*)d_in[8];
    const float* Wr1        = (const float*)d_in[9];
    const float* Wr2        = (const float*)d_in[10];
    const float* W2s        = (const float*)d_in[11];
    const float* W2v        = (const float*)d_in[12];
    const float* Wscs       = (const float*)d_in[13];
    const float* Wscv       = (const float*)d_in[14];
    float* out = (float*)d_out;

    // one-time host-side resources (no device memory involved)
    static cudaStream_t s_side = nullptr;
    static cudaEvent_t ev_fork = nullptr, ev_join = nullptr;
    if (s_side == nullptr) {
        cudaStreamCreateWithFlags(&s_side, cudaStreamNonBlocking);
        cudaEventCreateWithFlags(&ev_fork, cudaEventDisableTiming);
        cudaEventCreateWithFlags(&ev_join, cudaEventDisableTiming);

        const int scan_smem = (N_NODES + 32) * sizeof(int);
        cudaFuncSetAttribute(k_scan, cudaFuncAttributeMaxDynamicSharedMemorySize, scan_smem);
        cudaFuncSetAttribute(k_edge, cudaFuncAttributeMaxDynamicSharedMemorySize,
                             EDGE_SMEM_FLOATS * sizeof(float));
        cudaFuncSetAttribute(k_out, cudaFuncAttributeMaxDynamicSharedMemorySize,
                             OUT_SMEM_FLOATS * sizeof(float));
    }
    const int scan_smem = (N_NODES + 32) * sizeof(int);

    // fork: sort chain on side stream
    cudaEventRecord(ev_fork, 0);
    cudaStreamWaitEvent(s_side, ev_fork, 0);
    k_zero_cnt<<<(N_NODES + 255) / 256, 256, 0, s_side>>>();
    k_hist<<<2500, 256, 0, s_side>>>(edge_index);
    k_scan<<<1, 1024, scan_smem, s_side>>>();
    k_scatter<<<2500, 256, 0, s_side>>>(edge_index);
    cudaEventRecord(ev_join, s_side);

    // main stream: feature chain (independent of sort)
    k_prep<<<1, 512>>>(Wr1, Wr2);
    k_zero_agg<<<5000, 256>>>();
    k_lin1<<<(2 * N_NODES + 255) / 256, 256>>>(node_s, node_v, W1s, W1v);

    // join, then edge + out
    cudaStreamWaitEvent(0, ev_join, 0);
    k_edge<<<N_EDGES / ET, ETHREADS, EDGE_SMEM_FLOATS * sizeof(float)>>>(
        edge_emb, edge_y0, edge_y1, edge_index);
    k_out<<<(N_NODES * 8) / 256, 256, OUT_SMEM_FLOATS * sizeof(float)>>>(
        node_s, node_v, node_attrs, W2s, W2v, Wscs, Wscv, out);
}

// round 16
// speedup vs baseline: 1.3045x; 1.0276x over previous
#include <cuda_runtime.h>
#include <cstdint>

#define N_NODES 20000
#define N_EDGES 640000
#define MUL 32
#define ATTR 8
#define RB 16
#define FH 64

#define INV_M      0.17677669529663687f
#define INV_RB     0.25f
#define INV_FH     0.125f
#define INV_SQRT3  0.5773502691896258f
#define INV_DEG    0.17677669529663687f
#define INV_2M     0.125f
#define INV_FAN    0.0625f
#define LOG2F_     0.6931471805599453f

// Scratch (device globals)
__device__ float g_s[N_NODES * MUL];
__device__ float g_v[N_NODES * MUL * 3];      // SoA: [node][comp(3)][u(32)]
__device__ float g_agg[N_NODES * MUL * 8];
// sort scratch
__device__ int g_cnt[N_NODES];
__device__ int g_off[N_NODES + 1];
__device__ int g_perm[N_EDGES];
__device__ int g_rank[N_EDGES];
// packed sorted-edge records: {src, dst, y0, y1x, y1y, y1z, pad, pad}
__device__ float g_epack[(size_t)N_EDGES * 8];
// preprocessed weights (packed bf16x2 hi|lo image of Wr2^T, + scaled Wr1)
__device__ unsigned g_pBc[8704];
__device__ float g_Wr1c[1024];

__device__ __forceinline__ float sspf(float x) {
    return fmaxf(x, 0.0f) + log1pf(__expf(-fabsf(x))) - LOG2F_;
}

// no "memory" clobber — g_agg is write-only here and atomic adds commute
__device__ __forceinline__ void red_add_v4(float* addr, float a, float b, float c, float d) {
    asm volatile("red.global.add.v4.f32 [%0], {%1,%2,%3,%4};"
                 :: "l"(addr), "f"(a), "f"(b), "f"(c), "f"(d));
}

// ---- packed f32x2 helpers ----
__device__ __forceinline__ unsigned long long pack2(float x, float y) {
    unsigned long long r;
    asm("mov.b64 %0, {%1,%2};" : "=l"(r) : "f"(x), "f"(y));
    return r;
}
__device__ __forceinline__ void unpack2(float& x, float& y, unsigned long long r) {
    asm("mov.b64 {%0,%1}, %2;" : "=f"(x), "=f"(y) : "l"(r));
}
__device__ __forceinline__ void fma2(unsigned long long& d, unsigned long long a,
                                     unsigned long long b) {
    asm("fma.rn.f32x2 %0, %1, %2, %0;" : "+l"(d) : "l"(a), "l"(b));
}

// ---- bf16 pack helpers ----
__device__ __forceinline__ unsigned bf16x2_of(float x1, float x0) {
    unsigned r;
    asm("cvt.rn.bf16x2.f32 %0, %1, %2;" : "=r"(r) : "f"(x1), "f"(x0));
    return r;
}
__device__ __forceinline__ void bf16_hilo(float x0, float x1, unsigned& hi, unsigned& lo) {
    hi = bf16x2_of(x1, x0);
    float h0 = __uint_as_float(hi << 16);
    float h1 = __uint_as_float(hi & 0xffff0000u);
    lo = bf16x2_of(x1 - h1, x0 - h0);
}

__device__ __forceinline__ void mma16816(float* d, const unsigned* a, const unsigned* b) {
    asm volatile(
        "mma.sync.aligned.m16n8k16.row.col.f32.bf16.bf16.f32 "
        "{%0,%1,%2,%3}, {%4,%5,%6,%7}, {%8,%9}, {%0,%1,%2,%3};"
        : "+f"(d[0]), "+f"(d[1]), "+f"(d[2]), "+f"(d[3])
        : "r"(a[0]), "r"(a[1]), "r"(a[2]), "r"(a[3]), "r"(b[0]), "r"(b[1]));
}

// kk (bf16x2 word index 0..31) -> paired layout index so (kk, kk+4) are adjacent
__device__ __forceinline__ int kp_of(int kk) {
    int ks = kk >> 3, r = kk & 7;
    return ((ks << 2) + (r & 3)) * 2 + (r >> 2);
}

// ---------------------------------------------------------------------------
// One-shot weight preprocessing
// ---------------------------------------------------------------------------
__global__ void k_prep(const float* __restrict__ Wr1,
                       const float* __restrict__ Wr2) {
    int tid = threadIdx.x;                      // 512 threads, 1 block
    for (int i = tid; i < 1024; i += 512) g_Wr1c[i] = Wr1[i] * INV_RB;
    for (int i = tid; i < 4096; i += 512) {
        int n = i & 127, kk = i >> 7;
        float sc = INV_FH * INV_DEG * ((n >= 96) ? INV_SQRT3 : 1.0f);
        float w0 = Wr2[(2 * kk) * 128 + n] * sc;
        float w1 = Wr2[(2 * kk + 1) * 128 + n] * sc;
        unsigned hi, lo;
        bf16_hilo(w0, w1, hi, lo);
        int kp = kp_of(kk);
        g_pBc[n * 34 + kp] = hi;
        g_pBc[4352 + n * 34 + kp] = lo;
    }
}

// ---------------------------------------------------------------------------
__global__ void k_zero_cnt() {
    int i = blockIdx.x * blockDim.x + threadIdx.x;
    if (i < N_NODES) g_cnt[i] = 0;
}

__global__ void k_zero_agg() {
    int i = blockIdx.x * blockDim.x + threadIdx.x;
    float4* p = reinterpret_cast<float4*>(g_agg);
    p[i] = make_float4(0.f, 0.f, 0.f, 0.f);
}

__global__ void k_hist(const int* __restrict__ eidx) {
    int e = blockIdx.x * blockDim.x + threadIdx.x;
    if (e < N_EDGES) {
        int r = atomicAdd(&g_cnt[eidx[N_EDGES + e]], 1);
        g_rank[e] = r;
    }
}

// ---------------------------------------------------------------------------
// k_scan: 3-barrier shuffle scan with coalesced smem staging.
// ---------------------------------------------------------------------------
__global__ void k_scan() {
    extern __shared__ int si[];
    int* swarp = si + 20000;
    int tid = threadIdx.x;
    int lane = tid & 31;
    int wid = tid >> 5;

    for (int i = tid; i < N_NODES; i += 1024) si[i] = g_cnt[i];
    __syncthreads();

    int base = tid * 20;
    int s = 0;
    if (tid < 1000) {
#pragma unroll
        for (int j = 0; j < 20; j++) s += si[base + j];
    }
    int own = s;

#pragma unroll
    for (int off = 1; off < 32; off <<= 1) {
        int v = __shfl_up_sync(0xffffffffu, s, off);
        if (lane >= off) s += v;
    }
    if (lane == 31) swarp[wid] = s;
    __syncthreads();

    if (wid == 0) {
        int v = swarp[lane];
#pragma unroll
        for (int off = 1; off < 32; off <<= 1) {
            int u = __shfl_up_sync(0xffffffffu, v, off);
            if (lane >= off) v += u;
        }
        swarp[lane] = v;
    }
    __syncthreads();

    int warp_excl = (wid == 0) ? 0 : swarp[wid - 1];
    int excl = warp_excl + (s - own);

    if (tid < 1000) {
        int running = excl;
#pragma unroll
        for (int j = 0; j < 20; j++) {
            int c = si[base + j];
            si[base + j] = running;
            running += c;
        }
    }
    __syncthreads();

    for (int i = tid; i < N_NODES; i += 1024) g_off[i] = si[i];
    if (tid == 0) g_off[N_NODES] = swarp[31];
}

// atomic-free scatter: perm + packed 32B sorted-edge record
__global__ void k_scatter(const int* __restrict__ eidx,
                          const float* __restrict__ y0,
                          const float* __restrict__ y1) {
    int e = blockIdx.x * blockDim.x + threadIdx.x;
    if (e < N_EDGES) {
        int dst = eidx[N_EDGES + e];
        int pos = g_off[dst] + g_rank[e];
        g_perm[pos] = e;
        float4 a = make_float4(__int_as_float(eidx[e]), __int_as_float(dst),
                               y0[e], y1[3 * e + 0]);
        float4 b = make_float4(y1[3 * e + 1], y1[3 * e + 2], 0.f, 0.f);
        float4* gp = reinterpret_cast<float4*>(g_epack + (size_t)pos * 8);
        gp[0] = a;
        gp[1] = b;
    }
}

// ---------------------------------------------------------------------------
// Kernel 1: linear_1 (writes g_v in SoA [node][comp][32])
// ---------------------------------------------------------------------------
__global__ void k_lin1(const float* __restrict__ node_s,
                       const float* __restrict__ node_v,
                       const float* __restrict__ W1s,
                       const float* __restrict__ W1v) {
    __shared__ float sW1s[1024];
    __shared__ float sW1v[1024];
    int tid = threadIdx.x;
    for (int i = tid; i < 1024; i += 256) {
        sW1s[i] = W1s[i] * INV_M;
        sW1v[i] = W1v[i] * INV_M;
    }
    __syncthreads();

    int gt = blockIdx.x * 256 + tid;
    int node = gt >> 1;
    int h = gt & 1;
    if (node >= N_NODES) return;

    float accs[16];
    float accv[16][3];
#pragma unroll
    for (int w = 0; w < 16; w++) { accs[w] = 0.f; accv[w][0] = accv[w][1] = accv[w][2] = 0.f; }

    const float* srow = node_s + node * 32;
    const float* vrow = node_v + node * 96;
    for (int u = 0; u < 32; u++) {
        float su = srow[u];
        float vx = vrow[u * 3 + 0], vy = vrow[u * 3 + 1], vz = vrow[u * 3 + 2];
        const float* ws = &sW1s[u * 32 + h * 16];
        const float* wv = &sW1v[u * 32 + h * 16];
#pragma unroll
        for (int w = 0; w < 16; w++) {
            accs[w]    += su * ws[w];
            accv[w][0] += vx * wv[w];
            accv[w][1] += vy * wv[w];
            accv[w][2] += vz * wv[w];
        }
    }
    float* so = g_s + node * 32 + h * 16;
    float* vo = g_v + node * 96 + h * 16;
#pragma unroll
    for (int w = 0; w < 16; w++) {
        so[w] = accs[w];
        vo[w]      = accv[w][0];
        vo[32 + w] = accv[w][1];
        vo[64 + w] = accv[w][2];
    }
}

// ---------------------------------------------------------------------------
// Kernel 2: fused edge kernel (R14 structure: ONE 128-edge tile per block),
// 512 threads; metadata read as coalesced packed records.
// ---------------------------------------------------------------------------
#define ET 128
#define ETHREADS 512
#define PHA_HI 0
#define PHA_LO 4352
#define PB_HI  8704
#define PB_LO  13056
#define WR1_OFF 17408
#define EMB_OFF 18432
#define PERM_OFF 20608
#define SEDGE_OFF 20736
#define EDGE_SMEM_FLOATS 21760

__global__ void __launch_bounds__(ETHREADS, 2)
k_edge(const float* __restrict__ emb) {
    extern __shared__ float sm[];
    unsigned* su   = reinterpret_cast<unsigned*>(sm);
    float* sw    = sm;                    // overlay after MMA (PHA/PB dead)
    float* sWr1  = sm + WR1_OFF;
    float* semb  = sm + EMB_OFF;
    int*   sperm = (int*)(sm + PERM_OFF);
    float* sedge = sm + SEDGE_OFF;        // [128][8] packed records

    int tid = threadIdx.x;
    int p0 = blockIdx.x * ET;

    if (tid < 128) sperm[tid] = g_perm[p0 + tid];
    // weight staging: straight vectorized copies of preprocessed images
    {
        const uint4* s4 = reinterpret_cast<const uint4*>(g_pBc);
        uint4* d4 = reinterpret_cast<uint4*>(su + PB_HI);
        for (int i = tid; i < 2176; i += ETHREADS) d4[i] = s4[i];
        const float4* w4 = reinterpret_cast<const float4*>(g_Wr1c);
        float4* dw = reinterpret_cast<float4*>(sWr1);
        for (int i = tid; i < 256; i += ETHREADS) dw[i] = w4[i];
    }
    // metadata: one coalesced float4 copy
    {
        const float4* s4 = reinterpret_cast<const float4*>(g_epack + (size_t)p0 * 8);
        float4* d4 = reinterpret_cast<float4*>(sedge);
        for (int i = tid; i < 256; i += ETHREADS) d4[i] = s4[i];
    }
    __syncthreads();

    for (int i = tid; i < ET * RB; i += ETHREADS) {
        int pos = i >> 4, k = i & 15;
        semb[pos * 17 + k] = emb[sperm[pos] * 16 + k];
    }
    __syncthreads();

    int lane = tid & 31;
    int th = tid >> 5;          // 0..15
    int cg = th >> 1;           // GEMM1 col group
    int eh = th & 1;            // GEMM1 edge half

    // ---- GEMM1 (fp32): 2 edges x 8 cols per thread ----
    float acc1[2][8];
#pragma unroll
    for (int j = 0; j < 2; j++)
#pragma unroll
        for (int m = 0; m < 8; m++) acc1[j][m] = 0.f;

    for (int k = 0; k < 16; k++) {
        float em[2];
#pragma unroll
        for (int j = 0; j < 2; j++) em[j] = semb[(lane + 32 * (eh * 2 + j)) * 17 + k];
        float wr[8];
#pragma unroll
        for (int m = 0; m < 8; m++) wr[m] = sWr1[k * 64 + cg * 8 + m];
#pragma unroll
        for (int j = 0; j < 2; j++)
#pragma unroll
            for (int m = 0; m < 8; m++) acc1[j][m] += em[j] * wr[m];
    }
#pragma unroll
    for (int j = 0; j < 2; j++) {
        int edge = lane + 32 * (eh * 2 + j);
#pragma unroll
        for (int m = 0; m < 8; m += 2) {
            float x0 = sspf(acc1[j][m]);
            float x1 = sspf(acc1[j][m + 1]);
            unsigned hi, lo;
            bf16_hilo(x0, x1, hi, lo);
            int kp = kp_of(cg * 4 + (m >> 1));
            su[PHA_HI + edge * 34 + kp] = hi;
            su[PHA_LO + edge * 34 + kp] = lo;
        }
    }
    __syncthreads();

    // ---- GEMM2 via mma.sync: warp pair (mt, nh); LDS.64 fragment loads ----
    int g = lane >> 2;
    int t4 = lane & 3;
    int mt = th >> 1;
    int nh = th & 1;
    float d[8][4];
#pragma unroll
    for (int ntl = 0; ntl < 8; ntl++)
#pragma unroll
        for (int c = 0; c < 4; c++) d[ntl][c] = 0.f;

    {
        int r0 = mt * 16 + g;
        int r1 = r0 + 8;
#pragma unroll
        for (int ks = 0; ks < 4; ks++) {
            int kb = (ks * 4 + t4) * 2;
            uint2 a0h = *(const uint2*)&su[PHA_HI + r0 * 34 + kb];
            uint2 a1h = *(const uint2*)&su[PHA_HI + r1 * 34 + kb];
            uint2 a0l = *(const uint2*)&su[PHA_LO + r0 * 34 + kb];
            uint2 a1l = *(const uint2*)&su[PHA_LO + r1 * 34 + kb];
            unsigned ahi[4] = {a0h.x, a1h.x, a0h.y, a1h.y};
            unsigned alo[4] = {a0l.x, a1l.x, a0l.y, a1l.y};
#pragma unroll
            for (int ntl = 0; ntl < 8; ntl++) {
                int n = (nh * 8 + ntl) * 8 + g;
                uint2 bh = *(const uint2*)&su[PB_HI + n * 34 + kb];
                uint2 bl = *(const uint2*)&su[PB_LO + n * 34 + kb];
                unsigned bhi[2] = {bh.x, bh.y};
                unsigned blo[2] = {bl.x, bl.y};
                mma16816(d[ntl], ahi, bhi);
                mma16816(d[ntl], alo, bhi);
                mma16816(d[ntl], ahi, blo);
            }
        }
    }
    __syncthreads();   // phA/pB dead; safe to overlay sw

    // ---- store D -> sw[edge][col] with xor swizzle ----
    {
        int e0 = mt * 16 + g;
        int e1 = e0 + 8;
        int sw0 = (e0 & 7) << 2;
        int sw1 = (e1 & 7) << 2;
#pragma unroll
        for (int ntl = 0; ntl < 8; ntl++) {
            int c = (nh * 8 + ntl) * 8 + 2 * t4;
            int b = c & ~31;
            int cc = c & 31;
            *(float2*)&sw[e0 * 128 + b + (cc ^ sw0)] = make_float2(d[ntl][0], d[ntl][1]);
            *(float2*)&sw[e1 * 128 + b + (cc ^ sw1)] = make_float2(d[ntl][2], d[ntl][3]);
        }
    }
    __syncthreads();   // TP warp reads rows produced by its warp pair

    // ---- warp-cooperative TP: warp th owns edges [th*8, th*8+8), lane = u ----
    int base = th * 8;

    float se_r[8];
#pragma unroll
    for (int j = 0; j < 8; j++) {
        int src = __float_as_int(sedge[(base + j) * 8 + 0]);
        se_r[j] = g_s[src * 32 + lane];
    }

    int src0 = __float_as_int(sedge[base * 8 + 0]);
    const float* vp0 = g_v + (size_t)src0 * 96 + lane;
    float vxc = vp0[0], vyc = vp0[32], vzc = vp0[64];

    float A[8];
#pragma unroll
    for (int q = 0; q < 8; q++) A[q] = 0.f;

    int cur = __float_as_int(sedge[base * 8 + 1]);
#pragma unroll
    for (int j = 0; j < 8; j++) {
        int pos = base + j;
        float vxn = 0.f, vyn = 0.f, vzn = 0.f;
        if (j < 7) {
            int srcn = __float_as_int(sedge[(pos + 1) * 8 + 0]);
            const float* vpn = g_v + (size_t)srcn * 96 + lane;
            vxn = vpn[0]; vyn = vpn[32]; vzn = vpn[64];
        }
        int dd = __float_as_int(sedge[pos * 8 + 1]);
        if (dd != cur) {
            float* q = g_agg + (size_t)cur * 256 + lane * 8;
            red_add_v4(q,     A[0], A[1], A[2], A[3]);
            red_add_v4(q + 4, A[4], A[5], A[6], A[7]);
#pragma unroll
            for (int qq = 0; qq < 8; qq++) A[qq] = 0.f;
            cur = dd;
        }
        float yy0 = sedge[pos * 8 + 2];
        float y1x = sedge[pos * 8 + 3];
        float y1y = sedge[pos * 8 + 4];
        float y1z = sedge[pos * 8 + 5];
        float se = se_r[j];
        int sx = lane ^ ((pos & 7) << 2);
        int wb = pos * 128;
        float w1 = sw[wb + sx], w2 = sw[wb + 32 + sx];
        float w3 = sw[wb + 64 + sx], w4 = sw[wb + 96 + sx];

        A[0] += w1 * (se * yy0);
        A[1] += w4 * (vxc * y1x + vyc * y1y + vzc * y1z);
        float a = w2 * se;
        A[2] += a * y1x; A[3] += a * y1y; A[4] += a * y1z;
        float b = w3 * yy0;
        A[5] += b * vxc; A[6] += b * vyc; A[7] += b * vzc;

        vxc = vxn; vyc = vyn; vzc = vzn;
    }
    float* q = g_agg + (size_t)cur * 256 + lane * 8;
    red_add_v4(q,     A[0], A[1], A[2], A[3]);
    red_add_v4(q + 4, A[4], A[5], A[6], A[7]);
}

// ---------------------------------------------------------------------------
// Kernel 3: linear_2 + self-connection (unchanged)
// ---------------------------------------------------------------------------
#define OUT_SMEM_FLOATS (2048 + 2048 + 8192 + 8192)

__global__ void __launch_bounds__(256)
k_out(const float* __restrict__ node_s,
      const float* __restrict__ node_v,
      const float* __restrict__ attrs,
      const float* __restrict__ W2s,
      const float* __restrict__ W2v,
      const float* __restrict__ Wscs,
      const float* __restrict__ Wscv,
      float* __restrict__ out) {
    extern __shared__ float sm[];
    float* sW2s  = sm;
    float* sW2v  = sW2s + 2048;
    float* sWscs = sW2v + 2048;
    float* sWscv = sWscs + 8192;

    int tid = threadIdx.x;
    for (int i = tid; i < 2048; i += 256) { sW2s[i]  = W2s[i]  * INV_2M;  sW2v[i]  = W2v[i]  * INV_2M; }
    for (int i = tid; i < 8192; i += 256) { sWscs[i] = Wscs[i] * INV_FAN; sWscv[i] = Wscv[i] * INV_FAN; }
    __syncthreads();

    int node = blockIdx.x * 32 + (tid >> 3);
    int part = tid & 7;
    int wo = part * 4;

    unsigned long long accs2[2] = {0ull, 0ull};
    unsigned long long accv2[3][2] = {{0ull, 0ull}, {0ull, 0ull}, {0ull, 0ull}};

    const float4* ag = reinterpret_cast<const float4*>(g_agg + (size_t)node * 256);
#pragma unroll 4
    for (int u = 0; u < 32; u++) {
        float4 Aq = ag[u * 2 + 0];
        float4 Bq = ag[u * 2 + 1];
#pragma unroll
        for (int half = 0; half < 2; half++) {
            int k = half * 32 + u;
            ulonglong2 ws = *(const ulonglong2*)&sW2s[k * 32 + wo];
            ulonglong2 wv = *(const ulonglong2*)&sW2v[k * 32 + wo];
            float as  = half ? Aq.y : Aq.x;
            float avx = half ? Bq.y : Aq.z;
            float avy = half ? Bq.z : Aq.w;
            float avz = half ? Bq.w : Bq.x;
            unsigned long long as2  = pack2(as, as);
            unsigned long long avx2 = pack2(avx, avx);
            unsigned long long avy2 = pack2(avy, avy);
            unsigned long long avz2 = pack2(avz, avz);
            fma2(accs2[0], as2, ws.x);
            fma2(accs2[1], as2, ws.y);
            fma2(accv2[0][0], avx2, wv.x);
            fma2(accv2[0][1], avx2, wv.y);
            fma2(accv2[1][0], avy2, wv.x);
            fma2(accv2[1][1], avy2, wv.y);
            fma2(accv2[2][0], avz2, wv.x);
            fma2(accv2[2][1], avz2, wv.y);
        }
    }

    unsigned long long at2[8];
    const float* arow = attrs + node * 8;
#pragma unroll
    for (int v = 0; v < 8; v++) { float a = arow[v]; at2[v] = pack2(a, a); }

    const float* srow = node_s + node * 32;
    const float* vrow = node_v + node * 96;
#pragma unroll 2
    for (int u = 0; u < 32; u++) {
        float su = srow[u];
        float vx = vrow[u * 3 + 0], vy = vrow[u * 3 + 1], vz = vrow[u * 3 + 2];
        unsigned long long Ts[2] = {0ull, 0ull};
        unsigned long long Tv[2] = {0ull, 0ull};
#pragma unroll
        for (int v = 0; v < 8; v++) {
            ulonglong2 ps = *(const ulonglong2*)&sWscs[(u * 8 + v) * 32 + wo];
            ulonglong2 pv = *(const ulonglong2*)&sWscv[(u * 8 + v) * 32 + wo];
            fma2(Ts[0], at2[v], ps.x);
            fma2(Ts[1], at2[v], ps.y);
            fma2(Tv[0], at2[v], pv.x);
            fma2(Tv[1], at2[v], pv.y);
        }
        unsigned long long su2 = pack2(su, su);
        unsigned long long vx2 = pack2(vx, vx);
        unsigned long long vy2 = pack2(vy, vy);
        unsigned long long vz2 = pack2(vz, vz);
#pragma unroll
        for (int p = 0; p < 2; p++) {
            fma2(accs2[p], su2, Ts[p]);
            fma2(accv2[0][p], vx2, Tv[p]);
            fma2(accv2[1][p], vy2, Tv[p]);
            fma2(accv2[2][p], vz2, Tv[p]);
        }
    }

    float* o = out + (size_t)node * 128;
#pragma unroll
    for (int p = 0; p < 2; p++) {
        float s0, s1;
        unpack2(s0, s1, accs2[p]);
        float v0[3], v1[3];
        unpack2(v0[0], v1[0], accv2[0][p]);
        unpack2(v0[1], v1[1], accv2[1][p]);
        unpack2(v0[2], v1[2], accv2[2][p]);
        int w0 = wo + p * 2;
        o[w0]     = s0;
        o[w0 + 1] = s1;
        o[32 + w0 * 3 + 0] = v0[0];
        o[32 + w0 * 3 + 1] = v0[1];
        o[32 + w0 * 3 + 2] = v0[2];
        o[32 + (w0 + 1) * 3 + 0] = v1[0];
        o[32 + (w0 + 1) * 3 + 1] = v1[1];
        o[32 + (w0 + 1) * 3 + 2] = v1[2];
    }
}

// ---------------------------------------------------------------------------
extern "C" void kernel_launch(void* const* d_in, const int* in_sizes, int n_in,
                              void* d_out, int out_size) {
    const float* node_s     = (const float*)d_in[0];
    const float* node_v     = (const float*)d_in[1];
    const float* node_attrs = (const float*)d_in[2];
    const float* edge_emb   = (const float*)d_in[3];
    const float* edge_y0    = (const float*)d_in[4];
    const float* edge_y1    = (const float*)d_in[5];
    const int*   edge_index = (const int*)d_in[6];
    const float* W1s        = (const float*)d_in[7];
    const float* W1v        = (const float*)d_in[8];
    const float* Wr1        = (const float*)d_in[9];
    const float* Wr2        = (const float*)d_in[10];
    const float* W2s        = (const float*)d_in[11];
    const float* W2v        = (const float*)d_in[12];
    const float* Wscs       = (const float*)d_in[13];
    const float* Wscv       = (const float*)d_in[14];
    float* out = (float*)d_out;

    static cudaStream_t s_side = nullptr;
    static cudaEvent_t ev_fork = nullptr, ev_join = nullptr;
    if (s_side == nullptr) {
        cudaStreamCreateWithFlags(&s_side, cudaStreamNonBlocking);
        cudaEventCreateWithFlags(&ev_fork, cudaEventDisableTiming);
        cudaEventCreateWithFlags(&ev_join, cudaEventDisableTiming);

        const int scan_smem_i = (N_NODES + 32) * sizeof(int);
        cudaFuncSetAttribute(k_scan, cudaFuncAttributeMaxDynamicSharedMemorySize, scan_smem_i);
        cudaFuncSetAttribute(k_edge, cudaFuncAttributeMaxDynamicSharedMemorySize,
                             EDGE_SMEM_FLOATS * sizeof(float));
        cudaFuncSetAttribute(k_out, cudaFuncAttributeMaxDynamicSharedMemorySize,
                             OUT_SMEM_FLOATS * sizeof(float));
    }
    const int scan_smem = (N_NODES + 32) * sizeof(int);

    // fork: sort chain on side stream
    cudaEventRecord(ev_fork, 0);
    cudaStreamWaitEvent(s_side, ev_fork, 0);
    k_zero_cnt<<<(N_NODES + 255) / 256, 256, 0, s_side>>>();
    k_hist<<<2500, 256, 0, s_side>>>(edge_index);
    k_scan<<<1, 1024, scan_smem, s_side>>>();
    k_scatter<<<2500, 256, 0, s_side>>>(edge_index, edge_y0, edge_y1);
    cudaEventRecord(ev_join, s_side);

    // main stream: feature chain
    k_prep<<<1, 512>>>(Wr1, Wr2);
    k_zero_agg<<<5000, 256>>>();
    k_lin1<<<(2 * N_NODES + 255) / 256, 256>>>(node_s, node_v, W1s, W1v);

    // join, then edge + out
    cudaStreamWaitEvent(0, ev_join, 0);
    k_edge<<<N_EDGES / ET, ETHREADS, EDGE_SMEM_FLOATS * sizeof(float)>>>(edge_emb);
    k_out<<<(N_NODES * 8) / 256, 256, OUT_SMEM_FLOATS * sizeof(float)>>>(
        node_s, node_v, node_attrs, W2s, W2v, Wscs, Wscv, out);
}

// round 17
// speedup vs baseline: 1.3777x; 1.0561x over previous
#include <cuda_runtime.h>
#include <cstdint>

#define N_NODES 20000
#define N_EDGES 640000
#define MUL 32
#define ATTR 8
#define RB 16
#define FH 64

#define INV_M      0.17677669529663687f
#define INV_RB     0.25f
#define INV_FH     0.125f
#define INV_SQRT3  0.5773502691896258f
#define INV_DEG    0.17677669529663687f
#define INV_2M     0.125f
#define INV_FAN    0.0625f
#define LOG2F_     0.6931471805599453f

// Scratch (device globals)
__device__ float g_s[N_NODES * MUL];
__device__ float g_v[N_NODES * MUL * 3];      // SoA: [node][comp(3)][u(32)]
__device__ float g_agg[N_NODES * MUL * 8];
// sort scratch
__device__ int g_cnt[N_NODES];
__device__ int g_off[N_NODES + 1];
__device__ int g_perm[N_EDGES];
__device__ int g_rank[N_EDGES];
// packed sorted-edge records: {src, dst, y0, y1x, y1y, y1z, pad, pad}
__device__ float g_epack[(size_t)N_EDGES * 8];
// preprocessed weights (packed bf16x2 hi|lo image of Wr2^T, + scaled Wr1)
__device__ unsigned g_pBc[8704];
__device__ float g_Wr1c[1024];

// fast softplus - log2 via MUFU (ex2/lg2); rel error ~1e-6, budget 1e-3
__device__ __forceinline__ float sspf(float x) {
    return fmaxf(x, 0.0f) + __logf(1.0f + __expf(-fabsf(x))) - LOG2F_;
}

// no "memory" clobber — g_agg is write-only here and atomic adds commute
__device__ __forceinline__ void red_add_v4(float* addr, float a, float b, float c, float d) {
    asm volatile("red.global.add.v4.f32 [%0], {%1,%2,%3,%4};"
                 :: "l"(addr), "f"(a), "f"(b), "f"(c), "f"(d));
}

// ---- packed f32x2 helpers ----
__device__ __forceinline__ unsigned long long pack2(float x, float y) {
    unsigned long long r;
    asm("mov.b64 %0, {%1,%2};" : "=l"(r) : "f"(x), "f"(y));
    return r;
}
__device__ __forceinline__ void unpack2(float& x, float& y, unsigned long long r) {
    asm("mov.b64 {%0,%1}, %2;" : "=f"(x), "=f"(y) : "l"(r));
}
__device__ __forceinline__ void fma2(unsigned long long& d, unsigned long long a,
                                     unsigned long long b) {
    asm("fma.rn.f32x2 %0, %1, %2, %0;" : "+l"(d) : "l"(a), "l"(b));
}

// ---- bf16 pack helpers ----
__device__ __forceinline__ unsigned bf16x2_of(float x1, float x0) {
    unsigned r;
    asm("cvt.rn.bf16x2.f32 %0, %1, %2;" : "=r"(r) : "f"(x1), "f"(x0));
    return r;
}
__device__ __forceinline__ void bf16_hilo(float x0, float x1, unsigned& hi, unsigned& lo) {
    hi = bf16x2_of(x1, x0);
    float h0 = __uint_as_float(hi << 16);
    float h1 = __uint_as_float(hi & 0xffff0000u);
    lo = bf16x2_of(x1 - h1, x0 - h0);
}

__device__ __forceinline__ void mma16816(float* d, const unsigned* a, const unsigned* b) {
    asm volatile(
        "mma.sync.aligned.m16n8k16.row.col.f32.bf16.bf16.f32 "
        "{%0,%1,%2,%3}, {%4,%5,%6,%7}, {%8,%9}, {%0,%1,%2,%3};"
        : "+f"(d[0]), "+f"(d[1]), "+f"(d[2]), "+f"(d[3])
        : "r"(a[0]), "r"(a[1]), "r"(a[2]), "r"(a[3]), "r"(b[0]), "r"(b[1]));
}

// kk (bf16x2 word index 0..31) -> paired layout index so (kk, kk+4) are adjacent
__device__ __forceinline__ int kp_of(int kk) {
    int ks = kk >> 3, r = kk & 7;
    return ((ks << 2) + (r & 3)) * 2 + (r >> 2);
}

// ---------------------------------------------------------------------------
// One-shot weight preprocessing
// ---------------------------------------------------------------------------
__global__ void k_prep(const float* __restrict__ Wr1,
                       const float* __restrict__ Wr2) {
    int tid = threadIdx.x;                      // 512 threads, 1 block
    for (int i = tid; i < 1024; i += 512) g_Wr1c[i] = Wr1[i] * INV_RB;
    for (int i = tid; i < 4096; i += 512) {
        int n = i & 127, kk = i >> 7;
        float sc = INV_FH * INV_DEG * ((n >= 96) ? INV_SQRT3 : 1.0f);
        float w0 = Wr2[(2 * kk) * 128 + n] * sc;
        float w1 = Wr2[(2 * kk + 1) * 128 + n] * sc;
        unsigned hi, lo;
        bf16_hilo(w0, w1, hi, lo);
        int kp = kp_of(kk);
        g_pBc[n * 34 + kp] = hi;
        g_pBc[4352 + n * 34 + kp] = lo;
    }
}

// ---------------------------------------------------------------------------
__global__ void k_zero_cnt() {
    int i = blockIdx.x * blockDim.x + threadIdx.x;
    if (i < N_NODES) g_cnt[i] = 0;
}

__global__ void k_zero_agg() {
    int i = blockIdx.x * blockDim.x + threadIdx.x;
    float4* p = reinterpret_cast<float4*>(g_agg);
    p[i] = make_float4(0.f, 0.f, 0.f, 0.f);
}

__global__ void k_hist(const int* __restrict__ eidx) {
    int e = blockIdx.x * blockDim.x + threadIdx.x;
    if (e < N_EDGES) {
        int r = atomicAdd(&g_cnt[eidx[N_EDGES + e]], 1);
        g_rank[e] = r;
    }
}

// ---------------------------------------------------------------------------
// k_scan: 3-barrier shuffle scan with coalesced smem staging.
// ---------------------------------------------------------------------------
__global__ void k_scan() {
    extern __shared__ int si[];
    int* swarp = si + 20000;
    int tid = threadIdx.x;
    int lane = tid & 31;
    int wid = tid >> 5;

    for (int i = tid; i < N_NODES; i += 1024) si[i] = g_cnt[i];
    __syncthreads();

    int base = tid * 20;
    int s = 0;
    if (tid < 1000) {
#pragma unroll
        for (int j = 0; j < 20; j++) s += si[base + j];
    }
    int own = s;

#pragma unroll
    for (int off = 1; off < 32; off <<= 1) {
        int v = __shfl_up_sync(0xffffffffu, s, off);
        if (lane >= off) s += v;
    }
    if (lane == 31) swarp[wid] = s;
    __syncthreads();

    if (wid == 0) {
        int v = swarp[lane];
#pragma unroll
        for (int off = 1; off < 32; off <<= 1) {
            int u = __shfl_up_sync(0xffffffffu, v, off);
            if (lane >= off) v += u;
        }
        swarp[lane] = v;
    }
    __syncthreads();

    int warp_excl = (wid == 0) ? 0 : swarp[wid - 1];
    int excl = warp_excl + (s - own);

    if (tid < 1000) {
        int running = excl;
#pragma unroll
        for (int j = 0; j < 20; j++) {
            int c = si[base + j];
            si[base + j] = running;
            running += c;
        }
    }
    __syncthreads();

    for (int i = tid; i < N_NODES; i += 1024) g_off[i] = si[i];
    if (tid == 0) g_off[N_NODES] = swarp[31];
}

// atomic-free scatter: perm + packed 32B sorted-edge record
__global__ void k_scatter(const int* __restrict__ eidx,
                          const float* __restrict__ y0,
                          const float* __restrict__ y1) {
    int e = blockIdx.x * blockDim.x + threadIdx.x;
    if (e < N_EDGES) {
        int dst = eidx[N_EDGES + e];
        int pos = g_off[dst] + g_rank[e];
        g_perm[pos] = e;
        float4 a = make_float4(__int_as_float(eidx[e]), __int_as_float(dst),
                               y0[e], y1[3 * e + 0]);
        float4 b = make_float4(y1[3 * e + 1], y1[3 * e + 2], 0.f, 0.f);
        float4* gp = reinterpret_cast<float4*>(g_epack + (size_t)pos * 8);
        gp[0] = a;
        gp[1] = b;
    }
}

// ---------------------------------------------------------------------------
// Kernel 1: linear_1 (writes g_v in SoA [node][comp][32])
// ---------------------------------------------------------------------------
__global__ void k_lin1(const float* __restrict__ node_s,
                       const float* __restrict__ node_v,
                       const float* __restrict__ W1s,
                       const float* __restrict__ W1v) {
    __shared__ float sW1s[1024];
    __shared__ float sW1v[1024];
    int tid = threadIdx.x;
    for (int i = tid; i < 1024; i += 256) {
        sW1s[i] = W1s[i] * INV_M;
        sW1v[i] = W1v[i] * INV_M;
    }
    __syncthreads();

    int gt = blockIdx.x * 256 + tid;
    int node = gt >> 1;
    int h = gt & 1;
    if (node >= N_NODES) return;

    float accs[16];
    float accv[16][3];
#pragma unroll
    for (int w = 0; w < 16; w++) { accs[w] = 0.f; accv[w][0] = accv[w][1] = accv[w][2] = 0.f; }

    const float* srow = node_s + node * 32;
    const float* vrow = node_v + node * 96;
    for (int u = 0; u < 32; u++) {
        float su = srow[u];
        float vx = vrow[u * 3 + 0], vy = vrow[u * 3 + 1], vz = vrow[u * 3 + 2];
        const float* ws = &sW1s[u * 32 + h * 16];
        const float* wv = &sW1v[u * 32 + h * 16];
#pragma unroll
        for (int w = 0; w < 16; w++) {
            accs[w]    += su * ws[w];
            accv[w][0] += vx * wv[w];
            accv[w][1] += vy * wv[w];
            accv[w][2] += vz * wv[w];
        }
    }
    float* so = g_s + node * 32 + h * 16;
    float* vo = g_v + node * 96 + h * 16;
#pragma unroll
    for (int w = 0; w < 16; w++) {
        so[w] = accs[w];
        vo[w]      = accv[w][0];
        vo[32 + w] = accv[w][1];
        vo[64 + w] = accv[w][2];
    }
}

// ---------------------------------------------------------------------------
// Kernel 2: fused edge kernel (one 128-edge tile per block), 512 threads;
// metadata read as coalesced packed records.
// ---------------------------------------------------------------------------
#define ET 128
#define ETHREADS 512
#define PHA_HI 0
#define PHA_LO 4352
#define PB_HI  8704
#define PB_LO  13056
#define WR1_OFF 17408
#define EMB_OFF 18432
#define PERM_OFF 20608
#define SEDGE_OFF 20736
#define EDGE_SMEM_FLOATS 21760

__global__ void __launch_bounds__(ETHREADS, 2)
k_edge(const float* __restrict__ emb) {
    extern __shared__ float sm[];
    unsigned* su   = reinterpret_cast<unsigned*>(sm);
    float* sw    = sm;                    // overlay after MMA (PHA/PB dead)
    float* sWr1  = sm + WR1_OFF;
    float* semb  = sm + EMB_OFF;
    int*   sperm = (int*)(sm + PERM_OFF);
    float* sedge = sm + SEDGE_OFF;        // [128][8] packed records

    int tid = threadIdx.x;
    int p0 = blockIdx.x * ET;

    if (tid < 128) sperm[tid] = g_perm[p0 + tid];
    // weight staging: straight vectorized copies of preprocessed images
    {
        const uint4* s4 = reinterpret_cast<const uint4*>(g_pBc);
        uint4* d4 = reinterpret_cast<uint4*>(su + PB_HI);
        for (int i = tid; i < 2176; i += ETHREADS) d4[i] = s4[i];
        const float4* w4 = reinterpret_cast<const float4*>(g_Wr1c);
        float4* dw = reinterpret_cast<float4*>(sWr1);
        for (int i = tid; i < 256; i += ETHREADS) dw[i] = w4[i];
    }
    // metadata: one coalesced float4 copy
    {
        const float4* s4 = reinterpret_cast<const float4*>(g_epack + (size_t)p0 * 8);
        float4* d4 = reinterpret_cast<float4*>(sedge);
        for (int i = tid; i < 256; i += ETHREADS) d4[i] = s4[i];
    }
    __syncthreads();

    for (int i = tid; i < ET * RB; i += ETHREADS) {
        int pos = i >> 4, k = i & 15;
        semb[pos * 17 + k] = emb[sperm[pos] * 16 + k];
    }
    __syncthreads();

    int lane = tid & 31;
    int th = tid >> 5;          // 0..15
    int cg = th >> 1;           // GEMM1 col group
    int eh = th & 1;            // GEMM1 edge half

    // ---- GEMM1 (fp32): 2 edges x 8 cols per thread ----
    float acc1[2][8];
#pragma unroll
    for (int j = 0; j < 2; j++)
#pragma unroll
        for (int m = 0; m < 8; m++) acc1[j][m] = 0.f;

    for (int k = 0; k < 16; k++) {
        float em[2];
#pragma unroll
        for (int j = 0; j < 2; j++) em[j] = semb[(lane + 32 * (eh * 2 + j)) * 17 + k];
        float wr[8];
#pragma unroll
        for (int m = 0; m < 8; m++) wr[m] = sWr1[k * 64 + cg * 8 + m];
#pragma unroll
        for (int j = 0; j < 2; j++)
#pragma unroll
            for (int m = 0; m < 8; m++) acc1[j][m] += em[j] * wr[m];
    }
#pragma unroll
    for (int j = 0; j < 2; j++) {
        int edge = lane + 32 * (eh * 2 + j);
#pragma unroll
        for (int m = 0; m < 8; m += 2) {
            float x0 = sspf(acc1[j][m]);
            float x1 = sspf(acc1[j][m + 1]);
            unsigned hi, lo;
            bf16_hilo(x0, x1, hi, lo);
            int kp = kp_of(cg * 4 + (m >> 1));
            su[PHA_HI + edge * 34 + kp] = hi;
            su[PHA_LO + edge * 34 + kp] = lo;
        }
    }
    __syncthreads();

    // ---- GEMM2 via mma.sync: warp pair (mt, nh); LDS.64 fragment loads ----
    int g = lane >> 2;
    int t4 = lane & 3;
    int mt = th >> 1;
    int nh = th & 1;
    float d[8][4];
#pragma unroll
    for (int ntl = 0; ntl < 8; ntl++)
#pragma unroll
        for (int c = 0; c < 4; c++) d[ntl][c] = 0.f;

    {
        int r0 = mt * 16 + g;
        int r1 = r0 + 8;
#pragma unroll
        for (int ks = 0; ks < 4; ks++) {
            int kb = (ks * 4 + t4) * 2;
            uint2 a0h = *(const uint2*)&su[PHA_HI + r0 * 34 + kb];
            uint2 a1h = *(const uint2*)&su[PHA_HI + r1 * 34 + kb];
            uint2 a0l = *(const uint2*)&su[PHA_LO + r0 * 34 + kb];
            uint2 a1l = *(const uint2*)&su[PHA_LO + r1 * 34 + kb];
            unsigned ahi[4] = {a0h.x, a1h.x, a0h.y, a1h.y};
            unsigned alo[4] = {a0l.x, a1l.x, a0l.y, a1l.y};
#pragma unroll
            for (int ntl = 0; ntl < 8; ntl++) {
                int n = (nh * 8 + ntl) * 8 + g;
                uint2 bh = *(const uint2*)&su[PB_HI + n * 34 + kb];
                uint2 bl = *(const uint2*)&su[PB_LO + n * 34 + kb];
                unsigned bhi[2] = {bh.x, bh.y};
                unsigned blo[2] = {bl.x, bl.y};
                mma16816(d[ntl], ahi, bhi);
                mma16816(d[ntl], alo, bhi);
                mma16816(d[ntl], ahi, blo);
            }
        }
    }
    __syncthreads();   // phA/pB dead; safe to overlay sw

    // ---- store D -> sw[edge][col] with xor swizzle ----
    {
        int e0 = mt * 16 + g;
        int e1 = e0 + 8;
        int sw0 = (e0 & 7) << 2;
        int sw1 = (e1 & 7) << 2;
#pragma unroll
        for (int ntl = 0; ntl < 8; ntl++) {
            int c = (nh * 8 + ntl) * 8 + 2 * t4;
            int b = c & ~31;
            int cc = c & 31;
            *(float2*)&sw[e0 * 128 + b + (cc ^ sw0)] = make_float2(d[ntl][0], d[ntl][1]);
            *(float2*)&sw[e1 * 128 + b + (cc ^ sw1)] = make_float2(d[ntl][2], d[ntl][3]);
        }
    }
    __syncthreads();   // TP warp reads rows produced by its warp pair

    // ---- warp-cooperative TP: warp th owns edges [th*8, th*8+8), lane = u ----
    int base = th * 8;

    float se_r[8];
#pragma unroll
    for (int j = 0; j < 8; j++) {
        int src = __float_as_int(sedge[(base + j) * 8 + 0]);
        se_r[j] = g_s[src * 32 + lane];
    }

    int src0 = __float_as_int(sedge[base * 8 + 0]);
    const float* vp0 = g_v + (size_t)src0 * 96 + lane;
    float vxc = vp0[0], vyc = vp0[32], vzc = vp0[64];

    float A[8];
#pragma unroll
    for (int q = 0; q < 8; q++) A[q] = 0.f;

    int cur = __float_as_int(sedge[base * 8 + 1]);
#pragma unroll
    for (int j = 0; j < 8; j++) {
        int pos = base + j;
        float vxn = 0.f, vyn = 0.f, vzn = 0.f;
        if (j < 7) {
            int srcn = __float_as_int(sedge[(pos + 1) * 8 + 0]);
            const float* vpn = g_v + (size_t)srcn * 96 + lane;
            vxn = vpn[0]; vyn = vpn[32]; vzn = vpn[64];
        }
        int dd = __float_as_int(sedge[pos * 8 + 1]);
        if (dd != cur) {
            float* q = g_agg + (size_t)cur * 256 + lane * 8;
            red_add_v4(q,     A[0], A[1], A[2], A[3]);
            red_add_v4(q + 4, A[4], A[5], A[6], A[7]);
#pragma unroll
            for (int qq = 0; qq < 8; qq++) A[qq] = 0.f;
            cur = dd;
        }
        float yy0 = sedge[pos * 8 + 2];
        float y1x = sedge[pos * 8 + 3];
        float y1y = sedge[pos * 8 + 4];
        float y1z = sedge[pos * 8 + 5];
        float se = se_r[j];
        int sx = lane ^ ((pos & 7) << 2);
        int wb = pos * 128;
        float w1 = sw[wb + sx], w2 = sw[wb + 32 + sx];
        float w3 = sw[wb + 64 + sx], w4 = sw[wb + 96 + sx];

        A[0] += w1 * (se * yy0);
        A[1] += w4 * (vxc * y1x + vyc * y1y + vzc * y1z);
        float a = w2 * se;
        A[2] += a * y1x; A[3] += a * y1y; A[4] += a * y1z;
        float b = w3 * yy0;
        A[5] += b * vxc; A[6] += b * vyc; A[7] += b * vzc;

        vxc = vxn; vyc = vyn; vzc = vzn;
    }
    float* q = g_agg + (size_t)cur * 256 + lane * 8;
    red_add_v4(q,     A[0], A[1], A[2], A[3]);
    red_add_v4(q + 4, A[4], A[5], A[6], A[7]);
}

// ---------------------------------------------------------------------------
// Kernel 3: linear_2 + self-connection (unchanged)
// ---------------------------------------------------------------------------
#define OUT_SMEM_FLOATS (2048 + 2048 + 8192 + 8192)

__global__ void __launch_bounds__(256)
k_out(const float* __restrict__ node_s,
      const float* __restrict__ node_v,
      const float* __restrict__ attrs,
      const float* __restrict__ W2s,
      const float* __restrict__ W2v,
      const float* __restrict__ Wscs,
      const float* __restrict__ Wscv,
      float* __restrict__ out) {
    extern __shared__ float sm[];
    float* sW2s  = sm;
    float* sW2v  = sW2s + 2048;
    float* sWscs = sW2v + 2048;
    float* sWscv = sWscs + 8192;

    int tid = threadIdx.x;
    for (int i = tid; i < 2048; i += 256) { sW2s[i]  = W2s[i]  * INV_2M;  sW2v[i]  = W2v[i]  * INV_2M; }
    for (int i = tid; i < 8192; i += 256) { sWscs[i] = Wscs[i] * INV_FAN; sWscv[i] = Wscv[i] * INV_FAN; }
    __syncthreads();

    int node = blockIdx.x * 32 + (tid >> 3);
    int part = tid & 7;
    int wo = part * 4;

    unsigned long long accs2[2] = {0ull, 0ull};
    unsigned long long accv2[3][2] = {{0ull, 0ull}, {0ull, 0ull}, {0ull, 0ull}};

    const float4* ag = reinterpret_cast<const float4*>(g_agg + (size_t)node * 256);
#pragma unroll 4
    for (int u = 0; u < 32; u++) {
        float4 Aq = ag[u * 2 + 0];
        float4 Bq = ag[u * 2 + 1];
#pragma unroll
        for (int half = 0; half < 2; half++) {
            int k = half * 32 + u;
            ulonglong2 ws = *(const ulonglong2*)&sW2s[k * 32 + wo];
            ulonglong2 wv = *(const ulonglong2*)&sW2v[k * 32 + wo];
            float as  = half ? Aq.y : Aq.x;
            float avx = half ? Bq.y : Aq.z;
            float avy = half ? Bq.z : Aq.w;
            float avz = half ? Bq.w : Bq.x;
            unsigned long long as2  = pack2(as, as);
            unsigned long long avx2 = pack2(avx, avx);
            unsigned long long avy2 = pack2(avy, avy);
            unsigned long long avz2 = pack2(avz, avz);
            fma2(accs2[0], as2, ws.x);
            fma2(accs2[1], as2, ws.y);
            fma2(accv2[0][0], avx2, wv.x);
            fma2(accv2[0][1], avx2, wv.y);
            fma2(accv2[1][0], avy2, wv.x);
            fma2(accv2[1][1], avy2, wv.y);
            fma2(accv2[2][0], avz2, wv.x);
            fma2(accv2[2][1], avz2, wv.y);
        }
    }

    unsigned long long at2[8];
    const float* arow = attrs + node * 8;
#pragma unroll
    for (int v = 0; v < 8; v++) { float a = arow[v]; at2[v] = pack2(a, a); }

    const float* srow = node_s + node * 32;
    const float* vrow = node_v + node * 96;
#pragma unroll 2
    for (int u = 0; u < 32; u++) {
        float su = srow[u];
        float vx = vrow[u * 3 + 0], vy = vrow[u * 3 + 1], vz = vrow[u * 3 + 2];
        unsigned long long Ts[2] = {0ull, 0ull};
        unsigned long long Tv[2] = {0ull, 0ull};
#pragma unroll
        for (int v = 0; v < 8; v++) {
            ulonglong2 ps = *(const ulonglong2*)&sWscs[(u * 8 + v) * 32 + wo];
            ulonglong2 pv = *(const ulonglong2*)&sWscv[(u * 8 + v) * 32 + wo];
            fma2(Ts[0], at2[v], ps.x);
            fma2(Ts[1], at2[v], ps.y);
            fma2(Tv[0], at2[v], pv.x);
            fma2(Tv[1], at2[v], pv.y);
        }
        unsigned long long su2 = pack2(su, su);
        unsigned long long vx2 = pack2(vx, vx);
        unsigned long long vy2 = pack2(vy, vy);
        unsigned long long vz2 = pack2(vz, vz);
#pragma unroll
        for (int p = 0; p < 2; p++) {
            fma2(accs2[p], su2, Ts[p]);
            fma2(accv2[0][p], vx2, Tv[p]);
            fma2(accv2[1][p], vy2, Tv[p]);
            fma2(accv2[2][p], vz2, Tv[p]);
        }
    }

    float* o = out + (size_t)node * 128;
#pragma unroll
    for (int p = 0; p < 2; p++) {
        float s0, s1;
        unpack2(s0, s1, accs2[p]);
        float v0[3], v1[3];
        unpack2(v0[0], v1[0], accv2[0][p]);
        unpack2(v0[1], v1[1], accv2[1][p]);
        unpack2(v0[2], v1[2], accv2[2][p]);
        int w0 = wo + p * 2;
        o[w0]     = s0;
        o[w0 + 1] = s1;
        o[32 + w0 * 3 + 0] = v0[0];
        o[32 + w0 * 3 + 1] = v0[1];
        o[32 + w0 * 3 + 2] = v0[2];
        o[32 + (w0 + 1) * 3 + 0] = v1[0];
        o[32 + (w0 + 1) * 3 + 1] = v1[1];
        o[32 + (w0 + 1) * 3 + 2] = v1[2];
    }
}

// ---------------------------------------------------------------------------
extern "C" void kernel_launch(void* const* d_in, const int* in_sizes, int n_in,
                              void* d_out, int out_size) {
    const float* node_s     = (const float*)d_in[0];
    const float* node_v     = (const float*)d_in[1];
    const float* node_attrs = (const float*)d_in[2];
    const float* edge_emb   = (const float*)d_in[3];
    const float* edge_y0    = (const float*)d_in[4];
    const float* edge_y1    = (const float*)d_in[5];
    const int*   edge_index = (const int*)d_in[6];
    const float* W1s        = (const float*)d_in[7];
    const float* W1v        = (const float*)d_in[8];
    const float* Wr1        = (const float*)d_in[9];
    const float* Wr2        = (const float*)d_in[10];
    const float* W2s        = (const float*)d_in[11];
    const float* W2v        = (const float*)d_in[12];
    const float* Wscs       = (const float*)d_in[13];
    const float* Wscv       = (const float*)d_in[14];
    float* out = (float*)d_out;

    static cudaStream_t s_side = nullptr;
    static cudaEvent_t ev_fork = nullptr, ev_join = nullptr;
    if (s_side == nullptr) {
        cudaStreamCreateWithFlags(&s_side, cudaStreamNonBlocking);
        cudaEventCreateWithFlags(&ev_fork, cudaEventDisableTiming);
        cudaEventCreateWithFlags(&ev_join, cudaEventDisableTiming);

        const int scan_smem_i = (N_NODES + 32) * sizeof(int);
        cudaFuncSetAttribute(k_scan, cudaFuncAttributeMaxDynamicSharedMemorySize, scan_smem_i);
        cudaFuncSetAttribute(k_edge, cudaFuncAttributeMaxDynamicSharedMemorySize,
                             EDGE_SMEM_FLOATS * sizeof(float));
        cudaFuncSetAttribute(k_out, cudaFuncAttributeMaxDynamicSharedMemorySize,
                             OUT_SMEM_FLOATS * sizeof(float));
    }
    const int scan_smem = (N_NODES + 32) * sizeof(int);

    // fork: sort chain on side stream
    cudaEventRecord(ev_fork, 0);
    cudaStreamWaitEvent(s_side, ev_fork, 0);
    k_zero_cnt<<<(N_NODES + 255) / 256, 256, 0, s_side>>>();
    k_hist<<<2500, 256, 0, s_side>>>(edge_index);
    k_scan<<<1, 1024, scan_smem, s_side>>>();
    k_scatter<<<2500, 256, 0, s_side>>>(edge_index, edge_y0, edge_y1);
    cudaEventRecord(ev_join, s_side);

    // main stream: feature chain
    k_prep<<<1, 512>>>(Wr1, Wr2);
    k_zero_agg<<<5000, 256>>>();
    k_lin1<<<(2 * N_NODES + 255) / 256, 256>>>(node_s, node_v, W1s, W1v);

    // join, then edge + out
    cudaStreamWaitEvent(0, ev_join, 0);
    k_edge<<<N_EDGES / ET, ETHREADS, EDGE_SMEM_FLOATS * sizeof(float)>>>(edge_emb);
    k_out<<<(N_NODES * 8) / 256, 256, OUT_SMEM_FLOATS * sizeof(float)>>>(
        node_s, node_v, node_attrs, W2s, W2v, Wscs, Wscv, out);
}